// round 6
// baseline (speedup 1.0000x reference)
#include <cuda_runtime.h>
#include <math.h>
#include <cstdint>

// ---------------- problem constants ----------------
#define LNUM 4
#define BB   4
#define TT   1024
#define CC   768
#define NH   12
#define HD   64
#define HID  3072
#define MM   (BB*TT)          // 4096 rows
#define EPS_LN 1e-5f

// ---------------- scratch (device globals; no allocation allowed) ----------------
__device__ float g_res[(size_t)MM*CC];
__device__ float g_ln [(size_t)MM*CC];
__device__ float g_q  [(size_t)MM*CC];
__device__ float g_k  [(size_t)MM*CC];
__device__ float g_v  [(size_t)MM*CC];
__device__ float g_y  [(size_t)MM*CC];
__device__ float g_h1 [(size_t)MM*HID];
// tf32-rounded weights
#define WQ_OFF 0
#define WK_OFF (WQ_OFF + (size_t)LNUM*CC*CC)
#define WV_OFF (WK_OFF + (size_t)LNUM*CC*CC)
#define WP_OFF (WV_OFF + (size_t)LNUM*CC*CC)
#define W1_OFF (WP_OFF + (size_t)LNUM*CC*CC)
#define W2_OFF (W1_OFF + (size_t)LNUM*CC*HID)
#define WT_TOTAL (W2_OFF + (size_t)LNUM*CC*HID)
__device__ float g_wt [WT_TOTAL];

// ---------------- helpers ----------------
__device__ __forceinline__ uint32_t smem_u32(const void* p) {
    uint32_t a;
    asm("{ .reg .u64 t; cvta.to.shared.u64 t, %1; cvt.u32.u64 %0, t; }" : "=r"(a) : "l"(p));
    return a;
}
__device__ __forceinline__ void cp_async16(uint32_t dst, const void* src) {
    asm volatile("cp.async.cg.shared.global [%0], [%1], 16;" :: "r"(dst), "l"(src));
}
#define CP_COMMIT() asm volatile("cp.async.commit_group;" ::: "memory")
template <int N>
__device__ __forceinline__ void cp_wait() {
    asm volatile("cp.async.wait_group %0;" :: "n"(N) : "memory");
}
__device__ __forceinline__ uint32_t f2tf32(float x) {
    uint32_t u;
    asm("cvt.rna.tf32.f32 %0, %1;" : "=r"(u) : "f"(x));
    return u;
}
__device__ __forceinline__ float f2tf32f(float x) { return __uint_as_float(f2tf32(x)); }

__device__ __forceinline__ void mma_tf32(float* d, uint32_t a0, uint32_t a1, uint32_t a2,
                                         uint32_t a3, uint32_t b0, uint32_t b1) {
    asm volatile(
        "mma.sync.aligned.m16n8k8.row.col.f32.tf32.tf32.f32 "
        "{%0,%1,%2,%3}, {%4,%5,%6,%7}, {%8,%9}, {%0,%1,%2,%3};"
        : "+f"(d[0]), "+f"(d[1]), "+f"(d[2]), "+f"(d[3])
        : "r"(a0), "r"(a1), "r"(a2), "r"(a3), "r"(b0), "r"(b1));
}
__device__ __forceinline__ void ldsm_x4(uint32_t addr, uint32_t* r) {
    asm volatile("ldmatrix.sync.aligned.m8n8.x4.shared.b16 {%0,%1,%2,%3}, [%4];"
        : "=r"(r[0]), "=r"(r[1]), "=r"(r[2]), "=r"(r[3]) : "r"(addr));
}

// ---------------- small kernels ----------------
__global__ void copy4_kernel(float4* __restrict__ dst, const float4* __restrict__ src, int n4) {
    int i = blockIdx.x * blockDim.x + threadIdx.x;
    if (i < n4) dst[i] = src[i];
}

__global__ void tf32_round_kernel(const float4* __restrict__ src, float4* __restrict__ dst, int n4) {
    int i = blockIdx.x * blockDim.x + threadIdx.x;
    if (i < n4) {
        float4 v = src[i];
        uint4 u = make_uint4(f2tf32(v.x), f2tf32(v.y), f2tf32(v.z), f2tf32(v.w));
        dst[i] = *(float4*)&u;
    }
}

// layernorm; output tf32-rounded (consumed only by GEMMs)
__global__ void ln_kernel(const float* __restrict__ x, const float* __restrict__ g,
                          const float* __restrict__ b, float* __restrict__ out) {
    __shared__ float red0[8], red1[8];
    int row = blockIdx.x;
    int tid = threadIdx.x;
    const float* xr = x + (size_t)row * CC;
    float s = 0.f, s2 = 0.f;
    for (int i = tid; i < CC; i += 256) { float v = xr[i]; s += v; s2 += v * v; }
    for (int o = 16; o; o >>= 1) {
        s  += __shfl_xor_sync(0xffffffffu, s,  o);
        s2 += __shfl_xor_sync(0xffffffffu, s2, o);
    }
    if ((tid & 31) == 0) { red0[tid >> 5] = s; red1[tid >> 5] = s2; }
    __syncthreads();
    if (tid < 32) {
        s  = (tid < 8) ? red0[tid] : 0.f;
        s2 = (tid < 8) ? red1[tid] : 0.f;
        for (int o = 4; o; o >>= 1) {
            s  += __shfl_xor_sync(0xffffffffu, s,  o);
            s2 += __shfl_xor_sync(0xffffffffu, s2, o);
        }
        if (tid == 0) { red0[0] = s; red1[0] = s2; }
    }
    __syncthreads();
    float mu  = red0[0] * (1.f / CC);
    float var = red1[0] * (1.f / CC) - mu * mu;
    float rs  = rsqrtf(var + EPS_LN);
    float* outr = out + (size_t)row * CC;
    for (int i = tid; i < CC; i += 256)
        outr[i] = f2tf32f((xr[i] - mu) * rs * g[i] + b[i]);
}

// ---------------- tf32 mma.sync GEMM, cp.async 3-stage, ldmatrix A-frags ----------------
#define EPI_BIAS  0
#define EPI_RESID 1
#define EPI_GELU  2

#define STAGES 3
#define ASTR 20
#define BSTR 136
#define A_STG (128 * ASTR)
#define B_STG (16 * BSTR)
#define GEMM_SMEM_WORDS (STAGES * (A_STG + B_STG) + 128)
#define GEMM_SMEM_BYTES (GEMM_SMEM_WORDS * 4)

template <int EPI>
__device__ __forceinline__ void gemm_body(const float* __restrict__ A, const float* __restrict__ W,
                                          const float* __restrict__ bias, const float* __restrict__ resid,
                                          float* __restrict__ C, int Ndim, int Kdim,
                                          int bm, int bn, float* dsm) {
    float* sA = dsm;
    float* sB = dsm + STAGES * A_STG;
    float* sBias = dsm + STAGES * (A_STG + B_STG);

    int tid = threadIdx.x;
    int lane = tid & 31;
    int wid = tid >> 5;

    if (tid < 128) sBias[tid] = bias[bn + tid];

    int lr = lane >> 2;
    int lc = lane & 3;
    int wm = (wid & 1) * 64;
    int wn = (wid >> 1) * 32;

    int aIdx0 = tid * 2, aIdx1 = tid * 2 + 1;
    int aRow0 = aIdx0 >> 2, aKg0 = (aIdx0 & 3) * 4;
    int aRow1 = aIdx1 >> 2, aKg1 = (aIdx1 & 3) * 4;
    int bKr0 = aIdx0 >> 5, bNg0 = (aIdx0 & 31) * 4;
    int bKr1 = aIdx1 >> 5, bNg1 = (aIdx1 & 31) * 4;

    uint32_t sA_base = smem_u32(sA);
    uint32_t sB_base = smem_u32(sB);

    // ldmatrix per-lane A fragment base: row = wm + (lane&15), col-half via lane&16
    uint32_t aFrag = sA_base + (uint32_t)((wm + (lane & 15)) * ASTR) * 4 + ((lane & 16) ? 16u : 0u);

    const float* aSrc0 = A + (size_t)(bm + aRow0) * Kdim + aKg0;
    const float* aSrc1 = A + (size_t)(bm + aRow1) * Kdim + aKg1;
    const float* bSrc0 = W + (size_t)bKr0 * Ndim + bn + bNg0;
    const float* bSrc1 = W + (size_t)bKr1 * Ndim + bn + bNg1;

    float acc[4][4][4];
#pragma unroll
    for (int i = 0; i < 4; i++)
#pragma unroll
        for (int j = 0; j < 4; j++)
#pragma unroll
            for (int r = 0; r < 4; r++) acc[i][j][r] = 0.f;

    int nch = Kdim >> 4;

#define LOAD_STAGE(stg, chunk) do {                                                   \
        int _k0 = (chunk) << 4;                                                       \
        uint32_t _ab = sA_base + (uint32_t)((stg) * A_STG) * 4;                       \
        uint32_t _bb = sB_base + (uint32_t)((stg) * B_STG) * 4;                       \
        cp_async16(_ab + (uint32_t)(aRow0 * ASTR + aKg0) * 4, aSrc0 + _k0);           \
        cp_async16(_ab + (uint32_t)(aRow1 * ASTR + aKg1) * 4, aSrc1 + _k0);           \
        cp_async16(_bb + (uint32_t)(bKr0 * BSTR + bNg0) * 4, bSrc0 + (size_t)_k0 * Ndim); \
        cp_async16(_bb + (uint32_t)(bKr1 * BSTR + bNg1) * 4, bSrc1 + (size_t)_k0 * Ndim); \
    } while (0)

#pragma unroll
    for (int s = 0; s < STAGES - 1; s++) {
        if (s < nch) LOAD_STAGE(s, s);
        CP_COMMIT();
    }
    cp_wait<STAGES - 2>();
    __syncthreads();

    for (int c = 0; c < nch; c++) {
        int buf = c % STAGES;
        int nc = c + STAGES - 1;
        if (nc < nch) LOAD_STAGE(nc % STAGES, nc);
        CP_COMMIT();

        uint32_t aStage = aFrag + (uint32_t)(buf * A_STG) * 4;
        const uint32_t* Bs = (const uint32_t*)(sB + buf * B_STG);
#pragma unroll
        for (int ks = 0; ks < 2; ks++) {
            int k0 = ks * 8;
            uint32_t b[4][2];
#pragma unroll
            for (int j = 0; j < 4; j++) {
                int n0 = wn + j * 8 + lr;
                b[j][0] = Bs[(k0 + lc) * BSTR + n0];
                b[j][1] = Bs[(k0 + lc + 4) * BSTR + n0];
            }
#pragma unroll
            for (int i = 0; i < 4; i++) {
                uint32_t a[4];
                ldsm_x4(aStage + (uint32_t)(i * 16 * ASTR) * 4 + ks * 32, a);
#pragma unroll
                for (int j = 0; j < 4; j++)
                    mma_tf32(acc[i][j], a[0], a[1], a[2], a[3], b[j][0], b[j][1]);
            }
        }
        cp_wait<STAGES - 2>();
        __syncthreads();
    }
#undef LOAD_STAGE

#pragma unroll
    for (int i = 0; i < 4; i++) {
        int r0 = bm + wm + i * 16 + lr;
#pragma unroll
        for (int j = 0; j < 4; j++) {
            int colL = wn + j * 8 + lc * 2;
            int col = bn + colL;
            float v0 = acc[i][j][0] + sBias[colL];
            float v1 = acc[i][j][1] + sBias[colL + 1];
            float v2 = acc[i][j][2] + sBias[colL];
            float v3 = acc[i][j][3] + sBias[colL + 1];
            if (EPI == EPI_RESID) {
                float2 ra = *(const float2*)(resid + (size_t)r0 * Ndim + col);
                float2 rb = *(const float2*)(resid + (size_t)(r0 + 8) * Ndim + col);
                v0 += ra.x; v1 += ra.y; v2 += rb.x; v3 += rb.y;
            }
            if (EPI == EPI_GELU) {
                v0 = v0 * 0.5f * (1.0f + erff(v0 * 0.70710678118654752f));
                v1 = v1 * 0.5f * (1.0f + erff(v1 * 0.70710678118654752f));
                v2 = v2 * 0.5f * (1.0f + erff(v2 * 0.70710678118654752f));
                v3 = v3 * 0.5f * (1.0f + erff(v3 * 0.70710678118654752f));
            }
            if (EPI != EPI_RESID) {   // outputs feeding later GEMM/attention: pre-round to tf32
                v0 = f2tf32f(v0); v1 = f2tf32f(v1); v2 = f2tf32f(v2); v3 = f2tf32f(v3);
            }
            *(float2*)(C + (size_t)r0 * Ndim + col)       = make_float2(v0, v1);
            *(float2*)(C + (size_t)(r0 + 8) * Ndim + col) = make_float2(v2, v3);
        }
    }
}

template <int EPI>
__global__ __launch_bounds__(256)
void tc_gemm_kernel(const float* __restrict__ A, const float* __restrict__ W,
                    const float* __restrict__ bias, const float* __restrict__ resid,
                    float* __restrict__ C, int Ndim, int Kdim) {
    extern __shared__ float dsm[];
    gemm_body<EPI>(A, W, bias, resid, C, Ndim, Kdim, blockIdx.y * 128, blockIdx.x * 128, dsm);
}

__global__ __launch_bounds__(256)
void qkv_gemm_kernel(const float* __restrict__ A,
                     const float* __restrict__ W0, const float* __restrict__ W1, const float* __restrict__ W2,
                     const float* __restrict__ b0, const float* __restrict__ b1, const float* __restrict__ b2,
                     float* __restrict__ C0, float* __restrict__ C1, float* __restrict__ C2) {
    extern __shared__ float dsm[];
    const float* W = (blockIdx.z == 0) ? W0 : (blockIdx.z == 1) ? W1 : W2;
    const float* bi = (blockIdx.z == 0) ? b0 : (blockIdx.z == 1) ? b1 : b2;
    float* C = (blockIdx.z == 0) ? C0 : (blockIdx.z == 1) ? C1 : C2;
    gemm_body<EPI_BIAS>(A, W, bi, nullptr, C, CC, CC, blockIdx.y * 128, blockIdx.x * 128, dsm);
}

// ---------------- tensor-core flash attention (inputs pre-rounded tf32) ----------------
#define QSTR 68
#define KSTR 68
#define VSTR 72
#define PSTR 68
#define ATT_Q_OFF 0
#define ATT_K_OFF (128 * QSTR)
#define ATT_V_OFF (ATT_K_OFF + 64 * KSTR)
#define ATT_P_OFF (ATT_V_OFF + 64 * VSTR)
#define ATT_M_OFF (ATT_P_OFF + 128 * PSTR)
#define ATT_L_OFF (ATT_M_OFF + 128)
#define ATTN_SMEM_WORDS (ATT_L_OFF + 128)
#define ATTN_SMEM (ATTN_SMEM_WORDS * (int)sizeof(float))

__global__ __launch_bounds__(256)
void attn_tc_kernel(const float* __restrict__ Q, const float* __restrict__ K,
                    const float* __restrict__ V, float* __restrict__ Y) {
    extern __shared__ float sm[];
    float* Qs = sm + ATT_Q_OFF;
    float* Ks = sm + ATT_K_OFF;
    float* Vs = sm + ATT_V_OFF;
    float* Ps = sm + ATT_P_OFF;
    float* mS = sm + ATT_M_OFF;
    float* lS = sm + ATT_L_OFF;

    int tid = threadIdx.x;
    int lane = tid & 31;
    int wid = tid >> 5;
    int lr = lane >> 2;
    int lc = lane & 3;
    int wr = wid * 16;

    int qb = blockIdx.x * 128;
    int bh = blockIdx.y;
    int b = bh / NH, h = bh % NH;
    size_t base = (size_t)b * TT * CC + (size_t)h * HD;

    // ldmatrix fragment bases
    uint32_t qFrag = smem_u32(Qs) + (uint32_t)((wr + (lane & 15)) * QSTR) * 4 + ((lane & 16) ? 16u : 0u);
    uint32_t pFrag = smem_u32(Ps) + (uint32_t)((wr + (lane & 15)) * PSTR) * 4 + ((lane & 16) ? 16u : 0u);
    // K B-frag: rows n = (lane&7) + ((lane&16)?8:0), col-half via lane&8
    uint32_t kFrag = smem_u32(Ks) + (uint32_t)(((lane & 7) + ((lane & 16) ? 8 : 0)) * KSTR) * 4
                   + ((lane & 8) ? 16u : 0u);

    // load Q tile (prescaled by 1/sqrt(hd); scale by 2^-3 preserves tf32 rounding)
    for (int i = tid; i < 128 * 16; i += 256) {
        int row = i >> 4, cg = (i & 15) * 4;
        float4 qv = *(const float4*)(Q + base + (size_t)(qb + row) * CC + cg);
        *(float4*)(Qs + row * QSTR + cg) =
            make_float4(qv.x * 0.125f, qv.y * 0.125f, qv.z * 0.125f, qv.w * 0.125f);
    }
    if (tid < 128) { mS[tid] = -1e30f; lS[tid] = 0.f; }

    float o[8][4];
#pragma unroll
    for (int j = 0; j < 8; j++)
#pragma unroll
        for (int r = 0; r < 4; r++) o[j][r] = 0.f;

    int qmod = qb & 255;
    int rm0 = qmod + wr + lr;
    int rm1 = rm0 + 8;

    for (int kb = 0; kb < TT; kb += 64) {
        int kbm = kb & 255;
        if (kbm > qmod + 127) continue;
        __syncthreads();
        for (int i = tid; i < 64 * 16; i += 256) {
            int row = i >> 4, cg = (i & 15) * 4;
            *(float4*)(Ks + row * KSTR + cg) = *(const float4*)(K + base + (size_t)(kb + row) * CC + cg);
            *(float4*)(Vs + row * VSTR + cg) = *(const float4*)(V + base + (size_t)(kb + row) * CC + cg);
        }
        __syncthreads();

        // ---- S = Q K^T ----
        float sacc[8][4];
#pragma unroll
        for (int j = 0; j < 8; j++)
#pragma unroll
            for (int r = 0; r < 4; r++) sacc[j][r] = 0.f;
#pragma unroll
        for (int ks = 0; ks < 8; ks++) {
            uint32_t a[4];
            ldsm_x4(qFrag + ks * 32, a);
#pragma unroll
            for (int jp = 0; jp < 4; jp++) {
                uint32_t bk[4];
                ldsm_x4(kFrag + (uint32_t)(jp * 16 * KSTR) * 4 + ks * 32, bk);
                mma_tf32(sacc[2 * jp],     a[0], a[1], a[2], a[3], bk[0], bk[1]);
                mma_tf32(sacc[2 * jp + 1], a[0], a[1], a[2], a[3], bk[2], bk[3]);
            }
        }

        // ---- mask + online softmax ----
        float m0 = -1e30f, m1 = -1e30f;
#pragma unroll
        for (int j = 0; j < 8; j++) {
            int c0 = kbm + j * 8 + 2 * lc;
            if (c0 > rm0)     sacc[j][0] = -1e30f;
            if (c0 + 1 > rm0) sacc[j][1] = -1e30f;
            if (c0 > rm1)     sacc[j][2] = -1e30f;
            if (c0 + 1 > rm1) sacc[j][3] = -1e30f;
            m0 = fmaxf(m0, fmaxf(sacc[j][0], sacc[j][1]));
            m1 = fmaxf(m1, fmaxf(sacc[j][2], sacc[j][3]));
        }
        m0 = fmaxf(m0, __shfl_xor_sync(0xffffffffu, m0, 1));
        m0 = fmaxf(m0, __shfl_xor_sync(0xffffffffu, m0, 2));
        m1 = fmaxf(m1, __shfl_xor_sync(0xffffffffu, m1, 1));
        m1 = fmaxf(m1, __shfl_xor_sync(0xffffffffu, m1, 2));

        int r0 = wr + lr, r1 = r0 + 8;
        float mo0 = mS[r0], mo1 = mS[r1];
        float mn0 = fmaxf(mo0, m0), mn1 = fmaxf(mo1, m1);
        float al0 = __expf(mo0 - mn0), al1 = __expf(mo1 - mn1);

        float sum0 = 0.f, sum1 = 0.f;
#pragma unroll
        for (int j = 0; j < 8; j++) {
            float p00 = __expf(sacc[j][0] - mn0);
            float p01 = __expf(sacc[j][1] - mn0);
            float p10 = __expf(sacc[j][2] - mn1);
            float p11 = __expf(sacc[j][3] - mn1);
            sum0 += p00 + p01;
            sum1 += p10 + p11;
            // store rounded tf32 for PV mma
            uint2 u0 = make_uint2(f2tf32(p00), f2tf32(p01));
            uint2 u1 = make_uint2(f2tf32(p10), f2tf32(p11));
            *(uint2*)(Ps + r0 * PSTR + j * 8 + 2 * lc) = u0;
            *(uint2*)(Ps + r1 * PSTR + j * 8 + 2 * lc) = u1;
            o[j][0] *= al0; o[j][1] *= al0; o[j][2] *= al1; o[j][3] *= al1;
        }
        sum0 += __shfl_xor_sync(0xffffffffu, sum0, 1);
        sum0 += __shfl_xor_sync(0xffffffffu, sum0, 2);
        sum1 += __shfl_xor_sync(0xffffffffu, sum1, 1);
        sum1 += __shfl_xor_sync(0xffffffffu, sum1, 2);
        if (lc == 0) {
            lS[r0] = lS[r0] * al0 + sum0;
            lS[r1] = lS[r1] * al1 + sum1;
            mS[r0] = mn0;
            mS[r1] = mn1;
        }
        __syncwarp();

        // ---- O += P V ----
#pragma unroll
        for (int ks = 0; ks < 8; ks++) {
            int k0 = ks * 8;
            uint32_t a[4];
            ldsm_x4(pFrag + ks * 32, a);
#pragma unroll
            for (int j = 0; j < 8; j++) {
                int n0 = j * 8 + lr;
                uint32_t b0 = *(const uint32_t*)(Vs + (k0 + lc) * VSTR + n0);
                uint32_t b1 = *(const uint32_t*)(Vs + (k0 + lc + 4) * VSTR + n0);
                mma_tf32(o[j], a[0], a[1], a[2], a[3], b0, b1);
            }
        }
    }

    __syncwarp();
    int r0 = wr + lr, r1 = r0 + 8;
    float inv0 = 1.0f / lS[r0];
    float inv1 = 1.0f / lS[r1];
#pragma unroll
    for (int j = 0; j < 8; j++) {
        int d = j * 8 + 2 * lc;
        *(float2*)(Y + base + (size_t)(qb + r0) * CC + d) =
            make_float2(f2tf32f(o[j][0] * inv0), f2tf32f(o[j][1] * inv0));
        *(float2*)(Y + base + (size_t)(qb + r1) * CC + d) =
            make_float2(f2tf32f(o[j][2] * inv1), f2tf32f(o[j][3] * inv1));
    }
}

// ---------------- host orchestration ----------------
extern "C" void kernel_launch(void* const* d_in, const int* in_sizes, int n_in,
                              void* d_out, int out_size) {
    const float* x     = (const float*)d_in[0];
    const float* ln1_g = (const float*)d_in[1];
    const float* ln1_b = (const float*)d_in[2];
    const float* Wq    = (const float*)d_in[3];
    const float* bq    = (const float*)d_in[4];
    const float* Wk    = (const float*)d_in[5];
    const float* bk    = (const float*)d_in[6];
    const float* Wv    = (const float*)d_in[7];
    const float* bv    = (const float*)d_in[8];
    const float* Wp    = (const float*)d_in[9];
    const float* bp    = (const float*)d_in[10];
    const float* ln2_g = (const float*)d_in[11];
    const float* ln2_b = (const float*)d_in[12];
    const float* W1    = (const float*)d_in[13];
    const float* b1    = (const float*)d_in[14];
    const float* W2    = (const float*)d_in[15];
    const float* b2    = (const float*)d_in[16];

    float *res, *ln, *q, *k, *v, *y, *h1, *wt;
    cudaGetSymbolAddress((void**)&res, g_res);
    cudaGetSymbolAddress((void**)&ln,  g_ln);
    cudaGetSymbolAddress((void**)&q,   g_q);
    cudaGetSymbolAddress((void**)&k,   g_k);
    cudaGetSymbolAddress((void**)&v,   g_v);
    cudaGetSymbolAddress((void**)&y,   g_y);
    cudaGetSymbolAddress((void**)&h1,  g_h1);
    cudaGetSymbolAddress((void**)&wt,  g_wt);

    cudaFuncSetAttribute(attn_tc_kernel, cudaFuncAttributeMaxDynamicSharedMemorySize, ATTN_SMEM);
    cudaFuncSetAttribute(tc_gemm_kernel<EPI_BIAS>,  cudaFuncAttributeMaxDynamicSharedMemorySize, GEMM_SMEM_BYTES);
    cudaFuncSetAttribute(tc_gemm_kernel<EPI_RESID>, cudaFuncAttributeMaxDynamicSharedMemorySize, GEMM_SMEM_BYTES);
    cudaFuncSetAttribute(tc_gemm_kernel<EPI_GELU>,  cudaFuncAttributeMaxDynamicSharedMemorySize, GEMM_SMEM_BYTES);
    cudaFuncSetAttribute(qkv_gemm_kernel,           cudaFuncAttributeMaxDynamicSharedMemorySize, GEMM_SMEM_BYTES);

    // ---- pre-round weights to tf32 ----
    {
        int nCC = LNUM * CC * CC / 4, nCH = LNUM * CC * HID / 4;
        int tb = 256;
        tf32_round_kernel<<<(nCC + tb - 1) / tb, tb>>>((const float4*)Wq, (float4*)(wt + WQ_OFF), nCC);
        tf32_round_kernel<<<(nCC + tb - 1) / tb, tb>>>((const float4*)Wk, (float4*)(wt + WK_OFF), nCC);
        tf32_round_kernel<<<(nCC + tb - 1) / tb, tb>>>((const float4*)Wv, (float4*)(wt + WV_OFF), nCC);
        tf32_round_kernel<<<(nCC + tb - 1) / tb, tb>>>((const float4*)Wp, (float4*)(wt + WP_OFF), nCC);
        tf32_round_kernel<<<(nCH + tb - 1) / tb, tb>>>((const float4*)W1, (float4*)(wt + W1_OFF), nCH);
        tf32_round_kernel<<<(nCH + tb - 1) / tb, tb>>>((const float4*)W2, (float4*)(wt + W2_OFF), nCH);
    }

    // residual = x
    {
        int n4 = (MM * CC) / 4;
        copy4_kernel<<<(n4 + 255) / 256, 256>>>((float4*)res, (const float4*)x, n4);
    }

    dim3 gemm_qkv3(CC / 128, MM / 128, 3);
    dim3 gemm_c  (CC / 128, MM / 128);
    dim3 gemm_h  (HID / 128, MM / 128);
    dim3 attn_grid(TT / 128, BB * NH);

    for (int l = 0; l < LNUM; l++) {
        const float* wq = wt + WQ_OFF + (size_t)l * CC * CC;
        const float* wk = wt + WK_OFF + (size_t)l * CC * CC;
        const float* wv = wt + WV_OFF + (size_t)l * CC * CC;
        const float* wp = wt + WP_OFF + (size_t)l * CC * CC;
        const float* w1 = wt + W1_OFF + (size_t)l * CC * HID;
        const float* w2 = wt + W2_OFF + (size_t)l * HID * CC;

        ln_kernel<<<MM, 256>>>(res, ln1_g + (size_t)l*CC, ln1_b + (size_t)l*CC, ln);
        qkv_gemm_kernel<<<gemm_qkv3, 256, GEMM_SMEM_BYTES>>>(
            ln, wq, wk, wv, bq + (size_t)l*CC, bk + (size_t)l*CC, bv + (size_t)l*CC, q, k, v);
        attn_tc_kernel<<<attn_grid, 256, ATTN_SMEM>>>(q, k, v, y);
        tc_gemm_kernel<EPI_RESID><<<gemm_c, 256, GEMM_SMEM_BYTES>>>(y, wp, bp + (size_t)l*CC, res, res, CC, CC);
        ln_kernel<<<MM, 256>>>(res, ln2_g + (size_t)l*CC, ln2_b + (size_t)l*CC, ln);
        tc_gemm_kernel<EPI_GELU><<<gemm_h, 256, GEMM_SMEM_BYTES>>>(ln, w1, b1 + (size_t)l*HID, nullptr, h1, HID, CC);
        tc_gemm_kernel<EPI_RESID><<<gemm_c, 256, GEMM_SMEM_BYTES>>>(h1, w2, b2 + (size_t)l*CC, res, res, CC, HID);
    }

    {
        int n4 = (MM * CC) / 4;
        copy4_kernel<<<(n4 + 255) / 256, 256>>>((float4*)d_out, (const float4*)res, n4);
    }
}

// round 7
// speedup vs baseline: 1.0203x; 1.0203x over previous
#include <cuda_runtime.h>
#include <math.h>
#include <cstdint>

// ---------------- problem constants ----------------
#define LNUM 4
#define BB   4
#define TT   1024
#define CC   768
#define NH   12
#define HD   64
#define HID  3072
#define MM   (BB*TT)          // 4096 rows
#define EPS_LN 1e-5f

// ---------------- scratch (device globals; no allocation allowed) ----------------
__device__ float g_res[(size_t)MM*CC];
__device__ float g_ln [(size_t)MM*CC];
__device__ float g_q  [(size_t)MM*CC];
__device__ float g_k  [(size_t)MM*CC];
__device__ float g_v  [(size_t)MM*CC];
__device__ float g_y  [(size_t)MM*CC];
__device__ float g_h1 [(size_t)MM*HID];
// tf32-rounded weights
#define WQ_OFF 0
#define WK_OFF (WQ_OFF + (size_t)LNUM*CC*CC)
#define WV_OFF (WK_OFF + (size_t)LNUM*CC*CC)
#define WP_OFF (WV_OFF + (size_t)LNUM*CC*CC)
#define W1_OFF (WP_OFF + (size_t)LNUM*CC*CC)
#define W2_OFF (W1_OFF + (size_t)LNUM*CC*HID)
#define WT_TOTAL (W2_OFF + (size_t)LNUM*CC*HID)
__device__ float g_wt [WT_TOTAL];

// ---------------- helpers ----------------
__device__ __forceinline__ uint32_t smem_u32(const void* p) {
    uint32_t a;
    asm("{ .reg .u64 t; cvta.to.shared.u64 t, %1; cvt.u32.u64 %0, t; }" : "=r"(a) : "l"(p));
    return a;
}
__device__ __forceinline__ void cp_async16(uint32_t dst, const void* src) {
    asm volatile("cp.async.cg.shared.global [%0], [%1], 16;" :: "r"(dst), "l"(src));
}
#define CP_COMMIT() asm volatile("cp.async.commit_group;" ::: "memory")
template <int N>
__device__ __forceinline__ void cp_wait() {
    asm volatile("cp.async.wait_group %0;" :: "n"(N) : "memory");
}
__device__ __forceinline__ uint32_t f2tf32(float x) {
    uint32_t u;
    asm("cvt.rna.tf32.f32 %0, %1;" : "=r"(u) : "f"(x));
    return u;
}
__device__ __forceinline__ float f2tf32f(float x) { return __uint_as_float(f2tf32(x)); }

__device__ __forceinline__ void mma_tf32(float* d, uint32_t a0, uint32_t a1, uint32_t a2,
                                         uint32_t a3, uint32_t b0, uint32_t b1) {
    asm volatile(
        "mma.sync.aligned.m16n8k8.row.col.f32.tf32.tf32.f32 "
        "{%0,%1,%2,%3}, {%4,%5,%6,%7}, {%8,%9}, {%0,%1,%2,%3};"
        : "+f"(d[0]), "+f"(d[1]), "+f"(d[2]), "+f"(d[3])
        : "r"(a0), "r"(a1), "r"(a2), "r"(a3), "r"(b0), "r"(b1));
}
__device__ __forceinline__ void ldsm_x4(uint32_t addr, uint32_t* r) {
    asm volatile("ldmatrix.sync.aligned.m8n8.x4.shared.b16 {%0,%1,%2,%3}, [%4];"
        : "=r"(r[0]), "=r"(r[1]), "=r"(r[2]), "=r"(r[3]) : "r"(addr));
}

// ---------------- small kernels ----------------
__global__ void copy4_kernel(float4* __restrict__ dst, const float4* __restrict__ src, int n4) {
    int i = blockIdx.x * blockDim.x + threadIdx.x;
    if (i < n4) dst[i] = src[i];
}

__global__ void tf32_round_kernel(const float4* __restrict__ src, float4* __restrict__ dst, int n4) {
    int i = blockIdx.x * blockDim.x + threadIdx.x;
    if (i < n4) {
        float4 v = src[i];
        uint4 u = make_uint4(f2tf32(v.x), f2tf32(v.y), f2tf32(v.z), f2tf32(v.w));
        dst[i] = *(float4*)&u;
    }
}

// layernorm; output tf32-rounded (consumed only by GEMMs)
__global__ void ln_kernel(const float* __restrict__ x, const float* __restrict__ g,
                          const float* __restrict__ b, float* __restrict__ out) {
    __shared__ float red0[8], red1[8];
    int row = blockIdx.x;
    int tid = threadIdx.x;
    const float* xr = x + (size_t)row * CC;
    float s = 0.f, s2 = 0.f;
    for (int i = tid; i < CC; i += 256) { float v = xr[i]; s += v; s2 += v * v; }
    for (int o = 16; o; o >>= 1) {
        s  += __shfl_xor_sync(0xffffffffu, s,  o);
        s2 += __shfl_xor_sync(0xffffffffu, s2, o);
    }
    if ((tid & 31) == 0) { red0[tid >> 5] = s; red1[tid >> 5] = s2; }
    __syncthreads();
    if (tid < 32) {
        s  = (tid < 8) ? red0[tid] : 0.f;
        s2 = (tid < 8) ? red1[tid] : 0.f;
        for (int o = 4; o; o >>= 1) {
            s  += __shfl_xor_sync(0xffffffffu, s,  o);
            s2 += __shfl_xor_sync(0xffffffffu, s2, o);
        }
        if (tid == 0) { red0[0] = s; red1[0] = s2; }
    }
    __syncthreads();
    float mu  = red0[0] * (1.f / CC);
    float var = red1[0] * (1.f / CC) - mu * mu;
    float rs  = rsqrtf(var + EPS_LN);
    float* outr = out + (size_t)row * CC;
    for (int i = tid; i < CC; i += 256)
        outr[i] = f2tf32f((xr[i] - mu) * rs * g[i] + b[i]);
}

// ---------------- tf32 mma.sync GEMM, cp.async 3-stage, ldmatrix A-frags ----------------
// NTILE = 128 or 64 (output tile is 128 x NTILE)
#define EPI_BIAS  0
#define EPI_RESID 1
#define EPI_GELU  2

#define STAGES 3
#define ASTR 20
#define A_STG (128 * ASTR)

#define BSTR_128 136
#define BSTR_64  72
#define GEMM_SMEM_BYTES_128 ((STAGES * (A_STG + 16 * BSTR_128) + 128) * 4)
#define GEMM_SMEM_BYTES_64  ((STAGES * (A_STG + 16 * BSTR_64)  + 128) * 4)

template <int EPI, int NTILE>
__device__ __forceinline__ void gemm_body(const float* __restrict__ A, const float* __restrict__ W,
                                          const float* __restrict__ bias, const float* __restrict__ resid,
                                          float* __restrict__ C, int Ndim, int Kdim,
                                          int bm, int bn, float* dsm) {
    constexpr int BSTR_ = (NTILE == 128) ? BSTR_128 : BSTR_64;
    constexpr int B_STG_ = 16 * BSTR_;
    constexpr int WM_CNT = (NTILE == 128) ? 2 : 4;   // warps along M
    constexpr int MW = 128 / WM_CNT;                  // 64 or 32 rows per warp
    constexpr int I_IT = MW / 16;                     // 4 or 2

    float* sA = dsm;
    float* sB = dsm + STAGES * A_STG;
    float* sBias = dsm + STAGES * (A_STG + B_STG_);

    int tid = threadIdx.x;
    int lane = tid & 31;
    int wid = tid >> 5;

    if (tid < NTILE) sBias[tid] = bias[bn + tid];

    int lr = lane >> 2;
    int lc = lane & 3;
    int wm = (wid % WM_CNT) * MW;
    int wn = (wid / WM_CNT) * 32;

    // A cp.async mapping: 2 float4/thread
    int aIdx0 = tid * 2, aIdx1 = tid * 2 + 1;
    int aRow0 = aIdx0 >> 2, aKg0 = (aIdx0 & 3) * 4;
    int aRow1 = aIdx1 >> 2, aKg1 = (aIdx1 & 3) * 4;
    // B cp.async mapping
    int bKr0, bNg0, bKr1, bNg1;
    if (NTILE == 128) {
        bKr0 = (tid * 2) >> 5;     bNg0 = ((tid * 2) & 31) * 4;
        bKr1 = (tid * 2 + 1) >> 5; bNg1 = ((tid * 2 + 1) & 31) * 4;
    } else {
        bKr0 = tid >> 4;           bNg0 = (tid & 15) * 4;
        bKr1 = 0;                  bNg1 = 0;
    }

    uint32_t sA_base = smem_u32(sA);
    uint32_t sB_base = smem_u32(sB);
    uint32_t aFrag = sA_base + (uint32_t)((wm + (lane & 15)) * ASTR) * 4 + ((lane & 16) ? 16u : 0u);

    const float* aSrc0 = A + (size_t)(bm + aRow0) * Kdim + aKg0;
    const float* aSrc1 = A + (size_t)(bm + aRow1) * Kdim + aKg1;
    const float* bSrc0 = W + (size_t)bKr0 * Ndim + bn + bNg0;
    const float* bSrc1 = W + (size_t)bKr1 * Ndim + bn + bNg1;

    float acc[I_IT][4][4];
#pragma unroll
    for (int i = 0; i < I_IT; i++)
#pragma unroll
        for (int j = 0; j < 4; j++)
#pragma unroll
            for (int r = 0; r < 4; r++) acc[i][j][r] = 0.f;

    int nch = Kdim >> 4;

    auto load_stage = [&](int stg, int chunk) {
        int _k0 = chunk << 4;
        uint32_t _ab = sA_base + (uint32_t)(stg * A_STG) * 4;
        uint32_t _bb = sB_base + (uint32_t)(stg * B_STG_) * 4;
        cp_async16(_ab + (uint32_t)(aRow0 * ASTR + aKg0) * 4, aSrc0 + _k0);
        cp_async16(_ab + (uint32_t)(aRow1 * ASTR + aKg1) * 4, aSrc1 + _k0);
        cp_async16(_bb + (uint32_t)(bKr0 * BSTR_ + bNg0) * 4, bSrc0 + (size_t)_k0 * Ndim);
        if (NTILE == 128)
            cp_async16(_bb + (uint32_t)(bKr1 * BSTR_ + bNg1) * 4, bSrc1 + (size_t)_k0 * Ndim);
    };

#pragma unroll
    for (int s = 0; s < STAGES - 1; s++) {
        if (s < nch) load_stage(s, s);
        CP_COMMIT();
    }
    cp_wait<STAGES - 2>();
    __syncthreads();

    for (int c = 0; c < nch; c++) {
        int buf = c % STAGES;
        int nc = c + STAGES - 1;
        if (nc < nch) load_stage(nc % STAGES, nc);
        CP_COMMIT();

        uint32_t aStage = aFrag + (uint32_t)(buf * A_STG) * 4;
        const uint32_t* Bs = (const uint32_t*)(sB + buf * B_STG_);

        // B fragment double-buffer: prefetch step0, then step1 during step0 mma
        uint32_t bfr[2][4][2];
#pragma unroll
        for (int j = 0; j < 4; j++) {
            int n0 = wn + j * 8 + lr;
            bfr[0][j][0] = Bs[lc * BSTR_ + n0];
            bfr[0][j][1] = Bs[(lc + 4) * BSTR_ + n0];
        }
#pragma unroll
        for (int ks = 0; ks < 2; ks++) {
            if (ks == 0) {
#pragma unroll
                for (int j = 0; j < 4; j++) {
                    int n0 = wn + j * 8 + lr;
                    bfr[1][j][0] = Bs[(8 + lc) * BSTR_ + n0];
                    bfr[1][j][1] = Bs[(8 + lc + 4) * BSTR_ + n0];
                }
            }
#pragma unroll
            for (int i = 0; i < I_IT; i++) {
                uint32_t a[4];
                ldsm_x4(aStage + (uint32_t)(i * 16 * ASTR) * 4 + ks * 32, a);
#pragma unroll
                for (int j = 0; j < 4; j++)
                    mma_tf32(acc[i][j], a[0], a[1], a[2], a[3], bfr[ks][j][0], bfr[ks][j][1]);
            }
        }
        cp_wait<STAGES - 2>();
        __syncthreads();
    }

#pragma unroll
    for (int i = 0; i < I_IT; i++) {
        int r0 = bm + wm + i * 16 + lr;
#pragma unroll
        for (int j = 0; j < 4; j++) {
            int colL = wn + j * 8 + lc * 2;
            int col = bn + colL;
            float v0 = acc[i][j][0] + sBias[colL];
            float v1 = acc[i][j][1] + sBias[colL + 1];
            float v2 = acc[i][j][2] + sBias[colL];
            float v3 = acc[i][j][3] + sBias[colL + 1];
            if (EPI == EPI_RESID) {
                float2 ra = *(const float2*)(resid + (size_t)r0 * Ndim + col);
                float2 rb = *(const float2*)(resid + (size_t)(r0 + 8) * Ndim + col);
                v0 += ra.x; v1 += ra.y; v2 += rb.x; v3 += rb.y;
            }
            if (EPI == EPI_GELU) {
                v0 = v0 * 0.5f * (1.0f + erff(v0 * 0.70710678118654752f));
                v1 = v1 * 0.5f * (1.0f + erff(v1 * 0.70710678118654752f));
                v2 = v2 * 0.5f * (1.0f + erff(v2 * 0.70710678118654752f));
                v3 = v3 * 0.5f * (1.0f + erff(v3 * 0.70710678118654752f));
            }
            if (EPI != EPI_RESID) {
                v0 = f2tf32f(v0); v1 = f2tf32f(v1); v2 = f2tf32f(v2); v3 = f2tf32f(v3);
            }
            *(float2*)(C + (size_t)r0 * Ndim + col)       = make_float2(v0, v1);
            *(float2*)(C + (size_t)(r0 + 8) * Ndim + col) = make_float2(v2, v3);
        }
    }
}

template <int EPI, int NTILE>
__global__ __launch_bounds__(256, 2)
void tc_gemm_kernel(const float* __restrict__ A, const float* __restrict__ W,
                    const float* __restrict__ bias, const float* __restrict__ resid,
                    float* __restrict__ C, int Ndim, int Kdim) {
    extern __shared__ float dsm[];
    gemm_body<EPI, NTILE>(A, W, bias, resid, C, Ndim, Kdim, blockIdx.y * 128, blockIdx.x * NTILE, dsm);
}

__global__ __launch_bounds__(256, 2)
void qkv_gemm_kernel(const float* __restrict__ A,
                     const float* __restrict__ W0, const float* __restrict__ W1, const float* __restrict__ W2,
                     const float* __restrict__ b0, const float* __restrict__ b1, const float* __restrict__ b2,
                     float* __restrict__ C0, float* __restrict__ C1, float* __restrict__ C2) {
    extern __shared__ float dsm[];
    const float* W = (blockIdx.z == 0) ? W0 : (blockIdx.z == 1) ? W1 : W2;
    const float* bi = (blockIdx.z == 0) ? b0 : (blockIdx.z == 1) ? b1 : b2;
    float* C = (blockIdx.z == 0) ? C0 : (blockIdx.z == 1) ? C1 : C2;
    gemm_body<EPI_BIAS, 128>(A, W, bi, nullptr, C, CC, CC, blockIdx.y * 128, blockIdx.x * 128, dsm);
}

// ---------------- tensor-core flash attention (inputs pre-rounded tf32) ----------------
#define QSTR 68
#define KSTR 68
#define VSTR 72
#define PSTR 68
#define ATT_Q_OFF 0
#define ATT_K_OFF (128 * QSTR)
#define ATT_V_OFF (ATT_K_OFF + 64 * KSTR)
#define ATT_P_OFF (ATT_V_OFF + 64 * VSTR)
#define ATT_M_OFF (ATT_P_OFF + 128 * PSTR)
#define ATT_L_OFF (ATT_M_OFF + 128)
#define ATTN_SMEM_WORDS (ATT_L_OFF + 128)
#define ATTN_SMEM (ATTN_SMEM_WORDS * (int)sizeof(float))

__global__ __launch_bounds__(256)
void attn_tc_kernel(const float* __restrict__ Q, const float* __restrict__ K,
                    const float* __restrict__ V, float* __restrict__ Y) {
    extern __shared__ float sm[];
    float* Qs = sm + ATT_Q_OFF;
    float* Ks = sm + ATT_K_OFF;
    float* Vs = sm + ATT_V_OFF;
    float* Ps = sm + ATT_P_OFF;
    float* mS = sm + ATT_M_OFF;
    float* lS = sm + ATT_L_OFF;

    int tid = threadIdx.x;
    int lane = tid & 31;
    int wid = tid >> 5;
    int lr = lane >> 2;
    int lc = lane & 3;
    int wr = wid * 16;

    int qb = blockIdx.x * 128;
    int bh = blockIdx.y;
    int b = bh / NH, h = bh % NH;
    size_t base = (size_t)b * TT * CC + (size_t)h * HD;

    uint32_t qFrag = smem_u32(Qs) + (uint32_t)((wr + (lane & 15)) * QSTR) * 4 + ((lane & 16) ? 16u : 0u);
    uint32_t pFrag = smem_u32(Ps) + (uint32_t)((wr + (lane & 15)) * PSTR) * 4 + ((lane & 16) ? 16u : 0u);
    uint32_t kFrag = smem_u32(Ks) + (uint32_t)(((lane & 7) + ((lane & 16) ? 8 : 0)) * KSTR) * 4
                   + ((lane & 8) ? 16u : 0u);

    for (int i = tid; i < 128 * 16; i += 256) {
        int row = i >> 4, cg = (i & 15) * 4;
        float4 qv = *(const float4*)(Q + base + (size_t)(qb + row) * CC + cg);
        *(float4*)(Qs + row * QSTR + cg) =
            make_float4(qv.x * 0.125f, qv.y * 0.125f, qv.z * 0.125f, qv.w * 0.125f);
    }
    if (tid < 128) { mS[tid] = -1e30f; lS[tid] = 0.f; }

    float o[8][4];
#pragma unroll
    for (int j = 0; j < 8; j++)
#pragma unroll
        for (int r = 0; r < 4; r++) o[j][r] = 0.f;

    int qmod = qb & 255;
    int rm0 = qmod + wr + lr;
    int rm1 = rm0 + 8;

    for (int kb = 0; kb < TT; kb += 64) {
        int kbm = kb & 255;
        if (kbm > qmod + 127) continue;
        __syncthreads();
        for (int i = tid; i < 64 * 16; i += 256) {
            int row = i >> 4, cg = (i & 15) * 4;
            *(float4*)(Ks + row * KSTR + cg) = *(const float4*)(K + base + (size_t)(kb + row) * CC + cg);
            *(float4*)(Vs + row * VSTR + cg) = *(const float4*)(V + base + (size_t)(kb + row) * CC + cg);
        }
        __syncthreads();

        // ---- S = Q K^T ----
        float sacc[8][4];
#pragma unroll
        for (int j = 0; j < 8; j++)
#pragma unroll
            for (int r = 0; r < 4; r++) sacc[j][r] = 0.f;
#pragma unroll
        for (int ks = 0; ks < 8; ks++) {
            uint32_t a[4];
            ldsm_x4(qFrag + ks * 32, a);
#pragma unroll
            for (int jp = 0; jp < 4; jp++) {
                uint32_t bk[4];
                ldsm_x4(kFrag + (uint32_t)(jp * 16 * KSTR) * 4 + ks * 32, bk);
                mma_tf32(sacc[2 * jp],     a[0], a[1], a[2], a[3], bk[0], bk[1]);
                mma_tf32(sacc[2 * jp + 1], a[0], a[1], a[2], a[3], bk[2], bk[3]);
            }
        }

        // ---- mask + online softmax ----
        float m0 = -1e30f, m1 = -1e30f;
#pragma unroll
        for (int j = 0; j < 8; j++) {
            int c0 = kbm + j * 8 + 2 * lc;
            if (c0 > rm0)     sacc[j][0] = -1e30f;
            if (c0 + 1 > rm0) sacc[j][1] = -1e30f;
            if (c0 > rm1)     sacc[j][2] = -1e30f;
            if (c0 + 1 > rm1) sacc[j][3] = -1e30f;
            m0 = fmaxf(m0, fmaxf(sacc[j][0], sacc[j][1]));
            m1 = fmaxf(m1, fmaxf(sacc[j][2], sacc[j][3]));
        }
        m0 = fmaxf(m0, __shfl_xor_sync(0xffffffffu, m0, 1));
        m0 = fmaxf(m0, __shfl_xor_sync(0xffffffffu, m0, 2));
        m1 = fmaxf(m1, __shfl_xor_sync(0xffffffffu, m1, 1));
        m1 = fmaxf(m1, __shfl_xor_sync(0xffffffffu, m1, 2));

        int r0 = wr + lr, r1 = r0 + 8;
        float mo0 = mS[r0], mo1 = mS[r1];
        float mn0 = fmaxf(mo0, m0), mn1 = fmaxf(mo1, m1);
        float al0 = __expf(mo0 - mn0), al1 = __expf(mo1 - mn1);

        float sum0 = 0.f, sum1 = 0.f;
#pragma unroll
        for (int j = 0; j < 8; j++) {
            float p00 = __expf(sacc[j][0] - mn0);
            float p01 = __expf(sacc[j][1] - mn0);
            float p10 = __expf(sacc[j][2] - mn1);
            float p11 = __expf(sacc[j][3] - mn1);
            sum0 += p00 + p01;
            sum1 += p10 + p11;
            uint2 u0 = make_uint2(f2tf32(p00), f2tf32(p01));
            uint2 u1 = make_uint2(f2tf32(p10), f2tf32(p11));
            *(uint2*)(Ps + r0 * PSTR + j * 8 + 2 * lc) = u0;
            *(uint2*)(Ps + r1 * PSTR + j * 8 + 2 * lc) = u1;
            o[j][0] *= al0; o[j][1] *= al0; o[j][2] *= al1; o[j][3] *= al1;
        }
        sum0 += __shfl_xor_sync(0xffffffffu, sum0, 1);
        sum0 += __shfl_xor_sync(0xffffffffu, sum0, 2);
        sum1 += __shfl_xor_sync(0xffffffffu, sum1, 1);
        sum1 += __shfl_xor_sync(0xffffffffu, sum1, 2);
        if (lc == 0) {
            lS[r0] = lS[r0] * al0 + sum0;
            lS[r1] = lS[r1] * al1 + sum1;
            mS[r0] = mn0;
            mS[r1] = mn1;
        }
        __syncwarp();

        // ---- O += P V ----
#pragma unroll
        for (int ks = 0; ks < 8; ks++) {
            int k0 = ks * 8;
            uint32_t a[4];
            ldsm_x4(pFrag + ks * 32, a);
#pragma unroll
            for (int j = 0; j < 8; j++) {
                int n0 = j * 8 + lr;
                uint32_t b0 = *(const uint32_t*)(Vs + (k0 + lc) * VSTR + n0);
                uint32_t b1 = *(const uint32_t*)(Vs + (k0 + lc + 4) * VSTR + n0);
                mma_tf32(o[j], a[0], a[1], a[2], a[3], b0, b1);
            }
        }
    }

    __syncwarp();
    int r0 = wr + lr, r1 = r0 + 8;
    float inv0 = 1.0f / lS[r0];
    float inv1 = 1.0f / lS[r1];
#pragma unroll
    for (int j = 0; j < 8; j++) {
        int d = j * 8 + 2 * lc;
        *(float2*)(Y + base + (size_t)(qb + r0) * CC + d) =
            make_float2(f2tf32f(o[j][0] * inv0), f2tf32f(o[j][1] * inv0));
        *(float2*)(Y + base + (size_t)(qb + r1) * CC + d) =
            make_float2(f2tf32f(o[j][2] * inv1), f2tf32f(o[j][3] * inv1));
    }
}

// ---------------- host orchestration ----------------
extern "C" void kernel_launch(void* const* d_in, const int* in_sizes, int n_in,
                              void* d_out, int out_size) {
    const float* x     = (const float*)d_in[0];
    const float* ln1_g = (const float*)d_in[1];
    const float* ln1_b = (const float*)d_in[2];
    const float* Wq    = (const float*)d_in[3];
    const float* bq    = (const float*)d_in[4];
    const float* Wk    = (const float*)d_in[5];
    const float* bk    = (const float*)d_in[6];
    const float* Wv    = (const float*)d_in[7];
    const float* bv    = (const float*)d_in[8];
    const float* Wp    = (const float*)d_in[9];
    const float* bp    = (const float*)d_in[10];
    const float* ln2_g = (const float*)d_in[11];
    const float* ln2_b = (const float*)d_in[12];
    const float* W1    = (const float*)d_in[13];
    const float* b1    = (const float*)d_in[14];
    const float* W2    = (const float*)d_in[15];
    const float* b2    = (const float*)d_in[16];

    float *res, *ln, *q, *k, *v, *y, *h1, *wt;
    cudaGetSymbolAddress((void**)&res, g_res);
    cudaGetSymbolAddress((void**)&ln,  g_ln);
    cudaGetSymbolAddress((void**)&q,   g_q);
    cudaGetSymbolAddress((void**)&k,   g_k);
    cudaGetSymbolAddress((void**)&v,   g_v);
    cudaGetSymbolAddress((void**)&y,   g_y);
    cudaGetSymbolAddress((void**)&h1,  g_h1);
    cudaGetSymbolAddress((void**)&wt,  g_wt);

    cudaFuncSetAttribute(attn_tc_kernel, cudaFuncAttributeMaxDynamicSharedMemorySize, ATTN_SMEM);
    cudaFuncSetAttribute(tc_gemm_kernel<EPI_RESID, 64>,  cudaFuncAttributeMaxDynamicSharedMemorySize, GEMM_SMEM_BYTES_64);
    cudaFuncSetAttribute(tc_gemm_kernel<EPI_GELU, 128>,  cudaFuncAttributeMaxDynamicSharedMemorySize, GEMM_SMEM_BYTES_128);
    cudaFuncSetAttribute(qkv_gemm_kernel,                cudaFuncAttributeMaxDynamicSharedMemorySize, GEMM_SMEM_BYTES_128);

    // ---- pre-round weights to tf32 ----
    {
        int nCC = LNUM * CC * CC / 4, nCH = LNUM * CC * HID / 4;
        int tb = 256;
        tf32_round_kernel<<<(nCC + tb - 1) / tb, tb>>>((const float4*)Wq, (float4*)(wt + WQ_OFF), nCC);
        tf32_round_kernel<<<(nCC + tb - 1) / tb, tb>>>((const float4*)Wk, (float4*)(wt + WK_OFF), nCC);
        tf32_round_kernel<<<(nCC + tb - 1) / tb, tb>>>((const float4*)Wv, (float4*)(wt + WV_OFF), nCC);
        tf32_round_kernel<<<(nCC + tb - 1) / tb, tb>>>((const float4*)Wp, (float4*)(wt + WP_OFF), nCC);
        tf32_round_kernel<<<(nCH + tb - 1) / tb, tb>>>((const float4*)W1, (float4*)(wt + W1_OFF), nCH);
        tf32_round_kernel<<<(nCH + tb - 1) / tb, tb>>>((const float4*)W2, (float4*)(wt + W2_OFF), nCH);
    }

    // residual = x
    {
        int n4 = (MM * CC) / 4;
        copy4_kernel<<<(n4 + 255) / 256, 256>>>((float4*)res, (const float4*)x, n4);
    }

    dim3 gemm_qkv3(CC / 128, MM / 128, 3);   // 6 x 32 x 3 = 576
    dim3 gemm_c64 (CC / 64,  MM / 128);      // 12 x 32 = 384
    dim3 gemm_h   (HID / 128, MM / 128);     // 24 x 32 = 768
    dim3 attn_grid(TT / 128, BB * NH);       // 8 x 48 = 384

    for (int l = 0; l < LNUM; l++) {
        const float* wq = wt + WQ_OFF + (size_t)l * CC * CC;
        const float* wk = wt + WK_OFF + (size_t)l * CC * CC;
        const float* wv = wt + WV_OFF + (size_t)l * CC * CC;
        const float* wp = wt + WP_OFF + (size_t)l * CC * CC;
        const float* w1 = wt + W1_OFF + (size_t)l * CC * HID;
        const float* w2 = wt + W2_OFF + (size_t)l * HID * CC;

        ln_kernel<<<MM, 256>>>(res, ln1_g + (size_t)l*CC, ln1_b + (size_t)l*CC, ln);
        qkv_gemm_kernel<<<gemm_qkv3, 256, GEMM_SMEM_BYTES_128>>>(
            ln, wq, wk, wv, bq + (size_t)l*CC, bk + (size_t)l*CC, bv + (size_t)l*CC, q, k, v);
        attn_tc_kernel<<<attn_grid, 256, ATTN_SMEM>>>(q, k, v, y);
        tc_gemm_kernel<EPI_RESID, 64><<<gemm_c64, 256, GEMM_SMEM_BYTES_64>>>(y, wp, bp + (size_t)l*CC, res, res, CC, CC);
        ln_kernel<<<MM, 256>>>(res, ln2_g + (size_t)l*CC, ln2_b + (size_t)l*CC, ln);
        tc_gemm_kernel<EPI_GELU, 128><<<gemm_h, 256, GEMM_SMEM_BYTES_128>>>(ln, w1, b1 + (size_t)l*HID, nullptr, h1, HID, CC);
        tc_gemm_kernel<EPI_RESID, 64><<<gemm_c64, 256, GEMM_SMEM_BYTES_64>>>(h1, w2, b2 + (size_t)l*CC, res, res, CC, HID);
    }

    {
        int n4 = (MM * CC) / 4;
        copy4_kernel<<<(n4 + 255) / 256, 256>>>((float4*)d_out, (const float4*)res, n4);
    }
}

// round 8
// speedup vs baseline: 1.5344x; 1.5039x over previous
#include <cuda_runtime.h>
#include <cuda_fp16.h>
#include <math.h>
#include <cstdint>

// ---------------- problem constants ----------------
#define LNUM 4
#define BB   4
#define TT   1024
#define CC   768
#define NH   12
#define HD   64
#define HID  3072
#define MM   (BB*TT)          // 4096 rows
#define EPS_LN 1e-5f

// ---------------- scratch (device globals; no allocation allowed) ----------------
__device__ float  g_res[(size_t)MM*CC];
__device__ __half g_ln [(size_t)MM*CC];
__device__ float  g_q  [(size_t)MM*CC];
__device__ float  g_k  [(size_t)MM*CC];
__device__ float  g_v  [(size_t)MM*CC];
__device__ __half g_y  [(size_t)MM*CC];
__device__ __half g_h1 [(size_t)MM*HID];
// half, transposed [N][K] weights
#define WQ_OFF 0
#define WK_OFF (WQ_OFF + (size_t)LNUM*CC*CC)
#define WV_OFF (WK_OFF + (size_t)LNUM*CC*CC)
#define WP_OFF (WV_OFF + (size_t)LNUM*CC*CC)
#define W1_OFF (WP_OFF + (size_t)LNUM*CC*CC)
#define W2_OFF (W1_OFF + (size_t)LNUM*CC*HID)
#define WT_TOTAL (W2_OFF + (size_t)LNUM*CC*HID)
__device__ __half g_wt [WT_TOTAL];

// ---------------- helpers ----------------
__device__ __forceinline__ uint32_t smem_u32(const void* p) {
    uint32_t a;
    asm("{ .reg .u64 t; cvta.to.shared.u64 t, %1; cvt.u32.u64 %0, t; }" : "=r"(a) : "l"(p));
    return a;
}
__device__ __forceinline__ void cp_async16(uint32_t dst, const void* src) {
    asm volatile("cp.async.cg.shared.global [%0], [%1], 16;" :: "r"(dst), "l"(src));
}
#define CP_COMMIT() asm volatile("cp.async.commit_group;" ::: "memory")
template <int N>
__device__ __forceinline__ void cp_wait() {
    asm volatile("cp.async.wait_group %0;" :: "n"(N) : "memory");
}
__device__ __forceinline__ uint32_t f2tf32(float x) {
    uint32_t u;
    asm("cvt.rna.tf32.f32 %0, %1;" : "=r"(u) : "f"(x));
    return u;
}
__device__ __forceinline__ float f2tf32f(float x) { return __uint_as_float(f2tf32(x)); }

__device__ __forceinline__ void mma_tf32(float* d, uint32_t a0, uint32_t a1, uint32_t a2,
                                         uint32_t a3, uint32_t b0, uint32_t b1) {
    asm volatile(
        "mma.sync.aligned.m16n8k8.row.col.f32.tf32.tf32.f32 "
        "{%0,%1,%2,%3}, {%4,%5,%6,%7}, {%8,%9}, {%0,%1,%2,%3};"
        : "+f"(d[0]), "+f"(d[1]), "+f"(d[2]), "+f"(d[3])
        : "r"(a0), "r"(a1), "r"(a2), "r"(a3), "r"(b0), "r"(b1));
}
__device__ __forceinline__ void mma_f16(float* d, uint32_t a0, uint32_t a1, uint32_t a2,
                                        uint32_t a3, uint32_t b0, uint32_t b1) {
    asm volatile(
        "mma.sync.aligned.m16n8k16.row.col.f32.f16.f16.f32 "
        "{%0,%1,%2,%3}, {%4,%5,%6,%7}, {%8,%9}, {%0,%1,%2,%3};"
        : "+f"(d[0]), "+f"(d[1]), "+f"(d[2]), "+f"(d[3])
        : "r"(a0), "r"(a1), "r"(a2), "r"(a3), "r"(b0), "r"(b1));
}
__device__ __forceinline__ void ldsm_x4(uint32_t addr, uint32_t* r) {
    asm volatile("ldmatrix.sync.aligned.m8n8.x4.shared.b16 {%0,%1,%2,%3}, [%4];"
        : "=r"(r[0]), "=r"(r[1]), "=r"(r[2]), "=r"(r[3]) : "r"(addr));
}

// ---------------- small kernels ----------------
__global__ void copy4_kernel(float4* __restrict__ dst, const float4* __restrict__ src, int n4) {
    int i = blockIdx.x * blockDim.x + threadIdx.x;
    if (i < n4) dst[i] = src[i];
}

// convert fp32 [K][N] weight -> half transposed [N][K]; grid.z = layer
__global__ void convT_kernel(const float* __restrict__ src, __half* __restrict__ dst,
                             int K, int N) {
    __shared__ float tile[32][33];
    const float* s = src + (size_t)blockIdx.z * K * N;
    __half* d = dst + (size_t)blockIdx.z * K * N;
    int tx = threadIdx.x, ty = threadIdx.y;
    int n0 = blockIdx.x * 32, k0 = blockIdx.y * 32;
#pragma unroll
    for (int i = 0; i < 32; i += 8)
        tile[ty + i][tx] = s[(size_t)(k0 + ty + i) * N + n0 + tx];
    __syncthreads();
#pragma unroll
    for (int i = 0; i < 32; i += 8)
        d[(size_t)(n0 + ty + i) * K + k0 + tx] = __float2half_rn(tile[tx][ty + i]);
}

// layernorm; output half (consumed only as GEMM A operand)
__global__ void ln_kernel(const float* __restrict__ x, const float* __restrict__ g,
                          const float* __restrict__ b, __half* __restrict__ out) {
    __shared__ float red0[8], red1[8];
    int row = blockIdx.x;
    int tid = threadIdx.x;
    const float* xr = x + (size_t)row * CC;
    float s = 0.f, s2 = 0.f;
    for (int i = tid; i < CC; i += 256) { float v = xr[i]; s += v; s2 += v * v; }
    for (int o = 16; o; o >>= 1) {
        s  += __shfl_xor_sync(0xffffffffu, s,  o);
        s2 += __shfl_xor_sync(0xffffffffu, s2, o);
    }
    if ((tid & 31) == 0) { red0[tid >> 5] = s; red1[tid >> 5] = s2; }
    __syncthreads();
    if (tid < 32) {
        s  = (tid < 8) ? red0[tid] : 0.f;
        s2 = (tid < 8) ? red1[tid] : 0.f;
        for (int o = 4; o; o >>= 1) {
            s  += __shfl_xor_sync(0xffffffffu, s,  o);
            s2 += __shfl_xor_sync(0xffffffffu, s2, o);
        }
        if (tid == 0) { red0[0] = s; red1[0] = s2; }
    }
    __syncthreads();
    float mu  = red0[0] * (1.f / CC);
    float var = red1[0] * (1.f / CC) - mu * mu;
    float rs  = rsqrtf(var + EPS_LN);
    __half* outr = out + (size_t)row * CC;
    for (int i = tid; i < CC; i += 256)
        outr[i] = __float2half_rn((xr[i] - mu) * rs * g[i] + b[i]);
}

// ---------------- fp16 mma.sync GEMM, cp.async 3-stage, BK=32 ----------------
// C[M,N] = A[M,K](half) @ Wt[N,K](half)^T ; tile 128x128, 8 warps (warp 64x32).
#define EPI_BIAS  0
#define EPI_RESID 1
#define EPI_GELU  2

#define STAGES 3
#define BK 32
#define ASTR_H 40                      // halfs per A row (32 data + 8 pad) = 80B
#define BSTR_H 40                      // halfs per B row
#define A_STG_H (128 * ASTR_H)         // 5120 halfs
#define B_STG_H (128 * BSTR_H)         // 5120 halfs
#define GEMM_SMEM_BYTES (STAGES * (A_STG_H + B_STG_H) * 2 + 512)   // 61,952 B

template <int EPI, typename OutT>
__device__ __forceinline__ void gemm_body(const __half* __restrict__ A, const __half* __restrict__ Wt,
                                          const float* __restrict__ bias, const float* __restrict__ resid,
                                          OutT* __restrict__ C, int Ndim, int Kdim,
                                          int bm, int bn, char* dsm) {
    __half* sA = (__half*)dsm;
    __half* sB = (__half*)dsm + STAGES * A_STG_H;
    float* sBias = (float*)(dsm + STAGES * (A_STG_H + B_STG_H) * 2);

    int tid = threadIdx.x;
    int lane = tid & 31;
    int wid = tid >> 5;

    if (tid < 128) sBias[tid] = bias[bn + tid];

    int lr = lane >> 2;
    int lc = lane & 3;
    int wm = (wid & 1) * 64;
    int wn = (wid >> 1) * 32;

    // cp.async: 2 16B-chunks for A + 2 for B per thread per stage
    int idx0 = tid * 2, idx1 = tid * 2 + 1;
    int r0i = idx0 >> 2, s0i = (idx0 & 3) * 8;   // row, half-offset (8 halfs = 16B)
    int r1i = idx1 >> 2, s1i = (idx1 & 3) * 8;

    uint32_t sA_base = smem_u32(sA);
    uint32_t sB_base = smem_u32(sB);
    // ldmatrix A-frag base: row = wm + (lane&15), 16B col-half via lane&16
    uint32_t aFrag = sA_base + (uint32_t)((wm + (lane & 15)) * ASTR_H) * 2 + ((lane & 16) ? 16u : 0u);

    const __half* aSrc0 = A + (size_t)(bm + r0i) * Kdim + s0i;
    const __half* aSrc1 = A + (size_t)(bm + r1i) * Kdim + s1i;
    const __half* bSrc0 = Wt + (size_t)(bn + r0i) * Kdim + s0i;
    const __half* bSrc1 = Wt + (size_t)(bn + r1i) * Kdim + s1i;

    float acc[4][4][4];
#pragma unroll
    for (int i = 0; i < 4; i++)
#pragma unroll
        for (int j = 0; j < 4; j++)
#pragma unroll
            for (int r = 0; r < 4; r++) acc[i][j][r] = 0.f;

    int nch = Kdim / BK;

    auto load_stage = [&](int stg, int chunk) {
        int k0 = chunk * BK;
        uint32_t ab = sA_base + (uint32_t)(stg * A_STG_H) * 2;
        uint32_t bb = sB_base + (uint32_t)(stg * B_STG_H) * 2;
        cp_async16(ab + (uint32_t)(r0i * ASTR_H + s0i) * 2, aSrc0 + k0);
        cp_async16(ab + (uint32_t)(r1i * ASTR_H + s1i) * 2, aSrc1 + k0);
        cp_async16(bb + (uint32_t)(r0i * BSTR_H + s0i) * 2, bSrc0 + k0);
        cp_async16(bb + (uint32_t)(r1i * BSTR_H + s1i) * 2, bSrc1 + k0);
    };

#pragma unroll
    for (int s = 0; s < STAGES - 1; s++) {
        if (s < nch) load_stage(s, s);
        CP_COMMIT();
    }
    cp_wait<STAGES - 2>();
    __syncthreads();

    for (int c = 0; c < nch; c++) {
        int buf = c % STAGES;
        int nc = c + STAGES - 1;
        if (nc < nch) load_stage(nc % STAGES, nc);
        CP_COMMIT();

        uint32_t aStage = aFrag + (uint32_t)(buf * A_STG_H) * 2;
        const uint32_t* Bs = (const uint32_t*)(sB + buf * B_STG_H);   // 20 words per row

        // B fragment double-buffer across the 2 k16 steps
        uint32_t bfr[2][4][2];
#pragma unroll
        for (int j = 0; j < 4; j++) {
            int n0 = wn + j * 8 + lr;
            bfr[0][j][0] = Bs[n0 * 20 + lc];
            bfr[0][j][1] = Bs[n0 * 20 + 4 + lc];
        }
#pragma unroll
        for (int ks = 0; ks < 2; ks++) {
            if (ks == 0) {
#pragma unroll
                for (int j = 0; j < 4; j++) {
                    int n0 = wn + j * 8 + lr;
                    bfr[1][j][0] = Bs[n0 * 20 + 8 + lc];
                    bfr[1][j][1] = Bs[n0 * 20 + 12 + lc];
                }
            }
#pragma unroll
            for (int i = 0; i < 4; i++) {
                uint32_t a[4];
                ldsm_x4(aStage + (uint32_t)(i * 16 * ASTR_H) * 2 + ks * 32, a);
#pragma unroll
                for (int j = 0; j < 4; j++)
                    mma_f16(acc[i][j], a[0], a[1], a[2], a[3], bfr[ks][j][0], bfr[ks][j][1]);
            }
        }
        cp_wait<STAGES - 2>();
        __syncthreads();
    }

#pragma unroll
    for (int i = 0; i < 4; i++) {
        int r0 = bm + wm + i * 16 + lr;
#pragma unroll
        for (int j = 0; j < 4; j++) {
            int colL = wn + j * 8 + lc * 2;
            int col = bn + colL;
            float v0 = acc[i][j][0] + sBias[colL];
            float v1 = acc[i][j][1] + sBias[colL + 1];
            float v2 = acc[i][j][2] + sBias[colL];
            float v3 = acc[i][j][3] + sBias[colL + 1];
            if (EPI == EPI_RESID) {
                float2 ra = *(const float2*)(resid + (size_t)r0 * Ndim + col);
                float2 rb = *(const float2*)(resid + (size_t)(r0 + 8) * Ndim + col);
                v0 += ra.x; v1 += ra.y; v2 += rb.x; v3 += rb.y;
            }
            if (EPI == EPI_GELU) {
                v0 = v0 * 0.5f * (1.0f + erff(v0 * 0.70710678118654752f));
                v1 = v1 * 0.5f * (1.0f + erff(v1 * 0.70710678118654752f));
                v2 = v2 * 0.5f * (1.0f + erff(v2 * 0.70710678118654752f));
                v3 = v3 * 0.5f * (1.0f + erff(v3 * 0.70710678118654752f));
            }
            if (sizeof(OutT) == 4) {
                float w0 = v0, w1 = v1, w2 = v2, w3 = v3;
                if (EPI == EPI_BIAS) {   // q/k/v feed tf32 attention: pre-round
                    w0 = f2tf32f(w0); w1 = f2tf32f(w1); w2 = f2tf32f(w2); w3 = f2tf32f(w3);
                }
                *(float2*)((float*)C + (size_t)r0 * Ndim + col)       = make_float2(w0, w1);
                *(float2*)((float*)C + (size_t)(r0 + 8) * Ndim + col) = make_float2(w2, w3);
            } else {
                *(__half2*)((__half*)C + (size_t)r0 * Ndim + col)       = __floats2half2_rn(v0, v1);
                *(__half2*)((__half*)C + (size_t)(r0 + 8) * Ndim + col) = __floats2half2_rn(v2, v3);
            }
        }
    }
}

template <int EPI, typename OutT>
__global__ __launch_bounds__(256, 2)
void tc_gemm_kernel(const __half* __restrict__ A, const __half* __restrict__ Wt,
                    const float* __restrict__ bias, const float* __restrict__ resid,
                    OutT* __restrict__ C, int Ndim, int Kdim) {
    extern __shared__ char dsm[];
    gemm_body<EPI, OutT>(A, Wt, bias, resid, C, Ndim, Kdim, blockIdx.y * 128, blockIdx.x * 128, dsm);
}

__global__ __launch_bounds__(256, 2)
void qkv_gemm_kernel(const __half* __restrict__ A,
                     const __half* __restrict__ W0, const __half* __restrict__ W1, const __half* __restrict__ W2,
                     const float* __restrict__ b0, const float* __restrict__ b1, const float* __restrict__ b2,
                     float* __restrict__ C0, float* __restrict__ C1, float* __restrict__ C2) {
    extern __shared__ char dsm[];
    const __half* W = (blockIdx.z == 0) ? W0 : (blockIdx.z == 1) ? W1 : W2;
    const float* bi = (blockIdx.z == 0) ? b0 : (blockIdx.z == 1) ? b1 : b2;
    float* C = (blockIdx.z == 0) ? C0 : (blockIdx.z == 1) ? C1 : C2;
    gemm_body<EPI_BIAS, float>(A, W, bi, nullptr, C, CC, CC, blockIdx.y * 128, blockIdx.x * 128, dsm);
}

// ---------------- tensor-core flash attention (tf32; q/k/v fp32 pre-rounded) ----------------
#define QSTR 68
#define KSTR 68
#define VSTR 72
#define PSTR 68
#define ATT_Q_OFF 0
#define ATT_K_OFF (128 * QSTR)
#define ATT_V_OFF (ATT_K_OFF + 64 * KSTR)
#define ATT_P_OFF (ATT_V_OFF + 64 * VSTR)
#define ATT_M_OFF (ATT_P_OFF + 128 * PSTR)
#define ATT_L_OFF (ATT_M_OFF + 128)
#define ATTN_SMEM_WORDS (ATT_L_OFF + 128)
#define ATTN_SMEM (ATTN_SMEM_WORDS * (int)sizeof(float))

__global__ __launch_bounds__(256)
void attn_tc_kernel(const float* __restrict__ Q, const float* __restrict__ K,
                    const float* __restrict__ V, __half* __restrict__ Y) {
    extern __shared__ float sm[];
    float* Qs = sm + ATT_Q_OFF;
    float* Ks = sm + ATT_K_OFF;
    float* Vs = sm + ATT_V_OFF;
    float* Ps = sm + ATT_P_OFF;
    float* mS = sm + ATT_M_OFF;
    float* lS = sm + ATT_L_OFF;

    int tid = threadIdx.x;
    int lane = tid & 31;
    int wid = tid >> 5;
    int lr = lane >> 2;
    int lc = lane & 3;
    int wr = wid * 16;

    int qb = blockIdx.x * 128;
    int bh = blockIdx.y;
    int b = bh / NH, h = bh % NH;
    size_t base = (size_t)b * TT * CC + (size_t)h * HD;

    uint32_t qFrag = smem_u32(Qs) + (uint32_t)((wr + (lane & 15)) * QSTR) * 4 + ((lane & 16) ? 16u : 0u);
    uint32_t pFrag = smem_u32(Ps) + (uint32_t)((wr + (lane & 15)) * PSTR) * 4 + ((lane & 16) ? 16u : 0u);
    uint32_t kFrag = smem_u32(Ks) + (uint32_t)(((lane & 7) + ((lane & 16) ? 8 : 0)) * KSTR) * 4
                   + ((lane & 8) ? 16u : 0u);

    for (int i = tid; i < 128 * 16; i += 256) {
        int row = i >> 4, cg = (i & 15) * 4;
        float4 qv = *(const float4*)(Q + base + (size_t)(qb + row) * CC + cg);
        *(float4*)(Qs + row * QSTR + cg) =
            make_float4(qv.x * 0.125f, qv.y * 0.125f, qv.z * 0.125f, qv.w * 0.125f);
    }
    if (tid < 128) { mS[tid] = -1e30f; lS[tid] = 0.f; }

    float o[8][4];
#pragma unroll
    for (int j = 0; j < 8; j++)
#pragma unroll
        for (int r = 0; r < 4; r++) o[j][r] = 0.f;

    int qmod = qb & 255;
    int rm0 = qmod + wr + lr;
    int rm1 = rm0 + 8;

    for (int kb = 0; kb < TT; kb += 64) {
        int kbm = kb & 255;
        if (kbm > qmod + 127) continue;
        __syncthreads();
        for (int i = tid; i < 64 * 16; i += 256) {
            int row = i >> 4, cg = (i & 15) * 4;
            *(float4*)(Ks + row * KSTR + cg) = *(const float4*)(K + base + (size_t)(kb + row) * CC + cg);
            *(float4*)(Vs + row * VSTR + cg) = *(const float4*)(V + base + (size_t)(kb + row) * CC + cg);
        }
        __syncthreads();

        float sacc[8][4];
#pragma unroll
        for (int j = 0; j < 8; j++)
#pragma unroll
            for (int r = 0; r < 4; r++) sacc[j][r] = 0.f;
#pragma unroll
        for (int ks = 0; ks < 8; ks++) {
            uint32_t a[4];
            ldsm_x4(qFrag + ks * 32, a);
#pragma unroll
            for (int jp = 0; jp < 4; jp++) {
                uint32_t bk[4];
                ldsm_x4(kFrag + (uint32_t)(jp * 16 * KSTR) * 4 + ks * 32, bk);
                mma_tf32(sacc[2 * jp],     a[0], a[1], a[2], a[3], bk[0], bk[1]);
                mma_tf32(sacc[2 * jp + 1], a[0], a[1], a[2], a[3], bk[2], bk[3]);
            }
        }

        float m0 = -1e30f, m1 = -1e30f;
#pragma unroll
        for (int j = 0; j < 8; j++) {
            int c0 = kbm + j * 8 + 2 * lc;
            if (c0 > rm0)     sacc[j][0] = -1e30f;
            if (c0 + 1 > rm0) sacc[j][1] = -1e30f;
            if (c0 > rm1)     sacc[j][2] = -1e30f;
            if (c0 + 1 > rm1) sacc[j][3] = -1e30f;
            m0 = fmaxf(m0, fmaxf(sacc[j][0], sacc[j][1]));
            m1 = fmaxf(m1, fmaxf(sacc[j][2], sacc[j][3]));
        }
        m0 = fmaxf(m0, __shfl_xor_sync(0xffffffffu, m0, 1));
        m0 = fmaxf(m0, __shfl_xor_sync(0xffffffffu, m0, 2));
        m1 = fmaxf(m1, __shfl_xor_sync(0xffffffffu, m1, 1));
        m1 = fmaxf(m1, __shfl_xor_sync(0xffffffffu, m1, 2));

        int r0 = wr + lr, r1 = r0 + 8;
        float mo0 = mS[r0], mo1 = mS[r1];
        float mn0 = fmaxf(mo0, m0), mn1 = fmaxf(mo1, m1);
        float al0 = __expf(mo0 - mn0), al1 = __expf(mo1 - mn1);

        float sum0 = 0.f, sum1 = 0.f;
#pragma unroll
        for (int j = 0; j < 8; j++) {
            float p00 = __expf(sacc[j][0] - mn0);
            float p01 = __expf(sacc[j][1] - mn0);
            float p10 = __expf(sacc[j][2] - mn1);
            float p11 = __expf(sacc[j][3] - mn1);
            sum0 += p00 + p01;
            sum1 += p10 + p11;
            uint2 u0 = make_uint2(f2tf32(p00), f2tf32(p01));
            uint2 u1 = make_uint2(f2tf32(p10), f2tf32(p11));
            *(uint2*)(Ps + r0 * PSTR + j * 8 + 2 * lc) = u0;
            *(uint2*)(Ps + r1 * PSTR + j * 8 + 2 * lc) = u1;
            o[j][0] *= al0; o[j][1] *= al0; o[j][2] *= al1; o[j][3] *= al1;
        }
        sum0 += __shfl_xor_sync(0xffffffffu, sum0, 1);
        sum0 += __shfl_xor_sync(0xffffffffu, sum0, 2);
        sum1 += __shfl_xor_sync(0xffffffffu, sum1, 1);
        sum1 += __shfl_xor_sync(0xffffffffu, sum1, 2);
        if (lc == 0) {
            lS[r0] = lS[r0] * al0 + sum0;
            lS[r1] = lS[r1] * al1 + sum1;
            mS[r0] = mn0;
            mS[r1] = mn1;
        }
        __syncwarp();

#pragma unroll
        for (int ks = 0; ks < 8; ks++) {
            int k0 = ks * 8;
            uint32_t a[4];
            ldsm_x4(pFrag + ks * 32, a);
#pragma unroll
            for (int j = 0; j < 8; j++) {
                int n0 = j * 8 + lr;
                uint32_t b0 = *(const uint32_t*)(Vs + (k0 + lc) * VSTR + n0);
                uint32_t b1 = *(const uint32_t*)(Vs + (k0 + lc + 4) * VSTR + n0);
                mma_tf32(o[j], a[0], a[1], a[2], a[3], b0, b1);
            }
        }
    }

    __syncwarp();
    int r0 = wr + lr, r1 = r0 + 8;
    float inv0 = 1.0f / lS[r0];
    float inv1 = 1.0f / lS[r1];
#pragma unroll
    for (int j = 0; j < 8; j++) {
        int d = j * 8 + 2 * lc;
        *(__half2*)(Y + base + (size_t)(qb + r0) * CC + d) =
            __floats2half2_rn(o[j][0] * inv0, o[j][1] * inv0);
        *(__half2*)(Y + base + (size_t)(qb + r1) * CC + d) =
            __floats2half2_rn(o[j][2] * inv1, o[j][3] * inv1);
    }
}

// ---------------- host orchestration ----------------
extern "C" void kernel_launch(void* const* d_in, const int* in_sizes, int n_in,
                              void* d_out, int out_size) {
    const float* x     = (const float*)d_in[0];
    const float* ln1_g = (const float*)d_in[1];
    const float* ln1_b = (const float*)d_in[2];
    const float* Wq    = (const float*)d_in[3];
    const float* bq    = (const float*)d_in[4];
    const float* Wk    = (const float*)d_in[5];
    const float* bk    = (const float*)d_in[6];
    const float* Wv    = (const float*)d_in[7];
    const float* bv    = (const float*)d_in[8];
    const float* Wp    = (const float*)d_in[9];
    const float* bp    = (const float*)d_in[10];
    const float* ln2_g = (const float*)d_in[11];
    const float* ln2_b = (const float*)d_in[12];
    const float* W1    = (const float*)d_in[13];
    const float* b1    = (const float*)d_in[14];
    const float* W2    = (const float*)d_in[15];
    const float* b2    = (const float*)d_in[16];

    float *res, *q, *k, *v;
    __half *ln, *y, *h1, *wt;
    cudaGetSymbolAddress((void**)&res, g_res);
    cudaGetSymbolAddress((void**)&ln,  g_ln);
    cudaGetSymbolAddress((void**)&q,   g_q);
    cudaGetSymbolAddress((void**)&k,   g_k);
    cudaGetSymbolAddress((void**)&v,   g_v);
    cudaGetSymbolAddress((void**)&y,   g_y);
    cudaGetSymbolAddress((void**)&h1,  g_h1);
    cudaGetSymbolAddress((void**)&wt,  g_wt);

    cudaFuncSetAttribute(attn_tc_kernel, cudaFuncAttributeMaxDynamicSharedMemorySize, ATTN_SMEM);
    cudaFuncSetAttribute(tc_gemm_kernel<EPI_RESID, float>,  cudaFuncAttributeMaxDynamicSharedMemorySize, GEMM_SMEM_BYTES);
    cudaFuncSetAttribute(tc_gemm_kernel<EPI_GELU, __half>,  cudaFuncAttributeMaxDynamicSharedMemorySize, GEMM_SMEM_BYTES);
    cudaFuncSetAttribute(qkv_gemm_kernel,                   cudaFuncAttributeMaxDynamicSharedMemorySize, GEMM_SMEM_BYTES);

    // ---- convert + transpose weights to half [N][K] ----
    {
        dim3 tb(32, 8);
        convT_kernel<<<dim3(CC/32,  CC/32,  LNUM), tb>>>(Wq, wt + WQ_OFF, CC, CC);
        convT_kernel<<<dim3(CC/32,  CC/32,  LNUM), tb>>>(Wk, wt + WK_OFF, CC, CC);
        convT_kernel<<<dim3(CC/32,  CC/32,  LNUM), tb>>>(Wv, wt + WV_OFF, CC, CC);
        convT_kernel<<<dim3(CC/32,  CC/32,  LNUM), tb>>>(Wp, wt + WP_OFF, CC, CC);
        convT_kernel<<<dim3(HID/32, CC/32,  LNUM), tb>>>(W1, wt + W1_OFF, CC, HID);
        convT_kernel<<<dim3(CC/32,  HID/32, LNUM), tb>>>(W2, wt + W2_OFF, HID, CC);
    }

    // residual = x
    {
        int n4 = (MM * CC) / 4;
        copy4_kernel<<<(n4 + 255) / 256, 256>>>((float4*)res, (const float4*)x, n4);
    }

    dim3 gemm_qkv3(CC / 128, MM / 128, 3);   // 576
    dim3 gemm_c  (CC / 128, MM / 128);       // 192
    dim3 gemm_h  (HID / 128, MM / 128);      // 768
    dim3 attn_grid(TT / 128, BB * NH);       // 384

    for (int l = 0; l < LNUM; l++) {
        const __half* wq = wt + WQ_OFF + (size_t)l * CC * CC;
        const __half* wk = wt + WK_OFF + (size_t)l * CC * CC;
        const __half* wv = wt + WV_OFF + (size_t)l * CC * CC;
        const __half* wp = wt + WP_OFF + (size_t)l * CC * CC;
        const __half* w1 = wt + W1_OFF + (size_t)l * CC * HID;
        const __half* w2 = wt + W2_OFF + (size_t)l * HID * CC;

        ln_kernel<<<MM, 256>>>(res, ln1_g + (size_t)l*CC, ln1_b + (size_t)l*CC, ln);
        qkv_gemm_kernel<<<gemm_qkv3, 256, GEMM_SMEM_BYTES>>>(
            ln, wq, wk, wv, bq + (size_t)l*CC, bk + (size_t)l*CC, bv + (size_t)l*CC, q, k, v);
        attn_tc_kernel<<<attn_grid, 256, ATTN_SMEM>>>(q, k, v, y);
        tc_gemm_kernel<EPI_RESID, float><<<gemm_c, 256, GEMM_SMEM_BYTES>>>(
            y, wp, bp + (size_t)l*CC, res, res, CC, CC);
        ln_kernel<<<MM, 256>>>(res, ln2_g + (size_t)l*CC, ln2_b + (size_t)l*CC, ln);
        tc_gemm_kernel<EPI_GELU, __half><<<gemm_h, 256, GEMM_SMEM_BYTES>>>(
            ln, w1, b1 + (size_t)l*HID, nullptr, h1, HID, CC);
        tc_gemm_kernel<EPI_RESID, float><<<gemm_c, 256, GEMM_SMEM_BYTES>>>(
            h1, w2, b2 + (size_t)l*CC, res, res, CC, HID);
    }

    {
        int n4 = (MM * CC) / 4;
        copy4_kernel<<<(n4 + 255) / 256, 256>>>((float4*)d_out, (const float4*)res, n4);
    }
}

// round 9
// speedup vs baseline: 1.6569x; 1.0798x over previous
#include <cuda_runtime.h>
#include <cuda_fp16.h>
#include <math.h>
#include <cstdint>

// ---------------- problem constants ----------------
#define LNUM 4
#define BB   4
#define TT   1024
#define CC   768
#define NH   12
#define HD   64
#define HID  3072
#define MM   (BB*TT)          // 4096 rows
#define EPS_LN 1e-5f

// ---------------- scratch (device globals; no allocation allowed) ----------------
__device__ float  g_res[(size_t)MM*CC];
__device__ __half g_ln [(size_t)MM*CC];
__device__ __half g_q  [(size_t)MM*CC];
__device__ __half g_k  [(size_t)MM*CC];
__device__ __half g_v  [(size_t)MM*CC];
__device__ __half g_y  [(size_t)MM*CC];
__device__ __half g_h1 [(size_t)MM*HID];
// half, transposed [N][K] weights
#define WQ_OFF 0
#define WK_OFF (WQ_OFF + (size_t)LNUM*CC*CC)
#define WV_OFF (WK_OFF + (size_t)LNUM*CC*CC)
#define WP_OFF (WV_OFF + (size_t)LNUM*CC*CC)
#define W1_OFF (WP_OFF + (size_t)LNUM*CC*CC)
#define W2_OFF (W1_OFF + (size_t)LNUM*CC*HID)
#define WT_TOTAL (W2_OFF + (size_t)LNUM*CC*HID)
__device__ __half g_wt [WT_TOTAL];

// ---------------- helpers ----------------
__device__ __forceinline__ uint32_t smem_u32(const void* p) {
    uint32_t a;
    asm("{ .reg .u64 t; cvta.to.shared.u64 t, %1; cvt.u32.u64 %0, t; }" : "=r"(a) : "l"(p));
    return a;
}
__device__ __forceinline__ void cp_async16(uint32_t dst, const void* src) {
    asm volatile("cp.async.cg.shared.global [%0], [%1], 16;" :: "r"(dst), "l"(src));
}
#define CP_COMMIT() asm volatile("cp.async.commit_group;" ::: "memory")
template <int N>
__device__ __forceinline__ void cp_wait() {
    asm volatile("cp.async.wait_group %0;" :: "n"(N) : "memory");
}
__device__ __forceinline__ void mma_f16(float* d, uint32_t a0, uint32_t a1, uint32_t a2,
                                        uint32_t a3, uint32_t b0, uint32_t b1) {
    asm volatile(
        "mma.sync.aligned.m16n8k16.row.col.f32.f16.f16.f32 "
        "{%0,%1,%2,%3}, {%4,%5,%6,%7}, {%8,%9}, {%0,%1,%2,%3};"
        : "+f"(d[0]), "+f"(d[1]), "+f"(d[2]), "+f"(d[3])
        : "r"(a0), "r"(a1), "r"(a2), "r"(a3), "r"(b0), "r"(b1));
}
__device__ __forceinline__ void ldsm_x4(uint32_t addr, uint32_t* r) {
    asm volatile("ldmatrix.sync.aligned.m8n8.x4.shared.b16 {%0,%1,%2,%3}, [%4];"
        : "=r"(r[0]), "=r"(r[1]), "=r"(r[2]), "=r"(r[3]) : "r"(addr));
}

// ---------------- small kernels ----------------
__global__ void copy4_kernel(float4* __restrict__ dst, const float4* __restrict__ src, int n4) {
    int i = blockIdx.x * blockDim.x + threadIdx.x;
    if (i < n4) dst[i] = src[i];
}

// convert fp32 [K][N] weight -> half transposed [N][K]; grid.z = layer
__global__ void convT_kernel(const float* __restrict__ src, __half* __restrict__ dst,
                             int K, int N) {
    __shared__ float tile[32][33];
    const float* s = src + (size_t)blockIdx.z * K * N;
    __half* d = dst + (size_t)blockIdx.z * K * N;
    int tx = threadIdx.x, ty = threadIdx.y;
    int n0 = blockIdx.x * 32, k0 = blockIdx.y * 32;
#pragma unroll
    for (int i = 0; i < 32; i += 8)
        tile[ty + i][tx] = s[(size_t)(k0 + ty + i) * N + n0 + tx];
    __syncthreads();
#pragma unroll
    for (int i = 0; i < 32; i += 8)
        d[(size_t)(n0 + ty + i) * K + k0 + tx] = __float2half_rn(tile[tx][ty + i]);
}

// layernorm; output half (consumed only as GEMM A operand)
__global__ void ln_kernel(const float* __restrict__ x, const float* __restrict__ g,
                          const float* __restrict__ b, __half* __restrict__ out) {
    __shared__ float red0[8], red1[8];
    int row = blockIdx.x;
    int tid = threadIdx.x;
    const float* xr = x + (size_t)row * CC;
    float s = 0.f, s2 = 0.f;
    for (int i = tid; i < CC; i += 256) { float v = xr[i]; s += v; s2 += v * v; }
    for (int o = 16; o; o >>= 1) {
        s  += __shfl_xor_sync(0xffffffffu, s,  o);
        s2 += __shfl_xor_sync(0xffffffffu, s2, o);
    }
    if ((tid & 31) == 0) { red0[tid >> 5] = s; red1[tid >> 5] = s2; }
    __syncthreads();
    if (tid < 32) {
        s  = (tid < 8) ? red0[tid] : 0.f;
        s2 = (tid < 8) ? red1[tid] : 0.f;
        for (int o = 4; o; o >>= 1) {
            s  += __shfl_xor_sync(0xffffffffu, s,  o);
            s2 += __shfl_xor_sync(0xffffffffu, s2, o);
        }
        if (tid == 0) { red0[0] = s; red1[0] = s2; }
    }
    __syncthreads();
    float mu  = red0[0] * (1.f / CC);
    float var = red1[0] * (1.f / CC) - mu * mu;
    float rs  = rsqrtf(var + EPS_LN);
    __half* outr = out + (size_t)row * CC;
    for (int i = tid; i < CC; i += 256)
        outr[i] = __float2half_rn((xr[i] - mu) * rs * g[i] + b[i]);
}

// ---------------- fp16 mma.sync GEMM, cp.async 3-stage, BK=32 ----------------
#define EPI_BIAS  0
#define EPI_RESID 1
#define EPI_GELU  2

#define STAGES 3
#define BK 32
#define ASTR_H 40
#define BSTR_H 40
#define A_STG_H (128 * ASTR_H)
#define B_STG_H (128 * BSTR_H)
#define GEMM_SMEM_BYTES (STAGES * (A_STG_H + B_STG_H) * 2 + 512)

template <int EPI, typename OutT>
__device__ __forceinline__ void gemm_body(const __half* __restrict__ A, const __half* __restrict__ Wt,
                                          const float* __restrict__ bias, const float* __restrict__ resid,
                                          OutT* __restrict__ C, int Ndim, int Kdim,
                                          int bm, int bn, char* dsm) {
    __half* sA = (__half*)dsm;
    __half* sB = (__half*)dsm + STAGES * A_STG_H;
    float* sBias = (float*)(dsm + STAGES * (A_STG_H + B_STG_H) * 2);

    int tid = threadIdx.x;
    int lane = tid & 31;
    int wid = tid >> 5;

    if (tid < 128) sBias[tid] = bias[bn + tid];

    int lr = lane >> 2;
    int lc = lane & 3;
    int wm = (wid & 1) * 64;
    int wn = (wid >> 1) * 32;

    int idx0 = tid * 2, idx1 = tid * 2 + 1;
    int r0i = idx0 >> 2, s0i = (idx0 & 3) * 8;
    int r1i = idx1 >> 2, s1i = (idx1 & 3) * 8;

    uint32_t sA_base = smem_u32(sA);
    uint32_t sB_base = smem_u32(sB);
    uint32_t aFrag = sA_base + (uint32_t)((wm + (lane & 15)) * ASTR_H) * 2 + ((lane & 16) ? 16u : 0u);

    const __half* aSrc0 = A + (size_t)(bm + r0i) * Kdim + s0i;
    const __half* aSrc1 = A + (size_t)(bm + r1i) * Kdim + s1i;
    const __half* bSrc0 = Wt + (size_t)(bn + r0i) * Kdim + s0i;
    const __half* bSrc1 = Wt + (size_t)(bn + r1i) * Kdim + s1i;

    float acc[4][4][4];
#pragma unroll
    for (int i = 0; i < 4; i++)
#pragma unroll
        for (int j = 0; j < 4; j++)
#pragma unroll
            for (int r = 0; r < 4; r++) acc[i][j][r] = 0.f;

    int nch = Kdim / BK;

    auto load_stage = [&](int stg, int chunk) {
        int k0 = chunk * BK;
        uint32_t ab = sA_base + (uint32_t)(stg * A_STG_H) * 2;
        uint32_t bb = sB_base + (uint32_t)(stg * B_STG_H) * 2;
        cp_async16(ab + (uint32_t)(r0i * ASTR_H + s0i) * 2, aSrc0 + k0);
        cp_async16(ab + (uint32_t)(r1i * ASTR_H + s1i) * 2, aSrc1 + k0);
        cp_async16(bb + (uint32_t)(r0i * BSTR_H + s0i) * 2, bSrc0 + k0);
        cp_async16(bb + (uint32_t)(r1i * BSTR_H + s1i) * 2, bSrc1 + k0);
    };

#pragma unroll
    for (int s = 0; s < STAGES - 1; s++) {
        if (s < nch) load_stage(s, s);
        CP_COMMIT();
    }
    cp_wait<STAGES - 2>();
    __syncthreads();

    for (int c = 0; c < nch; c++) {
        int buf = c % STAGES;
        int nc = c + STAGES - 1;
        if (nc < nch) load_stage(nc % STAGES, nc);
        CP_COMMIT();

        uint32_t aStage = aFrag + (uint32_t)(buf * A_STG_H) * 2;
        const uint32_t* Bs = (const uint32_t*)(sB + buf * B_STG_H);

        uint32_t bfr[2][4][2];
#pragma unroll
        for (int j = 0; j < 4; j++) {
            int n0 = wn + j * 8 + lr;
            bfr[0][j][0] = Bs[n0 * 20 + lc];
            bfr[0][j][1] = Bs[n0 * 20 + 4 + lc];
        }
#pragma unroll
        for (int ks = 0; ks < 2; ks++) {
            if (ks == 0) {
#pragma unroll
                for (int j = 0; j < 4; j++) {
                    int n0 = wn + j * 8 + lr;
                    bfr[1][j][0] = Bs[n0 * 20 + 8 + lc];
                    bfr[1][j][1] = Bs[n0 * 20 + 12 + lc];
                }
            }
#pragma unroll
            for (int i = 0; i < 4; i++) {
                uint32_t a[4];
                ldsm_x4(aStage + (uint32_t)(i * 16 * ASTR_H) * 2 + ks * 32, a);
#pragma unroll
                for (int j = 0; j < 4; j++)
                    mma_f16(acc[i][j], a[0], a[1], a[2], a[3], bfr[ks][j][0], bfr[ks][j][1]);
            }
        }
        cp_wait<STAGES - 2>();
        __syncthreads();
    }

#pragma unroll
    for (int i = 0; i < 4; i++) {
        int r0 = bm + wm + i * 16 + lr;
#pragma unroll
        for (int j = 0; j < 4; j++) {
            int colL = wn + j * 8 + lc * 2;
            int col = bn + colL;
            float v0 = acc[i][j][0] + sBias[colL];
            float v1 = acc[i][j][1] + sBias[colL + 1];
            float v2 = acc[i][j][2] + sBias[colL];
            float v3 = acc[i][j][3] + sBias[colL + 1];
            if (EPI == EPI_RESID) {
                float2 ra = *(const float2*)(resid + (size_t)r0 * Ndim + col);
                float2 rb = *(const float2*)(resid + (size_t)(r0 + 8) * Ndim + col);
                v0 += ra.x; v1 += ra.y; v2 += rb.x; v3 += rb.y;
            }
            if (EPI == EPI_GELU) {
                v0 = v0 * 0.5f * (1.0f + erff(v0 * 0.70710678118654752f));
                v1 = v1 * 0.5f * (1.0f + erff(v1 * 0.70710678118654752f));
                v2 = v2 * 0.5f * (1.0f + erff(v2 * 0.70710678118654752f));
                v3 = v3 * 0.5f * (1.0f + erff(v3 * 0.70710678118654752f));
            }
            if (sizeof(OutT) == 4) {
                *(float2*)((float*)C + (size_t)r0 * Ndim + col)       = make_float2(v0, v1);
                *(float2*)((float*)C + (size_t)(r0 + 8) * Ndim + col) = make_float2(v2, v3);
            } else {
                *(__half2*)((__half*)C + (size_t)r0 * Ndim + col)       = __floats2half2_rn(v0, v1);
                *(__half2*)((__half*)C + (size_t)(r0 + 8) * Ndim + col) = __floats2half2_rn(v2, v3);
            }
        }
    }
}

template <int EPI, typename OutT>
__global__ __launch_bounds__(256, 2)
void tc_gemm_kernel(const __half* __restrict__ A, const __half* __restrict__ Wt,
                    const float* __restrict__ bias, const float* __restrict__ resid,
                    OutT* __restrict__ C, int Ndim, int Kdim) {
    extern __shared__ char dsm[];
    gemm_body<EPI, OutT>(A, Wt, bias, resid, C, Ndim, Kdim, blockIdx.y * 128, blockIdx.x * 128, dsm);
}

__global__ __launch_bounds__(256, 2)
void qkv_gemm_kernel(const __half* __restrict__ A,
                     const __half* __restrict__ W0, const __half* __restrict__ W1, const __half* __restrict__ W2,
                     const float* __restrict__ b0, const float* __restrict__ b1, const float* __restrict__ b2,
                     __half* __restrict__ C0, __half* __restrict__ C1, __half* __restrict__ C2) {
    extern __shared__ char dsm[];
    const __half* W = (blockIdx.z == 0) ? W0 : (blockIdx.z == 1) ? W1 : W2;
    const float* bi = (blockIdx.z == 0) ? b0 : (blockIdx.z == 1) ? b1 : b2;
    __half* C = (blockIdx.z == 0) ? C0 : (blockIdx.z == 1) ? C1 : C2;
    gemm_body<EPI_BIAS, __half>(A, W, bi, nullptr, C, CC, CC, blockIdx.y * 128, blockIdx.x * 128, dsm);
}

// ---------------- fp16 tensor-core flash attention ----------------
// 128 q-rows/block, 8 warps (16 rows each); S=QK^T and O+=PV via m16n8k16.
#define QSTR_H 72
#define KSTR_H 72
#define VTSTR_H 72
#define PSTR_H 72
#define ATT_Q_OFFH 0
#define ATT_K_OFFH (128 * QSTR_H)                    // 9216
#define ATT_VT_OFFH (ATT_K_OFFH + 64 * KSTR_H)       // 13824
#define ATT_P_OFFH (ATT_VT_OFFH + 64 * VTSTR_H)      // 18432
#define ATT_HALVES (ATT_P_OFFH + 128 * PSTR_H)       // 27648
#define ATTN_SMEM (ATT_HALVES * 2 + 256 * 4)         // 56320 B

__global__ __launch_bounds__(256, 2)
void attn_tc_kernel(const __half* __restrict__ Q, const __half* __restrict__ K,
                    const __half* __restrict__ V, __half* __restrict__ Y) {
    extern __shared__ __half smh[];
    __half* Qs  = smh + ATT_Q_OFFH;
    __half* Ks  = smh + ATT_K_OFFH;
    __half* VTs = smh + ATT_VT_OFFH;
    __half* Ps  = smh + ATT_P_OFFH;
    float* mS = (float*)(smh + ATT_HALVES);
    float* lS = mS + 128;

    int tid = threadIdx.x;
    int lane = tid & 31;
    int wid = tid >> 5;
    int lr = lane >> 2;
    int lc = lane & 3;
    int wr = wid * 16;

    int qb = blockIdx.x * 128;
    int bh = blockIdx.y;
    int b = bh / NH, h = bh % NH;
    size_t base = (size_t)b * TT * CC + (size_t)h * HD;

    uint32_t qFrag = smem_u32(Qs) + (uint32_t)((wr + (lane & 15)) * QSTR_H) * 2 + ((lane & 16) ? 16u : 0u);
    uint32_t pFrag = smem_u32(Ps) + (uint32_t)((wr + (lane & 15)) * PSTR_H) * 2 + ((lane & 16) ? 16u : 0u);

    // load Q tile, prescale by 1/8 (exact power of two)
    {
        const __half2 sc = __float2half2_rn(0.125f);
        for (int i = tid; i < 128 * 8; i += 256) {
            int row = i >> 3, cg = (i & 7) * 8;
            uint4 u = *(const uint4*)(Q + base + (size_t)(qb + row) * CC + cg);
            __half2* hp = (__half2*)&u;
            hp[0] = __hmul2(hp[0], sc); hp[1] = __hmul2(hp[1], sc);
            hp[2] = __hmul2(hp[2], sc); hp[3] = __hmul2(hp[3], sc);
            *(uint4*)(Qs + row * QSTR_H + cg) = u;
        }
    }
    if (tid < 128) { mS[tid] = -1e30f; lS[tid] = 0.f; }

    float o[8][4];
#pragma unroll
    for (int j = 0; j < 8; j++)
#pragma unroll
        for (int r = 0; r < 4; r++) o[j][r] = 0.f;

    int qmod = qb & 255;
    int rm0 = qmod + wr + lr;
    int rm1 = rm0 + 8;

    for (int kb = 0; kb < TT; kb += 64) {
        int kbm = kb & 255;
        if (kbm > qmod + 127) continue;
        __syncthreads();
        // K tile [64][64] half, straight copy
        for (int i = tid; i < 64 * 8; i += 256) {
            int row = i >> 3, cg = (i & 7) * 8;
            *(uint4*)(Ks + row * KSTR_H + cg) = *(const uint4*)(K + base + (size_t)(kb + row) * CC + cg);
        }
        // V tile transposed: VT[hd][kpos]
        {
            int row = tid & 63;            // kpos
            int cgrp = tid >> 6;           // 0..3, 16 hd cols each
            uint4 v0 = *(const uint4*)(V + base + (size_t)(kb + row) * CC + cgrp * 16);
            uint4 v1 = *(const uint4*)(V + base + (size_t)(kb + row) * CC + cgrp * 16 + 8);
            const __half* h0 = (const __half*)&v0;
            const __half* h1 = (const __half*)&v1;
#pragma unroll
            for (int j = 0; j < 8; j++) {
                VTs[(cgrp * 16 + j) * VTSTR_H + row] = h0[j];
                VTs[(cgrp * 16 + 8 + j) * VTSTR_H + row] = h1[j];
            }
        }
        __syncthreads();

        // ---- S = Q K^T ----
        float sacc[8][4];
#pragma unroll
        for (int j = 0; j < 8; j++)
#pragma unroll
            for (int r = 0; r < 4; r++) sacc[j][r] = 0.f;
#pragma unroll
        for (int ks = 0; ks < 4; ks++) {
            uint32_t a[4];
            ldsm_x4(qFrag + ks * 32, a);
#pragma unroll
            for (int j = 0; j < 8; j++) {
                int n0 = j * 8 + lr;
                uint32_t b0 = *(const uint32_t*)(Ks + n0 * KSTR_H + ks * 16 + 2 * lc);
                uint32_t b1 = *(const uint32_t*)(Ks + n0 * KSTR_H + ks * 16 + 8 + 2 * lc);
                mma_f16(sacc[j], a[0], a[1], a[2], a[3], b0, b1);
            }
        }

        // ---- mask + online softmax ----
        float m0 = -1e30f, m1 = -1e30f;
#pragma unroll
        for (int j = 0; j < 8; j++) {
            int c0 = kbm + j * 8 + 2 * lc;
            if (c0 > rm0)     sacc[j][0] = -1e30f;
            if (c0 + 1 > rm0) sacc[j][1] = -1e30f;
            if (c0 > rm1)     sacc[j][2] = -1e30f;
            if (c0 + 1 > rm1) sacc[j][3] = -1e30f;
            m0 = fmaxf(m0, fmaxf(sacc[j][0], sacc[j][1]));
            m1 = fmaxf(m1, fmaxf(sacc[j][2], sacc[j][3]));
        }
        m0 = fmaxf(m0, __shfl_xor_sync(0xffffffffu, m0, 1));
        m0 = fmaxf(m0, __shfl_xor_sync(0xffffffffu, m0, 2));
        m1 = fmaxf(m1, __shfl_xor_sync(0xffffffffu, m1, 1));
        m1 = fmaxf(m1, __shfl_xor_sync(0xffffffffu, m1, 2));

        int r0 = wr + lr, r1 = r0 + 8;
        float mo0 = mS[r0], mo1 = mS[r1];
        float mn0 = fmaxf(mo0, m0), mn1 = fmaxf(mo1, m1);
        float al0 = __expf(mo0 - mn0), al1 = __expf(mo1 - mn1);

        float sum0 = 0.f, sum1 = 0.f;
#pragma unroll
        for (int j = 0; j < 8; j++) {
            float p00 = __expf(sacc[j][0] - mn0);
            float p01 = __expf(sacc[j][1] - mn0);
            float p10 = __expf(sacc[j][2] - mn1);
            float p11 = __expf(sacc[j][3] - mn1);
            sum0 += p00 + p01;
            sum1 += p10 + p11;
            *(__half2*)(Ps + r0 * PSTR_H + j * 8 + 2 * lc) = __floats2half2_rn(p00, p01);
            *(__half2*)(Ps + r1 * PSTR_H + j * 8 + 2 * lc) = __floats2half2_rn(p10, p11);
            o[j][0] *= al0; o[j][1] *= al0; o[j][2] *= al1; o[j][3] *= al1;
        }
        sum0 += __shfl_xor_sync(0xffffffffu, sum0, 1);
        sum0 += __shfl_xor_sync(0xffffffffu, sum0, 2);
        sum1 += __shfl_xor_sync(0xffffffffu, sum1, 1);
        sum1 += __shfl_xor_sync(0xffffffffu, sum1, 2);
        if (lc == 0) {
            lS[r0] = lS[r0] * al0 + sum0;
            lS[r1] = lS[r1] * al1 + sum1;
            mS[r0] = mn0;
            mS[r1] = mn1;
        }
        __syncwarp();

        // ---- O += P V ----
#pragma unroll
        for (int ks = 0; ks < 4; ks++) {
            uint32_t a[4];
            ldsm_x4(pFrag + ks * 32, a);
#pragma unroll
            for (int j = 0; j < 8; j++) {
                int n0 = j * 8 + lr;
                uint32_t b0 = *(const uint32_t*)(VTs + n0 * VTSTR_H + ks * 16 + 2 * lc);
                uint32_t b1 = *(const uint32_t*)(VTs + n0 * VTSTR_H + ks * 16 + 8 + 2 * lc);
                mma_f16(o[j], a[0], a[1], a[2], a[3], b0, b1);
            }
        }
    }

    __syncwarp();
    int r0 = wr + lr, r1 = r0 + 8;
    float inv0 = 1.0f / lS[r0];
    float inv1 = 1.0f / lS[r1];
#pragma unroll
    for (int j = 0; j < 8; j++) {
        int d = j * 8 + 2 * lc;
        *(__half2*)(Y + base + (size_t)(qb + r0) * CC + d) =
            __floats2half2_rn(o[j][0] * inv0, o[j][1] * inv0);
        *(__half2*)(Y + base + (size_t)(qb + r1) * CC + d) =
            __floats2half2_rn(o[j][2] * inv1, o[j][3] * inv1);
    }
}

// ---------------- host orchestration ----------------
extern "C" void kernel_launch(void* const* d_in, const int* in_sizes, int n_in,
                              void* d_out, int out_size) {
    const float* x     = (const float*)d_in[0];
    const float* ln1_g = (const float*)d_in[1];
    const float* ln1_b = (const float*)d_in[2];
    const float* Wq    = (const float*)d_in[3];
    const float* bq    = (const float*)d_in[4];
    const float* Wk    = (const float*)d_in[5];
    const float* bk    = (const float*)d_in[6];
    const float* Wv    = (const float*)d_in[7];
    const float* bv    = (const float*)d_in[8];
    const float* Wp    = (const float*)d_in[9];
    const float* bp    = (const float*)d_in[10];
    const float* ln2_g = (const float*)d_in[11];
    const float* ln2_b = (const float*)d_in[12];
    const float* W1    = (const float*)d_in[13];
    const float* b1    = (const float*)d_in[14];
    const float* W2    = (const float*)d_in[15];
    const float* b2    = (const float*)d_in[16];

    float* res;
    __half *ln, *q, *k, *v, *y, *h1, *wt;
    cudaGetSymbolAddress((void**)&res, g_res);
    cudaGetSymbolAddress((void**)&ln,  g_ln);
    cudaGetSymbolAddress((void**)&q,   g_q);
    cudaGetSymbolAddress((void**)&k,   g_k);
    cudaGetSymbolAddress((void**)&v,   g_v);
    cudaGetSymbolAddress((void**)&y,   g_y);
    cudaGetSymbolAddress((void**)&h1,  g_h1);
    cudaGetSymbolAddress((void**)&wt,  g_wt);

    cudaFuncSetAttribute(attn_tc_kernel, cudaFuncAttributeMaxDynamicSharedMemorySize, ATTN_SMEM);
    cudaFuncSetAttribute(tc_gemm_kernel<EPI_RESID, float>,  cudaFuncAttributeMaxDynamicSharedMemorySize, GEMM_SMEM_BYTES);
    cudaFuncSetAttribute(tc_gemm_kernel<EPI_GELU, __half>,  cudaFuncAttributeMaxDynamicSharedMemorySize, GEMM_SMEM_BYTES);
    cudaFuncSetAttribute(qkv_gemm_kernel,                   cudaFuncAttributeMaxDynamicSharedMemorySize, GEMM_SMEM_BYTES);

    // ---- convert + transpose weights to half [N][K] ----
    {
        dim3 tb(32, 8);
        convT_kernel<<<dim3(CC/32,  CC/32,  LNUM), tb>>>(Wq, wt + WQ_OFF, CC, CC);
        convT_kernel<<<dim3(CC/32,  CC/32,  LNUM), tb>>>(Wk, wt + WK_OFF, CC, CC);
        convT_kernel<<<dim3(CC/32,  CC/32,  LNUM), tb>>>(Wv, wt + WV_OFF, CC, CC);
        convT_kernel<<<dim3(CC/32,  CC/32,  LNUM), tb>>>(Wp, wt + WP_OFF, CC, CC);
        convT_kernel<<<dim3(HID/32, CC/32,  LNUM), tb>>>(W1, wt + W1_OFF, CC, HID);
        convT_kernel<<<dim3(CC/32,  HID/32, LNUM), tb>>>(W2, wt + W2_OFF, HID, CC);
    }

    // residual = x
    {
        int n4 = (MM * CC) / 4;
        copy4_kernel<<<(n4 + 255) / 256, 256>>>((float4*)res, (const float4*)x, n4);
    }

    dim3 gemm_qkv3(CC / 128, MM / 128, 3);   // 576
    dim3 gemm_c  (CC / 128, MM / 128);       // 192
    dim3 gemm_h  (HID / 128, MM / 128);      // 768
    dim3 attn_grid(TT / 128, BB * NH);       // 384

    for (int l = 0; l < LNUM; l++) {
        const __half* wq = wt + WQ_OFF + (size_t)l * CC * CC;
        const __half* wk = wt + WK_OFF + (size_t)l * CC * CC;
        const __half* wv = wt + WV_OFF + (size_t)l * CC * CC;
        const __half* wp = wt + WP_OFF + (size_t)l * CC * CC;
        const __half* w1 = wt + W1_OFF + (size_t)l * CC * HID;
        const __half* w2 = wt + W2_OFF + (size_t)l * HID * CC;

        ln_kernel<<<MM, 256>>>(res, ln1_g + (size_t)l*CC, ln1_b + (size_t)l*CC, ln);
        qkv_gemm_kernel<<<gemm_qkv3, 256, GEMM_SMEM_BYTES>>>(
            ln, wq, wk, wv, bq + (size_t)l*CC, bk + (size_t)l*CC, bv + (size_t)l*CC, q, k, v);
        attn_tc_kernel<<<attn_grid, 256, ATTN_SMEM>>>(q, k, v, y);
        tc_gemm_kernel<EPI_RESID, float><<<gemm_c, 256, GEMM_SMEM_BYTES>>>(
            y, wp, bp + (size_t)l*CC, res, res, CC, CC);
        ln_kernel<<<MM, 256>>>(res, ln2_g + (size_t)l*CC, ln2_b + (size_t)l*CC, ln);
        tc_gemm_kernel<EPI_GELU, __half><<<gemm_h, 256, GEMM_SMEM_BYTES>>>(
            ln, w1, b1 + (size_t)l*HID, nullptr, h1, HID, CC);
        // last layer's W2-residual GEMM writes the final output directly
        float* outC = (l == LNUM - 1) ? (float*)d_out : res;
        tc_gemm_kernel<EPI_RESID, float><<<gemm_c, 256, GEMM_SMEM_BYTES>>>(
            h1, w2, b2 + (size_t)l*CC, res, outC, CC, HID);
    }
}

// round 10
// speedup vs baseline: 1.7626x; 1.0638x over previous
#include <cuda_runtime.h>
#include <cuda_fp16.h>
#include <math.h>
#include <cstdint>

// ---------------- problem constants ----------------
#define LNUM 4
#define BB   4
#define TT   1024
#define CC   768
#define NH   12
#define HD   64
#define HID  3072
#define MM   (BB*TT)          // 4096 rows
#define EPS_LN 1e-5f

// ---------------- scratch (device globals; no allocation allowed) ----------------
__device__ float  g_res[(size_t)MM*CC];
__device__ __half g_ln [(size_t)MM*CC];
__device__ __half g_q  [(size_t)MM*CC];
__device__ __half g_k  [(size_t)MM*CC];
__device__ __half g_v  [(size_t)MM*CC];
__device__ __half g_y  [(size_t)MM*CC];
__device__ __half g_h1 [(size_t)MM*HID];
// half, transposed [N][K] weights
#define WQ_OFF 0
#define WK_OFF (WQ_OFF + (size_t)LNUM*CC*CC)
#define WV_OFF (WK_OFF + (size_t)LNUM*CC*CC)
#define WP_OFF (WV_OFF + (size_t)LNUM*CC*CC)
#define W1_OFF (WP_OFF + (size_t)LNUM*CC*CC)
#define W2_OFF (W1_OFF + (size_t)LNUM*CC*HID)
#define WT_TOTAL (W2_OFF + (size_t)LNUM*CC*HID)
__device__ __half g_wt [WT_TOTAL];

// ---------------- helpers ----------------
__device__ __forceinline__ uint32_t smem_u32(const void* p) {
    uint32_t a;
    asm("{ .reg .u64 t; cvta.to.shared.u64 t, %1; cvt.u32.u64 %0, t; }" : "=r"(a) : "l"(p));
    return a;
}
__device__ __forceinline__ void cp_async16(uint32_t dst, const void* src) {
    asm volatile("cp.async.cg.shared.global [%0], [%1], 16;" :: "r"(dst), "l"(src));
}
#define CP_COMMIT() asm volatile("cp.async.commit_group;" ::: "memory")
template <int N>
__device__ __forceinline__ void cp_wait() {
    asm volatile("cp.async.wait_group %0;" :: "n"(N) : "memory");
}
__device__ __forceinline__ void mma_f16(float* d, uint32_t a0, uint32_t a1, uint32_t a2,
                                        uint32_t a3, uint32_t b0, uint32_t b1) {
    asm volatile(
        "mma.sync.aligned.m16n8k16.row.col.f32.f16.f16.f32 "
        "{%0,%1,%2,%3}, {%4,%5,%6,%7}, {%8,%9}, {%0,%1,%2,%3};"
        : "+f"(d[0]), "+f"(d[1]), "+f"(d[2]), "+f"(d[3])
        : "r"(a0), "r"(a1), "r"(a2), "r"(a3), "r"(b0), "r"(b1));
}
__device__ __forceinline__ void ldsm_x4(uint32_t addr, uint32_t* r) {
    asm volatile("ldmatrix.sync.aligned.m8n8.x4.shared.b16 {%0,%1,%2,%3}, [%4];"
        : "=r"(r[0]), "=r"(r[1]), "=r"(r[2]), "=r"(r[3]) : "r"(addr));
}

// ---------------- small kernels ----------------
__global__ void copy4_kernel(float4* __restrict__ dst, const float4* __restrict__ src, int n4) {
    int i = blockIdx.x * blockDim.x + threadIdx.x;
    if (i < n4) dst[i] = src[i];
}

// convert fp32 [K][N] weight -> half transposed [N][K]; grid.z = layer
__global__ void convT_kernel(const float* __restrict__ src, __half* __restrict__ dst,
                             int K, int N) {
    __shared__ float tile[32][33];
    const float* s = src + (size_t)blockIdx.z * K * N;
    __half* d = dst + (size_t)blockIdx.z * K * N;
    int tx = threadIdx.x, ty = threadIdx.y;
    int n0 = blockIdx.x * 32, k0 = blockIdx.y * 32;
#pragma unroll
    for (int i = 0; i < 32; i += 8)
        tile[ty + i][tx] = s[(size_t)(k0 + ty + i) * N + n0 + tx];
    __syncthreads();
#pragma unroll
    for (int i = 0; i < 32; i += 8)
        d[(size_t)(n0 + ty + i) * K + k0 + tx] = __float2half_rn(tile[tx][ty + i]);
}

// layernorm; output half (consumed only as GEMM A operand)
__global__ void ln_kernel(const float* __restrict__ x, const float* __restrict__ g,
                          const float* __restrict__ b, __half* __restrict__ out) {
    __shared__ float red0[8], red1[8];
    int row = blockIdx.x;
    int tid = threadIdx.x;
    const float* xr = x + (size_t)row * CC;
    float s = 0.f, s2 = 0.f;
    for (int i = tid; i < CC; i += 256) { float v = xr[i]; s += v; s2 += v * v; }
    for (int o = 16; o; o >>= 1) {
        s  += __shfl_xor_sync(0xffffffffu, s,  o);
        s2 += __shfl_xor_sync(0xffffffffu, s2, o);
    }
    if ((tid & 31) == 0) { red0[tid >> 5] = s; red1[tid >> 5] = s2; }
    __syncthreads();
    if (tid < 32) {
        s  = (tid < 8) ? red0[tid] : 0.f;
        s2 = (tid < 8) ? red1[tid] : 0.f;
        for (int o = 4; o; o >>= 1) {
            s  += __shfl_xor_sync(0xffffffffu, s,  o);
            s2 += __shfl_xor_sync(0xffffffffu, s2, o);
        }
        if (tid == 0) { red0[0] = s; red1[0] = s2; }
    }
    __syncthreads();
    float mu  = red0[0] * (1.f / CC);
    float var = red1[0] * (1.f / CC) - mu * mu;
    float rs  = rsqrtf(var + EPS_LN);
    __half* outr = out + (size_t)row * CC;
    for (int i = tid; i < CC; i += 256)
        outr[i] = __float2half_rn((xr[i] - mu) * rs * g[i] + b[i]);
}

// ---------------- fp16 mma.sync GEMM, cp.async 4-stage, BK=32, ldsm A+B ----------------
#define EPI_BIAS  0
#define EPI_RESID 1
#define EPI_GELU  2

#define STAGES 4
#define BK 32
#define ASTR_H 40
#define BSTR_H 40
#define A_STG_H (128 * ASTR_H)
#define B_STG_H (128 * BSTR_H)
#define GEMM_SMEM_BYTES (STAGES * (A_STG_H + B_STG_H) * 2 + 512)   // 82,432 B

template <int EPI, typename OutT>
__device__ __forceinline__ void gemm_body(const __half* __restrict__ A, const __half* __restrict__ Wt,
                                          const float* __restrict__ bias, const float* __restrict__ resid,
                                          OutT* __restrict__ C, int Ndim, int Kdim,
                                          int bm, int bn, char* dsm) {
    __half* sA = (__half*)dsm;
    __half* sB = (__half*)dsm + STAGES * A_STG_H;
    float* sBias = (float*)(dsm + STAGES * (A_STG_H + B_STG_H) * 2);

    int tid = threadIdx.x;
    int lane = tid & 31;
    int wid = tid >> 5;

    if (tid < 128) sBias[tid] = bias[bn + tid];

    int lr = lane >> 2;
    int lc = lane & 3;
    int wm = (wid & 1) * 64;
    int wn = (wid >> 1) * 32;

    int idx0 = tid * 2, idx1 = tid * 2 + 1;
    int r0i = idx0 >> 2, s0i = (idx0 & 3) * 8;
    int r1i = idx1 >> 2, s1i = (idx1 & 3) * 8;

    uint32_t sA_base = smem_u32(sA);
    uint32_t sB_base = smem_u32(sB);
    // A ldsm frag base: row = wm + (lane&15), k-half via lane&16
    uint32_t aFrag = sA_base + (uint32_t)((wm + (lane & 15)) * ASTR_H) * 2 + ((lane & 16) ? 16u : 0u);
    // B ldsm frag base: row = wn + j*8 + (lane&7), matrix (lane>>3) selects 16B k-chunk
    uint32_t bFrag = sB_base + (uint32_t)((wn + (lane & 7)) * BSTR_H) * 2 + (uint32_t)(lane >> 3) * 16u;

    const __half* aSrc0 = A + (size_t)(bm + r0i) * Kdim + s0i;
    const __half* aSrc1 = A + (size_t)(bm + r1i) * Kdim + s1i;
    const __half* bSrc0 = Wt + (size_t)(bn + r0i) * Kdim + s0i;
    const __half* bSrc1 = Wt + (size_t)(bn + r1i) * Kdim + s1i;

    float acc[4][4][4];
#pragma unroll
    for (int i = 0; i < 4; i++)
#pragma unroll
        for (int j = 0; j < 4; j++)
#pragma unroll
            for (int r = 0; r < 4; r++) acc[i][j][r] = 0.f;

    int nch = Kdim / BK;

    auto load_stage = [&](int stg, int chunk) {
        int k0 = chunk * BK;
        uint32_t ab = sA_base + (uint32_t)(stg * A_STG_H) * 2;
        uint32_t bb = sB_base + (uint32_t)(stg * B_STG_H) * 2;
        cp_async16(ab + (uint32_t)(r0i * ASTR_H + s0i) * 2, aSrc0 + k0);
        cp_async16(ab + (uint32_t)(r1i * ASTR_H + s1i) * 2, aSrc1 + k0);
        cp_async16(bb + (uint32_t)(r0i * BSTR_H + s0i) * 2, bSrc0 + k0);
        cp_async16(bb + (uint32_t)(r1i * BSTR_H + s1i) * 2, bSrc1 + k0);
    };

#pragma unroll
    for (int s = 0; s < STAGES - 1; s++) {
        if (s < nch) load_stage(s, s);
        CP_COMMIT();
    }
    cp_wait<STAGES - 2>();
    __syncthreads();

    for (int c = 0; c < nch; c++) {
        int buf = c % STAGES;
        int nc = c + STAGES - 1;
        if (nc < nch) load_stage(nc % STAGES, nc);
        CP_COMMIT();

        uint32_t aStage = aFrag + (uint32_t)(buf * A_STG_H) * 2;
        uint32_t bStage = bFrag + (uint32_t)(buf * B_STG_H) * 2;

        // B frags: one ldsm.x4 per n-block covers both k16 steps
        uint32_t bfr[4][4];
#pragma unroll
        for (int j = 0; j < 4; j++)
            ldsm_x4(bStage + (uint32_t)(j * 8 * BSTR_H) * 2, bfr[j]);

#pragma unroll
        for (int ks = 0; ks < 2; ks++) {
#pragma unroll
            for (int i = 0; i < 4; i++) {
                uint32_t a[4];
                ldsm_x4(aStage + (uint32_t)(i * 16 * ASTR_H) * 2 + ks * 32, a);
#pragma unroll
                for (int j = 0; j < 4; j++)
                    mma_f16(acc[i][j], a[0], a[1], a[2], a[3], bfr[j][2 * ks], bfr[j][2 * ks + 1]);
            }
        }
        cp_wait<STAGES - 2>();
        __syncthreads();
    }

#pragma unroll
    for (int i = 0; i < 4; i++) {
        int r0 = bm + wm + i * 16 + lr;
#pragma unroll
        for (int j = 0; j < 4; j++) {
            int colL = wn + j * 8 + lc * 2;
            int col = bn + colL;
            float v0 = acc[i][j][0] + sBias[colL];
            float v1 = acc[i][j][1] + sBias[colL + 1];
            float v2 = acc[i][j][2] + sBias[colL];
            float v3 = acc[i][j][3] + sBias[colL + 1];
            if (EPI == EPI_RESID) {
                float2 ra = *(const float2*)(resid + (size_t)r0 * Ndim + col);
                float2 rb = *(const float2*)(resid + (size_t)(r0 + 8) * Ndim + col);
                v0 += ra.x; v1 += ra.y; v2 += rb.x; v3 += rb.y;
            }
            if (EPI == EPI_GELU) {
                v0 = v0 * 0.5f * (1.0f + erff(v0 * 0.70710678118654752f));
                v1 = v1 * 0.5f * (1.0f + erff(v1 * 0.70710678118654752f));
                v2 = v2 * 0.5f * (1.0f + erff(v2 * 0.70710678118654752f));
                v3 = v3 * 0.5f * (1.0f + erff(v3 * 0.70710678118654752f));
            }
            if (sizeof(OutT) == 4) {
                *(float2*)((float*)C + (size_t)r0 * Ndim + col)       = make_float2(v0, v1);
                *(float2*)((float*)C + (size_t)(r0 + 8) * Ndim + col) = make_float2(v2, v3);
            } else {
                *(__half2*)((__half*)C + (size_t)r0 * Ndim + col)       = __floats2half2_rn(v0, v1);
                *(__half2*)((__half*)C + (size_t)(r0 + 8) * Ndim + col) = __floats2half2_rn(v2, v3);
            }
        }
    }
}

template <int EPI, typename OutT>
__global__ __launch_bounds__(256, 2)
void tc_gemm_kernel(const __half* __restrict__ A, const __half* __restrict__ Wt,
                    const float* __restrict__ bias, const float* __restrict__ resid,
                    OutT* __restrict__ C, int Ndim, int Kdim) {
    extern __shared__ char dsm[];
    gemm_body<EPI, OutT>(A, Wt, bias, resid, C, Ndim, Kdim, blockIdx.y * 128, blockIdx.x * 128, dsm);
}

__global__ __launch_bounds__(256, 2)
void qkv_gemm_kernel(const __half* __restrict__ A,
                     const __half* __restrict__ W0, const __half* __restrict__ W1, const __half* __restrict__ W2,
                     const float* __restrict__ b0, const float* __restrict__ b1, const float* __restrict__ b2,
                     __half* __restrict__ C0, __half* __restrict__ C1, __half* __restrict__ C2) {
    extern __shared__ char dsm[];
    const __half* W = (blockIdx.z == 0) ? W0 : (blockIdx.z == 1) ? W1 : W2;
    const float* bi = (blockIdx.z == 0) ? b0 : (blockIdx.z == 1) ? b1 : b2;
    __half* C = (blockIdx.z == 0) ? C0 : (blockIdx.z == 1) ? C1 : C2;
    gemm_body<EPI_BIAS, __half>(A, W, bi, nullptr, C, CC, CC, blockIdx.y * 128, blockIdx.x * 128, dsm);
}

// ---------------- fp16 tensor-core flash attention ----------------
#define QSTR_H 72
#define KSTR_H 72
#define VTSTR_H 72
#define PSTR_H 72
#define ATT_Q_OFFH 0
#define ATT_K_OFFH (128 * QSTR_H)
#define ATT_VT_OFFH (ATT_K_OFFH + 64 * KSTR_H)
#define ATT_P_OFFH (ATT_VT_OFFH + 64 * VTSTR_H)
#define ATT_HALVES (ATT_P_OFFH + 128 * PSTR_H)
#define ATTN_SMEM (ATT_HALVES * 2 + 256 * 4)

__global__ __launch_bounds__(256, 2)
void attn_tc_kernel(const __half* __restrict__ Q, const __half* __restrict__ K,
                    const __half* __restrict__ V, __half* __restrict__ Y) {
    extern __shared__ __half smh[];
    __half* Qs  = smh + ATT_Q_OFFH;
    __half* Ks  = smh + ATT_K_OFFH;
    __half* VTs = smh + ATT_VT_OFFH;
    __half* Ps  = smh + ATT_P_OFFH;
    float* mS = (float*)(smh + ATT_HALVES);
    float* lS = mS + 128;

    int tid = threadIdx.x;
    int lane = tid & 31;
    int wid = tid >> 5;
    int lr = lane >> 2;
    int lc = lane & 3;
    int wr = wid * 16;

    // heavy-tile-first scheduling: blocks with qmod=128 (16 k-tiles) launch first
    int bx = blockIdx.x;
    int qb = (bx < 4) ? ((bx * 2 + 1) * 128) : ((bx - 4) * 2 * 128);
    int bh = blockIdx.y;
    int b = bh / NH, h = bh % NH;
    size_t base = (size_t)b * TT * CC + (size_t)h * HD;

    uint32_t qFrag = smem_u32(Qs) + (uint32_t)((wr + (lane & 15)) * QSTR_H) * 2 + ((lane & 16) ? 16u : 0u);
    uint32_t pFrag = smem_u32(Ps) + (uint32_t)((wr + (lane & 15)) * PSTR_H) * 2 + ((lane & 16) ? 16u : 0u);

    {
        const __half2 sc = __float2half2_rn(0.125f);
        for (int i = tid; i < 128 * 8; i += 256) {
            int row = i >> 3, cg = (i & 7) * 8;
            uint4 u = *(const uint4*)(Q + base + (size_t)(qb + row) * CC + cg);
            __half2* hp = (__half2*)&u;
            hp[0] = __hmul2(hp[0], sc); hp[1] = __hmul2(hp[1], sc);
            hp[2] = __hmul2(hp[2], sc); hp[3] = __hmul2(hp[3], sc);
            *(uint4*)(Qs + row * QSTR_H + cg) = u;
        }
    }
    if (tid < 128) { mS[tid] = -1e30f; lS[tid] = 0.f; }

    float o[8][4];
#pragma unroll
    for (int j = 0; j < 8; j++)
#pragma unroll
        for (int r = 0; r < 4; r++) o[j][r] = 0.f;

    int qmod = qb & 255;
    int rm0 = qmod + wr + lr;
    int rm1 = rm0 + 8;

    for (int kb = 0; kb < TT; kb += 64) {
        int kbm = kb & 255;
        if (kbm > qmod + 127) continue;
        __syncthreads();
        for (int i = tid; i < 64 * 8; i += 256) {
            int row = i >> 3, cg = (i & 7) * 8;
            *(uint4*)(Ks + row * KSTR_H + cg) = *(const uint4*)(K + base + (size_t)(kb + row) * CC + cg);
        }
        {
            int row = tid & 63;
            int cgrp = tid >> 6;
            uint4 v0 = *(const uint4*)(V + base + (size_t)(kb + row) * CC + cgrp * 16);
            uint4 v1 = *(const uint4*)(V + base + (size_t)(kb + row) * CC + cgrp * 16 + 8);
            const __half* h0 = (const __half*)&v0;
            const __half* h1 = (const __half*)&v1;
#pragma unroll
            for (int j = 0; j < 8; j++) {
                VTs[(cgrp * 16 + j) * VTSTR_H + row] = h0[j];
                VTs[(cgrp * 16 + 8 + j) * VTSTR_H + row] = h1[j];
            }
        }
        __syncthreads();

        // ---- S = Q K^T ----
        float sacc[8][4];
#pragma unroll
        for (int j = 0; j < 8; j++)
#pragma unroll
            for (int r = 0; r < 4; r++) sacc[j][r] = 0.f;
#pragma unroll
        for (int ks = 0; ks < 4; ks++) {
            uint32_t a[4];
            ldsm_x4(qFrag + ks * 32, a);
#pragma unroll
            for (int j = 0; j < 8; j++) {
                int n0 = j * 8 + lr;
                uint32_t b0 = *(const uint32_t*)(Ks + n0 * KSTR_H + ks * 16 + 2 * lc);
                uint32_t b1 = *(const uint32_t*)(Ks + n0 * KSTR_H + ks * 16 + 8 + 2 * lc);
                mma_f16(sacc[j], a[0], a[1], a[2], a[3], b0, b1);
            }
        }

        // ---- mask + online softmax ----
        float m0 = -1e30f, m1 = -1e30f;
#pragma unroll
        for (int j = 0; j < 8; j++) {
            int c0 = kbm + j * 8 + 2 * lc;
            if (c0 > rm0)     sacc[j][0] = -1e30f;
            if (c0 + 1 > rm0) sacc[j][1] = -1e30f;
            if (c0 > rm1)     sacc[j][2] = -1e30f;
            if (c0 + 1 > rm1) sacc[j][3] = -1e30f;
            m0 = fmaxf(m0, fmaxf(sacc[j][0], sacc[j][1]));
            m1 = fmaxf(m1, fmaxf(sacc[j][2], sacc[j][3]));
        }
        m0 = fmaxf(m0, __shfl_xor_sync(0xffffffffu, m0, 1));
        m0 = fmaxf(m0, __shfl_xor_sync(0xffffffffu, m0, 2));
        m1 = fmaxf(m1, __shfl_xor_sync(0xffffffffu, m1, 1));
        m1 = fmaxf(m1, __shfl_xor_sync(0xffffffffu, m1, 2));

        int r0 = wr + lr, r1 = r0 + 8;
        float mo0 = mS[r0], mo1 = mS[r1];
        float mn0 = fmaxf(mo0, m0), mn1 = fmaxf(mo1, m1);
        float al0 = __expf(mo0 - mn0), al1 = __expf(mo1 - mn1);

        float sum0 = 0.f, sum1 = 0.f;
#pragma unroll
        for (int j = 0; j < 8; j++) {
            float p00 = __expf(sacc[j][0] - mn0);
            float p01 = __expf(sacc[j][1] - mn0);
            float p10 = __expf(sacc[j][2] - mn1);
            float p11 = __expf(sacc[j][3] - mn1);
            sum0 += p00 + p01;
            sum1 += p10 + p11;
            *(__half2*)(Ps + r0 * PSTR_H + j * 8 + 2 * lc) = __floats2half2_rn(p00, p01);
            *(__half2*)(Ps + r1 * PSTR_H + j * 8 + 2 * lc) = __floats2half2_rn(p10, p11);
            o[j][0] *= al0; o[j][1] *= al0; o[j][2] *= al1; o[j][3] *= al1;
        }
        sum0 += __shfl_xor_sync(0xffffffffu, sum0, 1);
        sum0 += __shfl_xor_sync(0xffffffffu, sum0, 2);
        sum1 += __shfl_xor_sync(0xffffffffu, sum1, 1);
        sum1 += __shfl_xor_sync(0xffffffffu, sum1, 2);
        if (lc == 0) {
            lS[r0] = lS[r0] * al0 + sum0;
            lS[r1] = lS[r1] * al1 + sum1;
            mS[r0] = mn0;
            mS[r1] = mn1;
        }
        __syncwarp();

        // ---- O += P V ----
#pragma unroll
        for (int ks = 0; ks < 4; ks++) {
            uint32_t a[4];
            ldsm_x4(pFrag + ks * 32, a);
#pragma unroll
            for (int j = 0; j < 8; j++) {
                int n0 = j * 8 + lr;
                uint32_t b0 = *(const uint32_t*)(VTs + n0 * VTSTR_H + ks * 16 + 2 * lc);
                uint32_t b1 = *(const uint32_t*)(VTs + n0 * VTSTR_H + ks * 16 + 8 + 2 * lc);
                mma_f16(o[j], a[0], a[1], a[2], a[3], b0, b1);
            }
        }
    }

    __syncwarp();
    int r0 = wr + lr, r1 = r0 + 8;
    float inv0 = 1.0f / lS[r0];
    float inv1 = 1.0f / lS[r1];
#pragma unroll
    for (int j = 0; j < 8; j++) {
        int d = j * 8 + 2 * lc;
        *(__half2*)(Y + base + (size_t)(qb + r0) * CC + d) =
            __floats2half2_rn(o[j][0] * inv0, o[j][1] * inv0);
        *(__half2*)(Y + base + (size_t)(qb + r1) * CC + d) =
            __floats2half2_rn(o[j][2] * inv1, o[j][3] * inv1);
    }
}

// ---------------- host orchestration ----------------
extern "C" void kernel_launch(void* const* d_in, const int* in_sizes, int n_in,
                              void* d_out, int out_size) {
    const float* x     = (const float*)d_in[0];
    const float* ln1_g = (const float*)d_in[1];
    const float* ln1_b = (const float*)d_in[2];
    const float* Wq    = (const float*)d_in[3];
    const float* bq    = (const float*)d_in[4];
    const float* Wk    = (const float*)d_in[5];
    const float* bk    = (const float*)d_in[6];
    const float* Wv    = (const float*)d_in[7];
    const float* bv    = (const float*)d_in[8];
    const float* Wp    = (const float*)d_in[9];
    const float* bp    = (const float*)d_in[10];
    const float* ln2_g = (const float*)d_in[11];
    const float* ln2_b = (const float*)d_in[12];
    const float* W1    = (const float*)d_in[13];
    const float* b1    = (const float*)d_in[14];
    const float* W2    = (const float*)d_in[15];
    const float* b2    = (const float*)d_in[16];

    float* res;
    __half *ln, *q, *k, *v, *y, *h1, *wt;
    cudaGetSymbolAddress((void**)&res, g_res);
    cudaGetSymbolAddress((void**)&ln,  g_ln);
    cudaGetSymbolAddress((void**)&q,   g_q);
    cudaGetSymbolAddress((void**)&k,   g_k);
    cudaGetSymbolAddress((void**)&v,   g_v);
    cudaGetSymbolAddress((void**)&y,   g_y);
    cudaGetSymbolAddress((void**)&h1,  g_h1);
    cudaGetSymbolAddress((void**)&wt,  g_wt);

    cudaFuncSetAttribute(attn_tc_kernel, cudaFuncAttributeMaxDynamicSharedMemorySize, ATTN_SMEM);
    cudaFuncSetAttribute(tc_gemm_kernel<EPI_RESID, float>,  cudaFuncAttributeMaxDynamicSharedMemorySize, GEMM_SMEM_BYTES);
    cudaFuncSetAttribute(tc_gemm_kernel<EPI_GELU, __half>,  cudaFuncAttributeMaxDynamicSharedMemorySize, GEMM_SMEM_BYTES);
    cudaFuncSetAttribute(qkv_gemm_kernel,                   cudaFuncAttributeMaxDynamicSharedMemorySize, GEMM_SMEM_BYTES);

    // ---- convert + transpose weights to half [N][K] ----
    {
        dim3 tb(32, 8);
        convT_kernel<<<dim3(CC/32,  CC/32,  LNUM), tb>>>(Wq, wt + WQ_OFF, CC, CC);
        convT_kernel<<<dim3(CC/32,  CC/32,  LNUM), tb>>>(Wk, wt + WK_OFF, CC, CC);
        convT_kernel<<<dim3(CC/32,  CC/32,  LNUM), tb>>>(Wv, wt + WV_OFF, CC, CC);
        convT_kernel<<<dim3(CC/32,  CC/32,  LNUM), tb>>>(Wp, wt + WP_OFF, CC, CC);
        convT_kernel<<<dim3(HID/32, CC/32,  LNUM), tb>>>(W1, wt + W1_OFF, CC, HID);
        convT_kernel<<<dim3(CC/32,  HID/32, LNUM), tb>>>(W2, wt + W2_OFF, HID, CC);
    }

    // residual = x
    {
        int n4 = (MM * CC) / 4;
        copy4_kernel<<<(n4 + 255) / 256, 256>>>((float4*)res, (const float4*)x, n4);
    }

    dim3 gemm_qkv3(CC / 128, MM / 128, 3);   // 576
    dim3 gemm_c  (CC / 128, MM / 128);       // 192
    dim3 gemm_h  (HID / 128, MM / 128);      // 768
    dim3 attn_grid(TT / 128, BB * NH);       // 384

    for (int l = 0; l < LNUM; l++) {
        const __half* wq = wt + WQ_OFF + (size_t)l * CC * CC;
        const __half* wk = wt + WK_OFF + (size_t)l * CC * CC;
        const __half* wv = wt + WV_OFF + (size_t)l * CC * CC;
        const __half* wp = wt + WP_OFF + (size_t)l * CC * CC;
        const __half* w1 = wt + W1_OFF + (size_t)l * CC * HID;
        const __half* w2 = wt + W2_OFF + (size_t)l * HID * CC;

        ln_kernel<<<MM, 256>>>(res, ln1_g + (size_t)l*CC, ln1_b + (size_t)l*CC, ln);
        qkv_gemm_kernel<<<gemm_qkv3, 256, GEMM_SMEM_BYTES>>>(
            ln, wq, wk, wv, bq + (size_t)l*CC, bk + (size_t)l*CC, bv + (size_t)l*CC, q, k, v);
        attn_tc_kernel<<<attn_grid, 256, ATTN_SMEM>>>(q, k, v, y);
        tc_gemm_kernel<EPI_RESID, float><<<gemm_c, 256, GEMM_SMEM_BYTES>>>(
            y, wp, bp + (size_t)l*CC, res, res, CC, CC);
        ln_kernel<<<MM, 256>>>(res, ln2_g + (size_t)l*CC, ln2_b + (size_t)l*CC, ln);
        tc_gemm_kernel<EPI_GELU, __half><<<gemm_h, 256, GEMM_SMEM_BYTES>>>(
            ln, w1, b1 + (size_t)l*HID, nullptr, h1, HID, CC);
        float* outC = (l == LNUM - 1) ? (float*)d_out : res;
        tc_gemm_kernel<EPI_RESID, float><<<gemm_c, 256, GEMM_SMEM_BYTES>>>(
            h1, w2, b2 + (size_t)l*CC, res, outC, CC, HID);
    }
}

// round 11
// speedup vs baseline: 1.8014x; 1.0220x over previous
#include <cuda_runtime.h>
#include <cuda_fp16.h>
#include <math.h>
#include <cstdint>

// ---------------- problem constants ----------------
#define LNUM 4
#define BB   4
#define TT   1024
#define CC   768
#define NH   12
#define HD   64
#define HID  3072
#define MM   (BB*TT)          // 4096 rows
#define EPS_LN 1e-5f

// ---------------- scratch (device globals; no allocation allowed) ----------------
__device__ float  g_res[(size_t)MM*CC];
__device__ __half g_ln [(size_t)MM*CC];
__device__ __half g_q  [(size_t)MM*CC];
__device__ __half g_k  [(size_t)MM*CC];
__device__ __half g_v  [(size_t)MM*CC];
__device__ __half g_y  [(size_t)MM*CC];
__device__ __half g_h1 [(size_t)MM*HID];
// half, transposed [N][K] weights
#define WQ_OFF 0
#define WK_OFF (WQ_OFF + (size_t)LNUM*CC*CC)
#define WV_OFF (WK_OFF + (size_t)LNUM*CC*CC)
#define WP_OFF (WV_OFF + (size_t)LNUM*CC*CC)
#define W1_OFF (WP_OFF + (size_t)LNUM*CC*CC)
#define W2_OFF (W1_OFF + (size_t)LNUM*CC*HID)
#define WT_TOTAL (W2_OFF + (size_t)LNUM*CC*HID)
__device__ __half g_wt [WT_TOTAL];

// ---------------- helpers ----------------
__device__ __forceinline__ uint32_t smem_u32(const void* p) {
    uint32_t a;
    asm("{ .reg .u64 t; cvta.to.shared.u64 t, %1; cvt.u32.u64 %0, t; }" : "=r"(a) : "l"(p));
    return a;
}
__device__ __forceinline__ void cp_async16(uint32_t dst, const void* src) {
    asm volatile("cp.async.cg.shared.global [%0], [%1], 16;" :: "r"(dst), "l"(src));
}
#define CP_COMMIT() asm volatile("cp.async.commit_group;" ::: "memory")
template <int N>
__device__ __forceinline__ void cp_wait() {
    asm volatile("cp.async.wait_group %0;" :: "n"(N) : "memory");
}
__device__ __forceinline__ void mma_f16(float* d, uint32_t a0, uint32_t a1, uint32_t a2,
                                        uint32_t a3, uint32_t b0, uint32_t b1) {
    asm volatile(
        "mma.sync.aligned.m16n8k16.row.col.f32.f16.f16.f32 "
        "{%0,%1,%2,%3}, {%4,%5,%6,%7}, {%8,%9}, {%0,%1,%2,%3};"
        : "+f"(d[0]), "+f"(d[1]), "+f"(d[2]), "+f"(d[3])
        : "r"(a0), "r"(a1), "r"(a2), "r"(a3), "r"(b0), "r"(b1));
}
__device__ __forceinline__ void ldsm_x4(uint32_t addr, uint32_t* r) {
    asm volatile("ldmatrix.sync.aligned.m8n8.x4.shared.b16 {%0,%1,%2,%3}, [%4];"
        : "=r"(r[0]), "=r"(r[1]), "=r"(r[2]), "=r"(r[3]) : "r"(addr));
}
__device__ __forceinline__ uint32_t h2pack(float a, float b) {
    __half2 h = __floats2half2_rn(a, b);
    return *(uint32_t*)&h;
}

// ---------------- small kernels ----------------
// convert fp32 [K][N] weight -> half transposed [N][K]; grid.z = layer
__global__ void convT_kernel(const float* __restrict__ src, __half* __restrict__ dst,
                             int K, int N) {
    __shared__ float tile[32][33];
    const float* s = src + (size_t)blockIdx.z * K * N;
    __half* d = dst + (size_t)blockIdx.z * K * N;
    int tx = threadIdx.x, ty = threadIdx.y;
    int n0 = blockIdx.x * 32, k0 = blockIdx.y * 32;
#pragma unroll
    for (int i = 0; i < 32; i += 8)
        tile[ty + i][tx] = s[(size_t)(k0 + ty + i) * N + n0 + tx];
    __syncthreads();
#pragma unroll
    for (int i = 0; i < 32; i += 8)
        d[(size_t)(n0 + ty + i) * K + k0 + tx] = __float2half_rn(tile[tx][ty + i]);
}

// layernorm; output half (consumed only as GEMM A operand)
__global__ void ln_kernel(const float* __restrict__ x, const float* __restrict__ g,
                          const float* __restrict__ b, __half* __restrict__ out) {
    __shared__ float red0[8], red1[8];
    int row = blockIdx.x;
    int tid = threadIdx.x;
    const float* xr = x + (size_t)row * CC;
    float s = 0.f, s2 = 0.f;
    for (int i = tid; i < CC; i += 256) { float v = xr[i]; s += v; s2 += v * v; }
    for (int o = 16; o; o >>= 1) {
        s  += __shfl_xor_sync(0xffffffffu, s,  o);
        s2 += __shfl_xor_sync(0xffffffffu, s2, o);
    }
    if ((tid & 31) == 0) { red0[tid >> 5] = s; red1[tid >> 5] = s2; }
    __syncthreads();
    if (tid < 32) {
        s  = (tid < 8) ? red0[tid] : 0.f;
        s2 = (tid < 8) ? red1[tid] : 0.f;
        for (int o = 4; o; o >>= 1) {
            s  += __shfl_xor_sync(0xffffffffu, s,  o);
            s2 += __shfl_xor_sync(0xffffffffu, s2, o);
        }
        if (tid == 0) { red0[0] = s; red1[0] = s2; }
    }
    __syncthreads();
    float mu  = red0[0] * (1.f / CC);
    float var = red1[0] * (1.f / CC) - mu * mu;
    float rs  = rsqrtf(var + EPS_LN);
    __half* outr = out + (size_t)row * CC;
    for (int i = tid; i < CC; i += 256)
        outr[i] = __float2half_rn((xr[i] - mu) * rs * g[i] + b[i]);
}

// ---------------- fp16 mma.sync GEMM, cp.async 4-stage, BK=32, ldsm A+B ----------------
#define EPI_BIAS  0
#define EPI_RESID 1
#define EPI_GELU  2

#define STAGES 4
#define BK 32
#define ASTR_H 40
#define BSTR_H 40
#define A_STG_H (128 * ASTR_H)
#define B_STG_H (128 * BSTR_H)
#define GEMM_SMEM_BYTES (STAGES * (A_STG_H + B_STG_H) * 2 + 512)   // 82,432 B

template <int EPI, typename OutT>
__device__ __forceinline__ void gemm_body(const __half* __restrict__ A, const __half* __restrict__ Wt,
                                          const float* __restrict__ bias, const float* __restrict__ resid,
                                          OutT* __restrict__ C, int Ndim, int Kdim,
                                          int bm, int bn, char* dsm) {
    __half* sA = (__half*)dsm;
    __half* sB = (__half*)dsm + STAGES * A_STG_H;
    float* sBias = (float*)(dsm + STAGES * (A_STG_H + B_STG_H) * 2);

    int tid = threadIdx.x;
    int lane = tid & 31;
    int wid = tid >> 5;

    if (tid < 128) sBias[tid] = bias[bn + tid];

    int lr = lane >> 2;
    int lc = lane & 3;
    int wm = (wid & 1) * 64;
    int wn = (wid >> 1) * 32;

    int idx0 = tid * 2, idx1 = tid * 2 + 1;
    int r0i = idx0 >> 2, s0i = (idx0 & 3) * 8;
    int r1i = idx1 >> 2, s1i = (idx1 & 3) * 8;

    uint32_t sA_base = smem_u32(sA);
    uint32_t sB_base = smem_u32(sB);
    uint32_t aFrag = sA_base + (uint32_t)((wm + (lane & 15)) * ASTR_H) * 2 + ((lane & 16) ? 16u : 0u);
    uint32_t bFrag = sB_base + (uint32_t)((wn + (lane & 7)) * BSTR_H) * 2 + (uint32_t)(lane >> 3) * 16u;

    const __half* aSrc0 = A + (size_t)(bm + r0i) * Kdim + s0i;
    const __half* aSrc1 = A + (size_t)(bm + r1i) * Kdim + s1i;
    const __half* bSrc0 = Wt + (size_t)(bn + r0i) * Kdim + s0i;
    const __half* bSrc1 = Wt + (size_t)(bn + r1i) * Kdim + s1i;

    float acc[4][4][4];
#pragma unroll
    for (int i = 0; i < 4; i++)
#pragma unroll
        for (int j = 0; j < 4; j++)
#pragma unroll
            for (int r = 0; r < 4; r++) acc[i][j][r] = 0.f;

    int nch = Kdim / BK;

    auto load_stage = [&](int stg, int chunk) {
        int k0 = chunk * BK;
        uint32_t ab = sA_base + (uint32_t)(stg * A_STG_H) * 2;
        uint32_t bb = sB_base + (uint32_t)(stg * B_STG_H) * 2;
        cp_async16(ab + (uint32_t)(r0i * ASTR_H + s0i) * 2, aSrc0 + k0);
        cp_async16(ab + (uint32_t)(r1i * ASTR_H + s1i) * 2, aSrc1 + k0);
        cp_async16(bb + (uint32_t)(r0i * BSTR_H + s0i) * 2, bSrc0 + k0);
        cp_async16(bb + (uint32_t)(r1i * BSTR_H + s1i) * 2, bSrc1 + k0);
    };

#pragma unroll
    for (int s = 0; s < STAGES - 1; s++) {
        if (s < nch) load_stage(s, s);
        CP_COMMIT();
    }
    cp_wait<STAGES - 2>();
    __syncthreads();

    for (int c = 0; c < nch; c++) {
        int buf = c % STAGES;
        int nc = c + STAGES - 1;
        if (nc < nch) load_stage(nc % STAGES, nc);
        CP_COMMIT();

        uint32_t aStage = aFrag + (uint32_t)(buf * A_STG_H) * 2;
        uint32_t bStage = bFrag + (uint32_t)(buf * B_STG_H) * 2;

        uint32_t bfr[4][4];
#pragma unroll
        for (int j = 0; j < 4; j++)
            ldsm_x4(bStage + (uint32_t)(j * 8 * BSTR_H) * 2, bfr[j]);

#pragma unroll
        for (int ks = 0; ks < 2; ks++) {
#pragma unroll
            for (int i = 0; i < 4; i++) {
                uint32_t a[4];
                ldsm_x4(aStage + (uint32_t)(i * 16 * ASTR_H) * 2 + ks * 32, a);
#pragma unroll
                for (int j = 0; j < 4; j++)
                    mma_f16(acc[i][j], a[0], a[1], a[2], a[3], bfr[j][2 * ks], bfr[j][2 * ks + 1]);
            }
        }
        cp_wait<STAGES - 2>();
        __syncthreads();
    }

#pragma unroll
    for (int i = 0; i < 4; i++) {
        int r0 = bm + wm + i * 16 + lr;
#pragma unroll
        for (int j = 0; j < 4; j++) {
            int colL = wn + j * 8 + lc * 2;
            int col = bn + colL;
            float v0 = acc[i][j][0] + sBias[colL];
            float v1 = acc[i][j][1] + sBias[colL + 1];
            float v2 = acc[i][j][2] + sBias[colL];
            float v3 = acc[i][j][3] + sBias[colL + 1];
            if (EPI == EPI_RESID) {
                float2 ra = *(const float2*)(resid + (size_t)r0 * Ndim + col);
                float2 rb = *(const float2*)(resid + (size_t)(r0 + 8) * Ndim + col);
                v0 += ra.x; v1 += ra.y; v2 += rb.x; v3 += rb.y;
            }
            if (EPI == EPI_GELU) {
                v0 = v0 * 0.5f * (1.0f + erff(v0 * 0.70710678118654752f));
                v1 = v1 * 0.5f * (1.0f + erff(v1 * 0.70710678118654752f));
                v2 = v2 * 0.5f * (1.0f + erff(v2 * 0.70710678118654752f));
                v3 = v3 * 0.5f * (1.0f + erff(v3 * 0.70710678118654752f));
            }
            if (sizeof(OutT) == 4) {
                *(float2*)((float*)C + (size_t)r0 * Ndim + col)       = make_float2(v0, v1);
                *(float2*)((float*)C + (size_t)(r0 + 8) * Ndim + col) = make_float2(v2, v3);
            } else {
                *(__half2*)((__half*)C + (size_t)r0 * Ndim + col)       = __floats2half2_rn(v0, v1);
                *(__half2*)((__half*)C + (size_t)(r0 + 8) * Ndim + col) = __floats2half2_rn(v2, v3);
            }
        }
    }
}

template <int EPI, typename OutT>
__global__ __launch_bounds__(256, 2)
void tc_gemm_kernel(const __half* __restrict__ A, const __half* __restrict__ Wt,
                    const float* __restrict__ bias, const float* __restrict__ resid,
                    OutT* __restrict__ C, int Ndim, int Kdim) {
    extern __shared__ char dsm[];
    gemm_body<EPI, OutT>(A, Wt, bias, resid, C, Ndim, Kdim, blockIdx.y * 128, blockIdx.x * 128, dsm);
}

__global__ __launch_bounds__(256, 2)
void qkv_gemm_kernel(const __half* __restrict__ A,
                     const __half* __restrict__ W0, const __half* __restrict__ W1, const __half* __restrict__ W2,
                     const float* __restrict__ b0, const float* __restrict__ b1, const float* __restrict__ b2,
                     __half* __restrict__ C0, __half* __restrict__ C1, __half* __restrict__ C2) {
    extern __shared__ char dsm[];
    const __half* W = (blockIdx.z == 0) ? W0 : (blockIdx.z == 1) ? W1 : W2;
    const float* bi = (blockIdx.z == 0) ? b0 : (blockIdx.z == 1) ? b1 : b2;
    __half* C = (blockIdx.z == 0) ? C0 : (blockIdx.z == 1) ? C1 : C2;
    gemm_body<EPI_BIAS, __half>(A, W, bi, nullptr, C, CC, CC, blockIdx.y * 128, blockIdx.x * 128, dsm);
}

// ---------------- fp16 tensor-core flash attention (register P, register m/l) ----------------
#define QSTR_H 72
#define KSTR_H 72
#define VTSTR_H 72
#define ATT_Q_OFFH 0
#define ATT_K_OFFH (128 * QSTR_H)
#define ATT_VT_OFFH (ATT_K_OFFH + 64 * KSTR_H)
#define ATT_HALVES (ATT_VT_OFFH + 64 * VTSTR_H)
#define ATTN_SMEM (ATT_HALVES * 2)          // 36,864 B

__global__ __launch_bounds__(256, 2)
void attn_tc_kernel(const __half* __restrict__ Q, const __half* __restrict__ K,
                    const __half* __restrict__ V, __half* __restrict__ Y) {
    extern __shared__ __half smh[];
    __half* Qs  = smh + ATT_Q_OFFH;
    __half* Ks  = smh + ATT_K_OFFH;
    __half* VTs = smh + ATT_VT_OFFH;

    int tid = threadIdx.x;
    int lane = tid & 31;
    int wid = tid >> 5;
    int lr = lane >> 2;
    int lc = lane & 3;
    int wr = wid * 16;

    // heavy-tile-first scheduling: blocks with qmod=128 (16 k-tiles) launch first
    int bx = blockIdx.x;
    int qb = (bx < 4) ? ((bx * 2 + 1) * 128) : ((bx - 4) * 2 * 128);
    int bh = blockIdx.y;
    int b = bh / NH, h = bh % NH;
    size_t base = (size_t)b * TT * CC + (size_t)h * HD;

    uint32_t qFrag = smem_u32(Qs) + (uint32_t)((wr + (lane & 15)) * QSTR_H) * 2 + ((lane & 16) ? 16u : 0u);

    // load Q tile, prescale by 1/8
    {
        const __half2 sc = __float2half2_rn(0.125f);
        for (int i = tid; i < 128 * 8; i += 256) {
            int row = i >> 3, cg = (i & 7) * 8;
            uint4 u = *(const uint4*)(Q + base + (size_t)(qb + row) * CC + cg);
            __half2* hp = (__half2*)&u;
            hp[0] = __hmul2(hp[0], sc); hp[1] = __hmul2(hp[1], sc);
            hp[2] = __hmul2(hp[2], sc); hp[3] = __hmul2(hp[3], sc);
            *(uint4*)(Qs + row * QSTR_H + cg) = u;
        }
    }

    float o[8][4];
#pragma unroll
    for (int j = 0; j < 8; j++)
#pragma unroll
        for (int r = 0; r < 4; r++) o[j][r] = 0.f;

    // running max / sum in registers (rows r0 = wr+lr, r1 = r0+8; identical across lc-quad)
    float m0r = -1e30f, m1r = -1e30f;
    float l0r = 0.f, l1r = 0.f;

    int qmod = qb & 255;
    int rm0 = qmod + wr + lr;
    int rm1 = rm0 + 8;

    for (int kb = 0; kb < TT; kb += 64) {
        int kbm = kb & 255;
        if (kbm > qmod + 127) continue;
        __syncthreads();
        for (int i = tid; i < 64 * 8; i += 256) {
            int row = i >> 3, cg = (i & 7) * 8;
            *(uint4*)(Ks + row * KSTR_H + cg) = *(const uint4*)(K + base + (size_t)(kb + row) * CC + cg);
        }
        {
            int row = tid & 63;
            int cgrp = tid >> 6;
            uint4 v0 = *(const uint4*)(V + base + (size_t)(kb + row) * CC + cgrp * 16);
            uint4 v1 = *(const uint4*)(V + base + (size_t)(kb + row) * CC + cgrp * 16 + 8);
            const __half* h0 = (const __half*)&v0;
            const __half* h1 = (const __half*)&v1;
#pragma unroll
            for (int j = 0; j < 8; j++) {
                VTs[(cgrp * 16 + j) * VTSTR_H + row] = h0[j];
                VTs[(cgrp * 16 + 8 + j) * VTSTR_H + row] = h1[j];
            }
        }
        __syncthreads();

        // ---- S = Q K^T ----
        float sacc[8][4];
#pragma unroll
        for (int j = 0; j < 8; j++)
#pragma unroll
            for (int r = 0; r < 4; r++) sacc[j][r] = 0.f;
#pragma unroll
        for (int ks = 0; ks < 4; ks++) {
            uint32_t a[4];
            ldsm_x4(qFrag + ks * 32, a);
#pragma unroll
            for (int j = 0; j < 8; j++) {
                int n0 = j * 8 + lr;
                uint32_t b0 = *(const uint32_t*)(Ks + n0 * KSTR_H + ks * 16 + 2 * lc);
                uint32_t b1 = *(const uint32_t*)(Ks + n0 * KSTR_H + ks * 16 + 8 + 2 * lc);
                mma_f16(sacc[j], a[0], a[1], a[2], a[3], b0, b1);
            }
        }

        // ---- mask + online softmax (all register-resident) ----
        float m0 = -1e30f, m1 = -1e30f;
#pragma unroll
        for (int j = 0; j < 8; j++) {
            int c0 = kbm + j * 8 + 2 * lc;
            if (c0 > rm0)     sacc[j][0] = -1e30f;
            if (c0 + 1 > rm0) sacc[j][1] = -1e30f;
            if (c0 > rm1)     sacc[j][2] = -1e30f;
            if (c0 + 1 > rm1) sacc[j][3] = -1e30f;
            m0 = fmaxf(m0, fmaxf(sacc[j][0], sacc[j][1]));
            m1 = fmaxf(m1, fmaxf(sacc[j][2], sacc[j][3]));
        }
        m0 = fmaxf(m0, __shfl_xor_sync(0xffffffffu, m0, 1));
        m0 = fmaxf(m0, __shfl_xor_sync(0xffffffffu, m0, 2));
        m1 = fmaxf(m1, __shfl_xor_sync(0xffffffffu, m1, 1));
        m1 = fmaxf(m1, __shfl_xor_sync(0xffffffffu, m1, 2));

        float mn0 = fmaxf(m0r, m0), mn1 = fmaxf(m1r, m1);
        float al0 = __expf(m0r - mn0), al1 = __expf(m1r - mn1);
        m0r = mn0; m1r = mn1;

        // exp + pack P fragments directly as PV A-operands
        uint32_t pa[4][4];
        float sum0 = 0.f, sum1 = 0.f;
#pragma unroll
        for (int ks = 0; ks < 4; ks++) {
#pragma unroll
            for (int jj = 0; jj < 2; jj++) {
                int j = 2 * ks + jj;
                float p00 = __expf(sacc[j][0] - mn0);
                float p01 = __expf(sacc[j][1] - mn0);
                float p10 = __expf(sacc[j][2] - mn1);
                float p11 = __expf(sacc[j][3] - mn1);
                sum0 += p00 + p01;
                sum1 += p10 + p11;
                pa[ks][2 * jj]     = h2pack(p00, p01);
                pa[ks][2 * jj + 1] = h2pack(p10, p11);
            }
        }
        sum0 += __shfl_xor_sync(0xffffffffu, sum0, 1);
        sum0 += __shfl_xor_sync(0xffffffffu, sum0, 2);
        sum1 += __shfl_xor_sync(0xffffffffu, sum1, 1);
        sum1 += __shfl_xor_sync(0xffffffffu, sum1, 2);
        l0r = l0r * al0 + sum0;
        l1r = l1r * al1 + sum1;

        // rescale O
#pragma unroll
        for (int j = 0; j < 8; j++) {
            o[j][0] *= al0; o[j][1] *= al0; o[j][2] *= al1; o[j][3] *= al1;
        }

        // ---- O += P V (P fragments from registers) ----
#pragma unroll
        for (int ks = 0; ks < 4; ks++) {
#pragma unroll
            for (int j = 0; j < 8; j++) {
                int n0 = j * 8 + lr;
                uint32_t b0 = *(const uint32_t*)(VTs + n0 * VTSTR_H + ks * 16 + 2 * lc);
                uint32_t b1 = *(const uint32_t*)(VTs + n0 * VTSTR_H + ks * 16 + 8 + 2 * lc);
                mma_f16(o[j], pa[ks][0], pa[ks][1], pa[ks][2], pa[ks][3], b0, b1);
            }
        }
    }

    int r0 = wr + lr, r1 = r0 + 8;
    float inv0 = 1.0f / l0r;
    float inv1 = 1.0f / l1r;
#pragma unroll
    for (int j = 0; j < 8; j++) {
        int d = j * 8 + 2 * lc;
        *(__half2*)(Y + base + (size_t)(qb + r0) * CC + d) =
            __floats2half2_rn(o[j][0] * inv0, o[j][1] * inv0);
        *(__half2*)(Y + base + (size_t)(qb + r1) * CC + d) =
            __floats2half2_rn(o[j][2] * inv1, o[j][3] * inv1);
    }
}

// ---------------- host orchestration ----------------
extern "C" void kernel_launch(void* const* d_in, const int* in_sizes, int n_in,
                              void* d_out, int out_size) {
    const float* x     = (const float*)d_in[0];
    const float* ln1_g = (const float*)d_in[1];
    const float* ln1_b = (const float*)d_in[2];
    const float* Wq    = (const float*)d_in[3];
    const float* bq    = (const float*)d_in[4];
    const float* Wk    = (const float*)d_in[5];
    const float* bk    = (const float*)d_in[6];
    const float* Wv    = (const float*)d_in[7];
    const float* bv    = (const float*)d_in[8];
    const float* Wp    = (const float*)d_in[9];
    const float* bp    = (const float*)d_in[10];
    const float* ln2_g = (const float*)d_in[11];
    const float* ln2_b = (const float*)d_in[12];
    const float* W1    = (const float*)d_in[13];
    const float* b1    = (const float*)d_in[14];
    const float* W2    = (const float*)d_in[15];
    const float* b2    = (const float*)d_in[16];

    float* res;
    __half *ln, *q, *k, *v, *y, *h1, *wt;
    cudaGetSymbolAddress((void**)&res, g_res);
    cudaGetSymbolAddress((void**)&ln,  g_ln);
    cudaGetSymbolAddress((void**)&q,   g_q);
    cudaGetSymbolAddress((void**)&k,   g_k);
    cudaGetSymbolAddress((void**)&v,   g_v);
    cudaGetSymbolAddress((void**)&y,   g_y);
    cudaGetSymbolAddress((void**)&h1,  g_h1);
    cudaGetSymbolAddress((void**)&wt,  g_wt);

    cudaFuncSetAttribute(attn_tc_kernel, cudaFuncAttributeMaxDynamicSharedMemorySize, ATTN_SMEM);
    cudaFuncSetAttribute(tc_gemm_kernel<EPI_RESID, float>,  cudaFuncAttributeMaxDynamicSharedMemorySize, GEMM_SMEM_BYTES);
    cudaFuncSetAttribute(tc_gemm_kernel<EPI_GELU, __half>,  cudaFuncAttributeMaxDynamicSharedMemorySize, GEMM_SMEM_BYTES);
    cudaFuncSetAttribute(qkv_gemm_kernel,                   cudaFuncAttributeMaxDynamicSharedMemorySize, GEMM_SMEM_BYTES);

    // ---- convert + transpose weights to half [N][K] ----
    {
        dim3 tb(32, 8);
        convT_kernel<<<dim3(CC/32,  CC/32,  LNUM), tb>>>(Wq, wt + WQ_OFF, CC, CC);
        convT_kernel<<<dim3(CC/32,  CC/32,  LNUM), tb>>>(Wk, wt + WK_OFF, CC, CC);
        convT_kernel<<<dim3(CC/32,  CC/32,  LNUM), tb>>>(Wv, wt + WV_OFF, CC, CC);
        convT_kernel<<<dim3(CC/32,  CC/32,  LNUM), tb>>>(Wp, wt + WP_OFF, CC, CC);
        convT_kernel<<<dim3(HID/32, CC/32,  LNUM), tb>>>(W1, wt + W1_OFF, CC, HID);
        convT_kernel<<<dim3(CC/32,  HID/32, LNUM), tb>>>(W2, wt + W2_OFF, HID, CC);
    }

    dim3 gemm_qkv3(CC / 128, MM / 128, 3);   // 576
    dim3 gemm_c  (CC / 128, MM / 128);       // 192
    dim3 gemm_h  (HID / 128, MM / 128);      // 768
    dim3 attn_grid(TT / 128, BB * NH);       // 384

    for (int l = 0; l < LNUM; l++) {
        const __half* wq = wt + WQ_OFF + (size_t)l * CC * CC;
        const __half* wk = wt + WK_OFF + (size_t)l * CC * CC;
        const __half* wv = wt + WV_OFF + (size_t)l * CC * CC;
        const __half* wp = wt + WP_OFF + (size_t)l * CC * CC;
        const __half* w1 = wt + W1_OFF + (size_t)l * CC * HID;
        const __half* w2 = wt + W2_OFF + (size_t)l * HID * CC;

        // layer 0 reads the residual stream directly from x (no init copy)
        const float* resIn = (l == 0) ? x : res;

        ln_kernel<<<MM, 256>>>(resIn, ln1_g + (size_t)l*CC, ln1_b + (size_t)l*CC, ln);
        qkv_gemm_kernel<<<gemm_qkv3, 256, GEMM_SMEM_BYTES>>>(
            ln, wq, wk, wv, bq + (size_t)l*CC, bk + (size_t)l*CC, bv + (size_t)l*CC, q, k, v);
        attn_tc_kernel<<<attn_grid, 256, ATTN_SMEM>>>(q, k, v, y);
        tc_gemm_kernel<EPI_RESID, float><<<gemm_c, 256, GEMM_SMEM_BYTES>>>(
            y, wp, bp + (size_t)l*CC, resIn, res, CC, CC);
        ln_kernel<<<MM, 256>>>(res, ln2_g + (size_t)l*CC, ln2_b + (size_t)l*CC, ln);
        tc_gemm_kernel<EPI_GELU, __half><<<gemm_h, 256, GEMM_SMEM_BYTES>>>(
            ln, w1, b1 + (size_t)l*HID, nullptr, h1, HID, CC);
        float* outC = (l == LNUM - 1) ? (float*)d_out : res;
        tc_gemm_kernel<EPI_RESID, float><<<gemm_c, 256, GEMM_SMEM_BYTES>>>(
            h1, w2, b2 + (size_t)l*CC, res, outC, CC, HID);
    }
}

// round 12
// speedup vs baseline: 1.8372x; 1.0199x over previous
#include <cuda_runtime.h>
#include <cuda_fp16.h>
#include <math.h>
#include <cstdint>

// ---------------- problem constants ----------------
#define LNUM 4
#define BB   4
#define TT   1024
#define CC   768
#define NH   12
#define HD   64
#define HID  3072
#define MM   (BB*TT)          // 4096 rows
#define EPS_LN 1e-5f

// ---------------- scratch (device globals; no allocation allowed) ----------------
__device__ float  g_res[(size_t)MM*CC];
__device__ __half g_ln [(size_t)MM*CC];
__device__ __half g_q  [(size_t)MM*CC];
__device__ __half g_k  [(size_t)MM*CC];
__device__ __half g_v  [(size_t)MM*CC];
__device__ __half g_y  [(size_t)MM*CC];
__device__ __half g_h1 [(size_t)MM*HID];
// half, transposed [N][K] weights
#define WQ_OFF 0
#define WK_OFF (WQ_OFF + (size_t)LNUM*CC*CC)
#define WV_OFF (WK_OFF + (size_t)LNUM*CC*CC)
#define WP_OFF (WV_OFF + (size_t)LNUM*CC*CC)
#define W1_OFF (WP_OFF + (size_t)LNUM*CC*CC)
#define W2_OFF (W1_OFF + (size_t)LNUM*CC*HID)
#define WT_TOTAL (W2_OFF + (size_t)LNUM*CC*HID)
__device__ __half g_wt [WT_TOTAL];

// ---------------- helpers ----------------
__device__ __forceinline__ uint32_t smem_u32(const void* p) {
    uint32_t a;
    asm("{ .reg .u64 t; cvta.to.shared.u64 t, %1; cvt.u32.u64 %0, t; }" : "=r"(a) : "l"(p));
    return a;
}
__device__ __forceinline__ void cp_async16(uint32_t dst, const void* src) {
    asm volatile("cp.async.cg.shared.global [%0], [%1], 16;" :: "r"(dst), "l"(src));
}
#define CP_COMMIT() asm volatile("cp.async.commit_group;" ::: "memory")
template <int N>
__device__ __forceinline__ void cp_wait() {
    asm volatile("cp.async.wait_group %0;" :: "n"(N) : "memory");
}
__device__ __forceinline__ void mma_f16(float* d, uint32_t a0, uint32_t a1, uint32_t a2,
                                        uint32_t a3, uint32_t b0, uint32_t b1) {
    asm volatile(
        "mma.sync.aligned.m16n8k16.row.col.f32.f16.f16.f32 "
        "{%0,%1,%2,%3}, {%4,%5,%6,%7}, {%8,%9}, {%0,%1,%2,%3};"
        : "+f"(d[0]), "+f"(d[1]), "+f"(d[2]), "+f"(d[3])
        : "r"(a0), "r"(a1), "r"(a2), "r"(a3), "r"(b0), "r"(b1));
}
__device__ __forceinline__ void ldsm_x4(uint32_t addr, uint32_t* r) {
    asm volatile("ldmatrix.sync.aligned.m8n8.x4.shared.b16 {%0,%1,%2,%3}, [%4];"
        : "=r"(r[0]), "=r"(r[1]), "=r"(r[2]), "=r"(r[3]) : "r"(addr));
}
__device__ __forceinline__ void ldsm_x4_trans(uint32_t addr, uint32_t* r) {
    asm volatile("ldmatrix.sync.aligned.m8n8.x4.trans.shared.b16 {%0,%1,%2,%3}, [%4];"
        : "=r"(r[0]), "=r"(r[1]), "=r"(r[2]), "=r"(r[3]) : "r"(addr));
}
__device__ __forceinline__ uint32_t h2pack(float a, float b) {
    __half2 h = __floats2half2_rn(a, b);
    return *(uint32_t*)&h;
}

// ---------------- small kernels ----------------
// convert fp32 [K][N] weight -> half transposed [N][K]; grid.z = layer
__global__ void convT_kernel(const float* __restrict__ src, __half* __restrict__ dst,
                             int K, int N) {
    __shared__ float tile[32][33];
    const float* s = src + (size_t)blockIdx.z * K * N;
    __half* d = dst + (size_t)blockIdx.z * K * N;
    int tx = threadIdx.x, ty = threadIdx.y;
    int n0 = blockIdx.x * 32, k0 = blockIdx.y * 32;
#pragma unroll
    for (int i = 0; i < 32; i += 8)
        tile[ty + i][tx] = s[(size_t)(k0 + ty + i) * N + n0 + tx];
    __syncthreads();
#pragma unroll
    for (int i = 0; i < 32; i += 8)
        d[(size_t)(n0 + ty + i) * K + k0 + tx] = __float2half_rn(tile[tx][ty + i]);
}

// layernorm; output half (consumed only as GEMM A operand)
__global__ void ln_kernel(const float* __restrict__ x, const float* __restrict__ g,
                          const float* __restrict__ b, __half* __restrict__ out) {
    __shared__ float red0[8], red1[8];
    int row = blockIdx.x;
    int tid = threadIdx.x;
    const float* xr = x + (size_t)row * CC;
    float s = 0.f, s2 = 0.f;
    for (int i = tid; i < CC; i += 256) { float v = xr[i]; s += v; s2 += v * v; }
    for (int o = 16; o; o >>= 1) {
        s  += __shfl_xor_sync(0xffffffffu, s,  o);
        s2 += __shfl_xor_sync(0xffffffffu, s2, o);
    }
    if ((tid & 31) == 0) { red0[tid >> 5] = s; red1[tid >> 5] = s2; }
    __syncthreads();
    if (tid < 32) {
        s  = (tid < 8) ? red0[tid] : 0.f;
        s2 = (tid < 8) ? red1[tid] : 0.f;
        for (int o = 4; o; o >>= 1) {
            s  += __shfl_xor_sync(0xffffffffu, s,  o);
            s2 += __shfl_xor_sync(0xffffffffu, s2, o);
        }
        if (tid == 0) { red0[0] = s; red1[0] = s2; }
    }
    __syncthreads();
    float mu  = red0[0] * (1.f / CC);
    float var = red1[0] * (1.f / CC) - mu * mu;
    float rs  = rsqrtf(var + EPS_LN);
    __half* outr = out + (size_t)row * CC;
    for (int i = tid; i < CC; i += 256)
        outr[i] = __float2half_rn((xr[i] - mu) * rs * g[i] + b[i]);
}

// ---------------- fp16 mma.sync GEMM, cp.async 4-stage, BK=32, ldsm A+B ----------------
#define EPI_BIAS  0
#define EPI_RESID 1
#define EPI_GELU  2

#define STAGES 4
#define BK 32
#define ASTR_H 40
#define BSTR_H 40
#define A_STG_H (128 * ASTR_H)
#define B_STG_H (128 * BSTR_H)
#define GEMM_SMEM_BYTES (STAGES * (A_STG_H + B_STG_H) * 2 + 512)   // 82,432 B

template <int EPI, typename OutT>
__device__ __forceinline__ void gemm_body(const __half* __restrict__ A, const __half* __restrict__ Wt,
                                          const float* __restrict__ bias, const float* __restrict__ resid,
                                          OutT* __restrict__ C, int Ndim, int Kdim,
                                          int bm, int bn, char* dsm) {
    __half* sA = (__half*)dsm;
    __half* sB = (__half*)dsm + STAGES * A_STG_H;
    float* sBias = (float*)(dsm + STAGES * (A_STG_H + B_STG_H) * 2);

    int tid = threadIdx.x;
    int lane = tid & 31;
    int wid = tid >> 5;

    if (tid < 128) sBias[tid] = bias[bn + tid];

    int lr = lane >> 2;
    int lc = lane & 3;
    int wm = (wid & 1) * 64;
    int wn = (wid >> 1) * 32;

    int idx0 = tid * 2, idx1 = tid * 2 + 1;
    int r0i = idx0 >> 2, s0i = (idx0 & 3) * 8;
    int r1i = idx1 >> 2, s1i = (idx1 & 3) * 8;

    uint32_t sA_base = smem_u32(sA);
    uint32_t sB_base = smem_u32(sB);
    uint32_t aFrag = sA_base + (uint32_t)((wm + (lane & 15)) * ASTR_H) * 2 + ((lane & 16) ? 16u : 0u);
    uint32_t bFrag = sB_base + (uint32_t)((wn + (lane & 7)) * BSTR_H) * 2 + (uint32_t)(lane >> 3) * 16u;

    const __half* aSrc0 = A + (size_t)(bm + r0i) * Kdim + s0i;
    const __half* aSrc1 = A + (size_t)(bm + r1i) * Kdim + s1i;
    const __half* bSrc0 = Wt + (size_t)(bn + r0i) * Kdim + s0i;
    const __half* bSrc1 = Wt + (size_t)(bn + r1i) * Kdim + s1i;

    float acc[4][4][4];
#pragma unroll
    for (int i = 0; i < 4; i++)
#pragma unroll
        for (int j = 0; j < 4; j++)
#pragma unroll
            for (int r = 0; r < 4; r++) acc[i][j][r] = 0.f;

    int nch = Kdim / BK;

    auto load_stage = [&](int stg, int chunk) {
        int k0 = chunk * BK;
        uint32_t ab = sA_base + (uint32_t)(stg * A_STG_H) * 2;
        uint32_t bb = sB_base + (uint32_t)(stg * B_STG_H) * 2;
        cp_async16(ab + (uint32_t)(r0i * ASTR_H + s0i) * 2, aSrc0 + k0);
        cp_async16(ab + (uint32_t)(r1i * ASTR_H + s1i) * 2, aSrc1 + k0);
        cp_async16(bb + (uint32_t)(r0i * BSTR_H + s0i) * 2, bSrc0 + k0);
        cp_async16(bb + (uint32_t)(r1i * BSTR_H + s1i) * 2, bSrc1 + k0);
    };

#pragma unroll
    for (int s = 0; s < STAGES - 1; s++) {
        if (s < nch) load_stage(s, s);
        CP_COMMIT();
    }
    cp_wait<STAGES - 2>();
    __syncthreads();

    for (int c = 0; c < nch; c++) {
        int buf = c % STAGES;
        int nc = c + STAGES - 1;
        if (nc < nch) load_stage(nc % STAGES, nc);
        CP_COMMIT();

        uint32_t aStage = aFrag + (uint32_t)(buf * A_STG_H) * 2;
        uint32_t bStage = bFrag + (uint32_t)(buf * B_STG_H) * 2;

        uint32_t bfr[4][4];
#pragma unroll
        for (int j = 0; j < 4; j++)
            ldsm_x4(bStage + (uint32_t)(j * 8 * BSTR_H) * 2, bfr[j]);

#pragma unroll
        for (int ks = 0; ks < 2; ks++) {
#pragma unroll
            for (int i = 0; i < 4; i++) {
                uint32_t a[4];
                ldsm_x4(aStage + (uint32_t)(i * 16 * ASTR_H) * 2 + ks * 32, a);
#pragma unroll
                for (int j = 0; j < 4; j++)
                    mma_f16(acc[i][j], a[0], a[1], a[2], a[3], bfr[j][2 * ks], bfr[j][2 * ks + 1]);
            }
        }
        cp_wait<STAGES - 2>();
        __syncthreads();
    }

#pragma unroll
    for (int i = 0; i < 4; i++) {
        int r0 = bm + wm + i * 16 + lr;
#pragma unroll
        for (int j = 0; j < 4; j++) {
            int colL = wn + j * 8 + lc * 2;
            int col = bn + colL;
            float v0 = acc[i][j][0] + sBias[colL];
            float v1 = acc[i][j][1] + sBias[colL + 1];
            float v2 = acc[i][j][2] + sBias[colL];
            float v3 = acc[i][j][3] + sBias[colL + 1];
            if (EPI == EPI_RESID) {
                float2 ra = *(const float2*)(resid + (size_t)r0 * Ndim + col);
                float2 rb = *(const float2*)(resid + (size_t)(r0 + 8) * Ndim + col);
                v0 += ra.x; v1 += ra.y; v2 += rb.x; v3 += rb.y;
            }
            if (EPI == EPI_GELU) {
                v0 = v0 * 0.5f * (1.0f + erff(v0 * 0.70710678118654752f));
                v1 = v1 * 0.5f * (1.0f + erff(v1 * 0.70710678118654752f));
                v2 = v2 * 0.5f * (1.0f + erff(v2 * 0.70710678118654752f));
                v3 = v3 * 0.5f * (1.0f + erff(v3 * 0.70710678118654752f));
            }
            if (sizeof(OutT) == 4) {
                *(float2*)((float*)C + (size_t)r0 * Ndim + col)       = make_float2(v0, v1);
                *(float2*)((float*)C + (size_t)(r0 + 8) * Ndim + col) = make_float2(v2, v3);
            } else {
                *(__half2*)((__half*)C + (size_t)r0 * Ndim + col)       = __floats2half2_rn(v0, v1);
                *(__half2*)((__half*)C + (size_t)(r0 + 8) * Ndim + col) = __floats2half2_rn(v2, v3);
            }
        }
    }
}

template <int EPI, typename OutT>
__global__ __launch_bounds__(256, 2)
void tc_gemm_kernel(const __half* __restrict__ A, const __half* __restrict__ Wt,
                    const float* __restrict__ bias, const float* __restrict__ resid,
                    OutT* __restrict__ C, int Ndim, int Kdim) {
    extern __shared__ char dsm[];
    gemm_body<EPI, OutT>(A, Wt, bias, resid, C, Ndim, Kdim, blockIdx.y * 128, blockIdx.x * 128, dsm);
}

__global__ __launch_bounds__(256, 2)
void qkv_gemm_kernel(const __half* __restrict__ A,
                     const __half* __restrict__ W0, const __half* __restrict__ W1, const __half* __restrict__ W2,
                     const float* __restrict__ b0, const float* __restrict__ b1, const float* __restrict__ b2,
                     __half* __restrict__ C0, __half* __restrict__ C1, __half* __restrict__ C2) {
    extern __shared__ char dsm[];
    const __half* W = (blockIdx.z == 0) ? W0 : (blockIdx.z == 1) ? W1 : W2;
    const float* bi = (blockIdx.z == 0) ? b0 : (blockIdx.z == 1) ? b1 : b2;
    __half* C = (blockIdx.z == 0) ? C0 : (blockIdx.z == 1) ? C1 : C2;
    gemm_body<EPI_BIAS, __half>(A, W, bi, nullptr, C, CC, CC, blockIdx.y * 128, blockIdx.x * 128, dsm);
}

// ---------------- fp16 tensor-core flash attention (ldsm everywhere, register P/m/l) ----------------
#define QSTR_H 72
#define KSTR_H 72
#define VSTR_H 72
#define ATT_Q_OFFH 0
#define ATT_K_OFFH (128 * QSTR_H)
#define ATT_V_OFFH (ATT_K_OFFH + 64 * KSTR_H)
#define ATT_HALVES (ATT_V_OFFH + 64 * VSTR_H)
#define ATTN_SMEM (ATT_HALVES * 2)          // 36,864 B

__global__ __launch_bounds__(256, 2)
void attn_tc_kernel(const __half* __restrict__ Q, const __half* __restrict__ K,
                    const __half* __restrict__ V, __half* __restrict__ Y) {
    extern __shared__ __half smh[];
    __half* Qs = smh + ATT_Q_OFFH;
    __half* Ks = smh + ATT_K_OFFH;
    __half* Vs = smh + ATT_V_OFFH;

    int tid = threadIdx.x;
    int lane = tid & 31;
    int wid = tid >> 5;
    int lr = lane >> 2;
    int lc = lane & 3;
    int wr = wid * 16;

    // heavy-tile-first scheduling
    int bx = blockIdx.x;
    int qb = (bx < 4) ? ((bx * 2 + 1) * 128) : ((bx - 4) * 2 * 128);
    int bh = blockIdx.y;
    int b = bh / NH, h = bh % NH;
    size_t base = (size_t)b * TT * CC + (size_t)h * HD;

    uint32_t qFrag = smem_u32(Qs) + (uint32_t)((wr + (lane & 15)) * QSTR_H) * 2 + ((lane & 16) ? 16u : 0u);
    // K B-frag (non-trans, GEMM pattern): row = j*8 + (lane&7), chunk (lane>>3)*16B
    uint32_t kFrag = smem_u32(Ks) + (uint32_t)((lane & 7) * KSTR_H) * 2 + (uint32_t)(lane >> 3) * 16u;
    // V B-frag (trans): row = (lane&7) + ((lane>>3)&1)*8, n-half via lane&16
    uint32_t vFrag = smem_u32(Vs) + (uint32_t)(((lane & 7) + ((lane >> 3) & 1) * 8) * VSTR_H) * 2
                   + ((lane & 16) ? 16u : 0u);

    // load Q tile, prescale by 1/8
    {
        const __half2 sc = __float2half2_rn(0.125f);
        for (int i = tid; i < 128 * 8; i += 256) {
            int row = i >> 3, cg = (i & 7) * 8;
            uint4 u = *(const uint4*)(Q + base + (size_t)(qb + row) * CC + cg);
            __half2* hp = (__half2*)&u;
            hp[0] = __hmul2(hp[0], sc); hp[1] = __hmul2(hp[1], sc);
            hp[2] = __hmul2(hp[2], sc); hp[3] = __hmul2(hp[3], sc);
            *(uint4*)(Qs + row * QSTR_H + cg) = u;
        }
    }

    float o[8][4];
#pragma unroll
    for (int j = 0; j < 8; j++)
#pragma unroll
        for (int r = 0; r < 4; r++) o[j][r] = 0.f;

    float m0r = -1e30f, m1r = -1e30f;
    float l0r = 0.f, l1r = 0.f;

    int qmod = qb & 255;
    int rm0 = qmod + wr + lr;
    int rm1 = rm0 + 8;

    for (int kb = 0; kb < TT; kb += 64) {
        int kbm = kb & 255;
        if (kbm > qmod + 127) continue;
        __syncthreads();
        for (int i = tid; i < 64 * 8; i += 256) {
            int row = i >> 3, cg = (i & 7) * 8;
            *(uint4*)(Ks + row * KSTR_H + cg) = *(const uint4*)(K + base + (size_t)(kb + row) * CC + cg);
            *(uint4*)(Vs + row * VSTR_H + cg) = *(const uint4*)(V + base + (size_t)(kb + row) * CC + cg);
        }
        __syncthreads();

        // ---- S = Q K^T : B-frags via non-trans ldsm.x4, 2 k32 chunks ----
        float sacc[8][4];
#pragma unroll
        for (int j = 0; j < 8; j++)
#pragma unroll
            for (int r = 0; r < 4; r++) sacc[j][r] = 0.f;
#pragma unroll
        for (int kc = 0; kc < 2; kc++) {
            uint32_t bf[8][4];
#pragma unroll
            for (int j = 0; j < 8; j++)
                ldsm_x4(kFrag + (uint32_t)(j * 8 * KSTR_H) * 2 + kc * 64, bf[j]);
#pragma unroll
            for (int ksl = 0; ksl < 2; ksl++) {
                int ks = kc * 2 + ksl;
                uint32_t a[4];
                ldsm_x4(qFrag + ks * 32, a);
#pragma unroll
                for (int j = 0; j < 8; j++)
                    mma_f16(sacc[j], a[0], a[1], a[2], a[3], bf[j][2 * ksl], bf[j][2 * ksl + 1]);
            }
        }

        // ---- mask + online softmax (register-resident) ----
        float m0 = -1e30f, m1 = -1e30f;
#pragma unroll
        for (int j = 0; j < 8; j++) {
            int c0 = kbm + j * 8 + 2 * lc;
            if (c0 > rm0)     sacc[j][0] = -1e30f;
            if (c0 + 1 > rm0) sacc[j][1] = -1e30f;
            if (c0 > rm1)     sacc[j][2] = -1e30f;
            if (c0 + 1 > rm1) sacc[j][3] = -1e30f;
            m0 = fmaxf(m0, fmaxf(sacc[j][0], sacc[j][1]));
            m1 = fmaxf(m1, fmaxf(sacc[j][2], sacc[j][3]));
        }
        m0 = fmaxf(m0, __shfl_xor_sync(0xffffffffu, m0, 1));
        m0 = fmaxf(m0, __shfl_xor_sync(0xffffffffu, m0, 2));
        m1 = fmaxf(m1, __shfl_xor_sync(0xffffffffu, m1, 1));
        m1 = fmaxf(m1, __shfl_xor_sync(0xffffffffu, m1, 2));

        float mn0 = fmaxf(m0r, m0), mn1 = fmaxf(m1r, m1);
        float al0 = __expf(m0r - mn0), al1 = __expf(m1r - mn1);
        m0r = mn0; m1r = mn1;

        uint32_t pa[4][4];
        float sum0 = 0.f, sum1 = 0.f;
#pragma unroll
        for (int ks = 0; ks < 4; ks++) {
#pragma unroll
            for (int jj = 0; jj < 2; jj++) {
                int j = 2 * ks + jj;
                float p00 = __expf(sacc[j][0] - mn0);
                float p01 = __expf(sacc[j][1] - mn0);
                float p10 = __expf(sacc[j][2] - mn1);
                float p11 = __expf(sacc[j][3] - mn1);
                sum0 += p00 + p01;
                sum1 += p10 + p11;
                pa[ks][2 * jj]     = h2pack(p00, p01);
                pa[ks][2 * jj + 1] = h2pack(p10, p11);
            }
        }
        sum0 += __shfl_xor_sync(0xffffffffu, sum0, 1);
        sum0 += __shfl_xor_sync(0xffffffffu, sum0, 2);
        sum1 += __shfl_xor_sync(0xffffffffu, sum1, 1);
        sum1 += __shfl_xor_sync(0xffffffffu, sum1, 2);
        l0r = l0r * al0 + sum0;
        l1r = l1r * al1 + sum1;

#pragma unroll
        for (int j = 0; j < 8; j++) {
            o[j][0] *= al0; o[j][1] *= al0; o[j][2] *= al1; o[j][3] *= al1;
        }

        // ---- O += P V : B-frags via trans ldsm.x4 from row-major V tile ----
#pragma unroll
        for (int ks = 0; ks < 4; ks++) {
#pragma unroll
            for (int j2 = 0; j2 < 4; j2++) {
                uint32_t bv[4];
                ldsm_x4_trans(vFrag + (uint32_t)(ks * 16 * VSTR_H) * 2 + j2 * 32, bv);
                mma_f16(o[2 * j2],     pa[ks][0], pa[ks][1], pa[ks][2], pa[ks][3], bv[0], bv[1]);
                mma_f16(o[2 * j2 + 1], pa[ks][0], pa[ks][1], pa[ks][2], pa[ks][3], bv[2], bv[3]);
            }
        }
    }

    int r0 = wr + lr, r1 = r0 + 8;
    float inv0 = 1.0f / l0r;
    float inv1 = 1.0f / l1r;
#pragma unroll
    for (int j = 0; j < 8; j++) {
        int d = j * 8 + 2 * lc;
        *(__half2*)(Y + base + (size_t)(qb + r0) * CC + d) =
            __floats2half2_rn(o[j][0] * inv0, o[j][1] * inv0);
        *(__half2*)(Y + base + (size_t)(qb + r1) * CC + d) =
            __floats2half2_rn(o[j][2] * inv1, o[j][3] * inv1);
    }
}

// ---------------- host orchestration ----------------
extern "C" void kernel_launch(void* const* d_in, const int* in_sizes, int n_in,
                              void* d_out, int out_size) {
    const float* x     = (const float*)d_in[0];
    const float* ln1_g = (const float*)d_in[1];
    const float* ln1_b = (const float*)d_in[2];
    const float* Wq    = (const float*)d_in[3];
    const float* bq    = (const float*)d_in[4];
    const float* Wk    = (const float*)d_in[5];
    const float* bk    = (const float*)d_in[6];
    const float* Wv    = (const float*)d_in[7];
    const float* bv    = (const float*)d_in[8];
    const float* Wp    = (const float*)d_in[9];
    const float* bp    = (const float*)d_in[10];
    const float* ln2_g = (const float*)d_in[11];
    const float* ln2_b = (const float*)d_in[12];
    const float* W1    = (const float*)d_in[13];
    const float* b1    = (const float*)d_in[14];
    const float* W2    = (const float*)d_in[15];
    const float* b2    = (const float*)d_in[16];

    float* res;
    __half *ln, *q, *k, *v, *y, *h1, *wt;
    cudaGetSymbolAddress((void**)&res, g_res);
    cudaGetSymbolAddress((void**)&ln,  g_ln);
    cudaGetSymbolAddress((void**)&q,   g_q);
    cudaGetSymbolAddress((void**)&k,   g_k);
    cudaGetSymbolAddress((void**)&v,   g_v);
    cudaGetSymbolAddress((void**)&y,   g_y);
    cudaGetSymbolAddress((void**)&h1,  g_h1);
    cudaGetSymbolAddress((void**)&wt,  g_wt);

    cudaFuncSetAttribute(attn_tc_kernel, cudaFuncAttributeMaxDynamicSharedMemorySize, ATTN_SMEM);
    cudaFuncSetAttribute(tc_gemm_kernel<EPI_RESID, float>,  cudaFuncAttributeMaxDynamicSharedMemorySize, GEMM_SMEM_BYTES);
    cudaFuncSetAttribute(tc_gemm_kernel<EPI_GELU, __half>,  cudaFuncAttributeMaxDynamicSharedMemorySize, GEMM_SMEM_BYTES);
    cudaFuncSetAttribute(qkv_gemm_kernel,                   cudaFuncAttributeMaxDynamicSharedMemorySize, GEMM_SMEM_BYTES);

    // ---- convert + transpose weights to half [N][K] ----
    {
        dim3 tb(32, 8);
        convT_kernel<<<dim3(CC/32,  CC/32,  LNUM), tb>>>(Wq, wt + WQ_OFF, CC, CC);
        convT_kernel<<<dim3(CC/32,  CC/32,  LNUM), tb>>>(Wk, wt + WK_OFF, CC, CC);
        convT_kernel<<<dim3(CC/32,  CC/32,  LNUM), tb>>>(Wv, wt + WV_OFF, CC, CC);
        convT_kernel<<<dim3(CC/32,  CC/32,  LNUM), tb>>>(Wp, wt + WP_OFF, CC, CC);
        convT_kernel<<<dim3(HID/32, CC/32,  LNUM), tb>>>(W1, wt + W1_OFF, CC, HID);
        convT_kernel<<<dim3(CC/32,  HID/32, LNUM), tb>>>(W2, wt + W2_OFF, HID, CC);
    }

    dim3 gemm_qkv3(CC / 128, MM / 128, 3);   // 576
    dim3 gemm_c  (CC / 128, MM / 128);       // 192
    dim3 gemm_h  (HID / 128, MM / 128);      // 768
    dim3 attn_grid(TT / 128, BB * NH);       // 384

    for (int l = 0; l < LNUM; l++) {
        const __half* wq = wt + WQ_OFF + (size_t)l * CC * CC;
        const __half* wk = wt + WK_OFF + (size_t)l * CC * CC;
        const __half* wv = wt + WV_OFF + (size_t)l * CC * CC;
        const __half* wp = wt + WP_OFF + (size_t)l * CC * CC;
        const __half* w1 = wt + W1_OFF + (size_t)l * CC * HID;
        const __half* w2 = wt + W2_OFF + (size_t)l * HID * CC;

        const float* resIn = (l == 0) ? x : res;

        ln_kernel<<<MM, 256>>>(resIn, ln1_g + (size_t)l*CC, ln1_b + (size_t)l*CC, ln);
        qkv_gemm_kernel<<<gemm_qkv3, 256, GEMM_SMEM_BYTES>>>(
            ln, wq, wk, wv, bq + (size_t)l*CC, bk + (size_t)l*CC, bv + (size_t)l*CC, q, k, v);
        attn_tc_kernel<<<attn_grid, 256, ATTN_SMEM>>>(q, k, v, y);
        tc_gemm_kernel<EPI_RESID, float><<<gemm_c, 256, GEMM_SMEM_BYTES>>>(
            y, wp, bp + (size_t)l*CC, resIn, res, CC, CC);
        ln_kernel<<<MM, 256>>>(res, ln2_g + (size_t)l*CC, ln2_b + (size_t)l*CC, ln);
        tc_gemm_kernel<EPI_GELU, __half><<<gemm_h, 256, GEMM_SMEM_BYTES>>>(
            ln, w1, b1 + (size_t)l*HID, nullptr, h1, HID, CC);
        float* outC = (l == LNUM - 1) ? (float*)d_out : res;
        tc_gemm_kernel<EPI_RESID, float><<<gemm_c, 256, GEMM_SMEM_BYTES>>>(
            h1, w2, b2 + (size_t)l*CC, res, outC, CC, HID);
    }
}

// round 13
// speedup vs baseline: 1.8936x; 1.0307x over previous
#include <cuda_runtime.h>
#include <cuda_fp16.h>
#include <math.h>
#include <cstdint>

// ---------------- problem constants ----------------
#define LNUM 4
#define BB   4
#define TT   1024
#define CC   768
#define NH   12
#define HD   64
#define HID  3072
#define MM   (BB*TT)          // 4096 rows
#define EPS_LN 1e-5f

// ---------------- scratch (device globals; no allocation allowed) ----------------
__device__ float  g_res[(size_t)MM*CC];
__device__ __half g_ln [(size_t)MM*CC];
__device__ __half g_q  [(size_t)MM*CC];
__device__ __half g_k  [(size_t)MM*CC];
__device__ __half g_v  [(size_t)MM*CC];
__device__ __half g_y  [(size_t)MM*CC];
__device__ __half g_h1 [(size_t)MM*HID];
// half, transposed [N][K] weights
#define WQ_OFF 0
#define WK_OFF (WQ_OFF + (size_t)LNUM*CC*CC)
#define WV_OFF (WK_OFF + (size_t)LNUM*CC*CC)
#define WP_OFF (WV_OFF + (size_t)LNUM*CC*CC)
#define W1_OFF (WP_OFF + (size_t)LNUM*CC*CC)
#define W2_OFF (W1_OFF + (size_t)LNUM*CC*HID)
#define WT_TOTAL (W2_OFF + (size_t)LNUM*CC*HID)
__device__ __half g_wt [WT_TOTAL];

// ---------------- helpers ----------------
__device__ __forceinline__ uint32_t smem_u32(const void* p) {
    uint32_t a;
    asm("{ .reg .u64 t; cvta.to.shared.u64 t, %1; cvt.u32.u64 %0, t; }" : "=r"(a) : "l"(p));
    return a;
}
__device__ __forceinline__ void cp_async16(uint32_t dst, const void* src) {
    asm volatile("cp.async.cg.shared.global [%0], [%1], 16;" :: "r"(dst), "l"(src));
}
#define CP_COMMIT() asm volatile("cp.async.commit_group;" ::: "memory")
template <int N>
__device__ __forceinline__ void cp_wait() {
    asm volatile("cp.async.wait_group %0;" :: "n"(N) : "memory");
}
__device__ __forceinline__ void mma_f16(float* d, uint32_t a0, uint32_t a1, uint32_t a2,
                                        uint32_t a3, uint32_t b0, uint32_t b1) {
    asm volatile(
        "mma.sync.aligned.m16n8k16.row.col.f32.f16.f16.f32 "
        "{%0,%1,%2,%3}, {%4,%5,%6,%7}, {%8,%9}, {%0,%1,%2,%3};"
        : "+f"(d[0]), "+f"(d[1]), "+f"(d[2]), "+f"(d[3])
        : "r"(a0), "r"(a1), "r"(a2), "r"(a3), "r"(b0), "r"(b1));
}
__device__ __forceinline__ void ldsm_x4(uint32_t addr, uint32_t* r) {
    asm volatile("ldmatrix.sync.aligned.m8n8.x4.shared.b16 {%0,%1,%2,%3}, [%4];"
        : "=r"(r[0]), "=r"(r[1]), "=r"(r[2]), "=r"(r[3]) : "r"(addr));
}
__device__ __forceinline__ void ldsm_x4_trans(uint32_t addr, uint32_t* r) {
    asm volatile("ldmatrix.sync.aligned.m8n8.x4.trans.shared.b16 {%0,%1,%2,%3}, [%4];"
        : "=r"(r[0]), "=r"(r[1]), "=r"(r[2]), "=r"(r[3]) : "r"(addr));
}
__device__ __forceinline__ uint32_t h2pack(float a, float b) {
    __half2 h = __floats2half2_rn(a, b);
    return *(uint32_t*)&h;
}

// ---------------- small kernels ----------------
// convert fp32 [K][N] weight -> half transposed [N][K]; grid.z = layer
__global__ void convT_kernel(const float* __restrict__ src, __half* __restrict__ dst,
                             int K, int N) {
    __shared__ float tile[32][33];
    const float* s = src + (size_t)blockIdx.z * K * N;
    __half* d = dst + (size_t)blockIdx.z * K * N;
    int tx = threadIdx.x, ty = threadIdx.y;
    int n0 = blockIdx.x * 32, k0 = blockIdx.y * 32;
#pragma unroll
    for (int i = 0; i < 32; i += 8)
        tile[ty + i][tx] = s[(size_t)(k0 + ty + i) * N + n0 + tx];
    __syncthreads();
#pragma unroll
    for (int i = 0; i < 32; i += 8)
        d[(size_t)(n0 + ty + i) * K + k0 + tx] = __float2half_rn(tile[tx][ty + i]);
}

// layernorm: one warp per row, float4 loads, shuffle-only reduction, no barriers.
// 256 threads = 8 rows/block; grid = MM/8.
__global__ __launch_bounds__(256)
void ln_kernel(const float* __restrict__ x, const float* __restrict__ g,
               const float* __restrict__ b, __half* __restrict__ out) {
    int lane = threadIdx.x & 31;
    int wrow = threadIdx.x >> 5;
    int row = blockIdx.x * 8 + wrow;
    const float* xr = x + (size_t)row * CC;

    float4 v[6];
    float s = 0.f, s2 = 0.f;
#pragma unroll
    for (int i = 0; i < 6; i++) {
        v[i] = *(const float4*)(xr + i * 128 + lane * 4);
        s  += v[i].x + v[i].y + v[i].z + v[i].w;
        s2 += v[i].x * v[i].x + v[i].y * v[i].y + v[i].z * v[i].z + v[i].w * v[i].w;
    }
#pragma unroll
    for (int o = 16; o; o >>= 1) {
        s  += __shfl_xor_sync(0xffffffffu, s,  o);
        s2 += __shfl_xor_sync(0xffffffffu, s2, o);
    }
    float mu  = s * (1.f / CC);
    float var = s2 * (1.f / CC) - mu * mu;
    float rs  = rsqrtf(var + EPS_LN);

    __half* outr = out + (size_t)row * CC;
#pragma unroll
    for (int i = 0; i < 6; i++) {
        int c = i * 128 + lane * 4;
        float4 gv = *(const float4*)(g + c);
        float4 bv = *(const float4*)(b + c);
        uint2 o2;
        o2.x = h2pack((v[i].x - mu) * rs * gv.x + bv.x, (v[i].y - mu) * rs * gv.y + bv.y);
        o2.y = h2pack((v[i].z - mu) * rs * gv.z + bv.z, (v[i].w - mu) * rs * gv.w + bv.w);
        *(uint2*)(outr + c) = o2;
    }
}

// ---------------- fp16 mma.sync GEMM, cp.async 4-stage, BK=32, ldsm A+B ----------------
#define EPI_BIAS  0
#define EPI_RESID 1
#define EPI_GELU  2

#define STAGES 4
#define BK 32
#define ASTR_H 40
#define BSTR_H 40
#define A_STG_H (128 * ASTR_H)
#define B_STG_H (128 * BSTR_H)
#define GEMM_SMEM_BYTES (STAGES * (A_STG_H + B_STG_H) * 2 + 512)   // 82,432 B

template <int EPI, typename OutT>
__device__ __forceinline__ void gemm_body(const __half* __restrict__ A, const __half* __restrict__ Wt,
                                          const float* __restrict__ bias, const float* __restrict__ resid,
                                          OutT* __restrict__ C, int Ndim, int Kdim,
                                          int bm, int bn, char* dsm) {
    __half* sA = (__half*)dsm;
    __half* sB = (__half*)dsm + STAGES * A_STG_H;
    float* sBias = (float*)(dsm + STAGES * (A_STG_H + B_STG_H) * 2);

    int tid = threadIdx.x;
    int lane = tid & 31;
    int wid = tid >> 5;

    if (tid < 128) sBias[tid] = bias[bn + tid];

    int lr = lane >> 2;
    int lc = lane & 3;
    int wm = (wid & 1) * 64;
    int wn = (wid >> 1) * 32;

    int idx0 = tid * 2, idx1 = tid * 2 + 1;
    int r0i = idx0 >> 2, s0i = (idx0 & 3) * 8;
    int r1i = idx1 >> 2, s1i = (idx1 & 3) * 8;

    uint32_t sA_base = smem_u32(sA);
    uint32_t sB_base = smem_u32(sB);
    uint32_t aFrag = sA_base + (uint32_t)((wm + (lane & 15)) * ASTR_H) * 2 + ((lane & 16) ? 16u : 0u);
    uint32_t bFrag = sB_base + (uint32_t)((wn + (lane & 7)) * BSTR_H) * 2 + (uint32_t)(lane >> 3) * 16u;

    const __half* aSrc0 = A + (size_t)(bm + r0i) * Kdim + s0i;
    const __half* aSrc1 = A + (size_t)(bm + r1i) * Kdim + s1i;
    const __half* bSrc0 = Wt + (size_t)(bn + r0i) * Kdim + s0i;
    const __half* bSrc1 = Wt + (size_t)(bn + r1i) * Kdim + s1i;

    float acc[4][4][4];
#pragma unroll
    for (int i = 0; i < 4; i++)
#pragma unroll
        for (int j = 0; j < 4; j++)
#pragma unroll
            for (int r = 0; r < 4; r++) acc[i][j][r] = 0.f;

    int nch = Kdim / BK;

    auto load_stage = [&](int stg, int chunk) {
        int k0 = chunk * BK;
        uint32_t ab = sA_base + (uint32_t)(stg * A_STG_H) * 2;
        uint32_t bb = sB_base + (uint32_t)(stg * B_STG_H) * 2;
        cp_async16(ab + (uint32_t)(r0i * ASTR_H + s0i) * 2, aSrc0 + k0);
        cp_async16(ab + (uint32_t)(r1i * ASTR_H + s1i) * 2, aSrc1 + k0);
        cp_async16(bb + (uint32_t)(r0i * BSTR_H + s0i) * 2, bSrc0 + k0);
        cp_async16(bb + (uint32_t)(r1i * BSTR_H + s1i) * 2, bSrc1 + k0);
    };

#pragma unroll
    for (int s = 0; s < STAGES - 1; s++) {
        if (s < nch) load_stage(s, s);
        CP_COMMIT();
    }
    cp_wait<STAGES - 2>();
    __syncthreads();

    for (int c = 0; c < nch; c++) {
        int buf = c % STAGES;
        int nc = c + STAGES - 1;
        if (nc < nch) load_stage(nc % STAGES, nc);
        CP_COMMIT();

        uint32_t aStage = aFrag + (uint32_t)(buf * A_STG_H) * 2;
        uint32_t bStage = bFrag + (uint32_t)(buf * B_STG_H) * 2;

        uint32_t bfr[4][4];
#pragma unroll
        for (int j = 0; j < 4; j++)
            ldsm_x4(bStage + (uint32_t)(j * 8 * BSTR_H) * 2, bfr[j]);

#pragma unroll
        for (int ks = 0; ks < 2; ks++) {
#pragma unroll
            for (int i = 0; i < 4; i++) {
                uint32_t a[4];
                ldsm_x4(aStage + (uint32_t)(i * 16 * ASTR_H) * 2 + ks * 32, a);
#pragma unroll
                for (int j = 0; j < 4; j++)
                    mma_f16(acc[i][j], a[0], a[1], a[2], a[3], bfr[j][2 * ks], bfr[j][2 * ks + 1]);
            }
        }
        cp_wait<STAGES - 2>();
        __syncthreads();
    }

#pragma unroll
    for (int i = 0; i < 4; i++) {
        int r0 = bm + wm + i * 16 + lr;
#pragma unroll
        for (int j = 0; j < 4; j++) {
            int colL = wn + j * 8 + lc * 2;
            int col = bn + colL;
            float v0 = acc[i][j][0] + sBias[colL];
            float v1 = acc[i][j][1] + sBias[colL + 1];
            float v2 = acc[i][j][2] + sBias[colL];
            float v3 = acc[i][j][3] + sBias[colL + 1];
            if (EPI == EPI_RESID) {
                float2 ra = *(const float2*)(resid + (size_t)r0 * Ndim + col);
                float2 rb = *(const float2*)(resid + (size_t)(r0 + 8) * Ndim + col);
                v0 += ra.x; v1 += ra.y; v2 += rb.x; v3 += rb.y;
            }
            if (EPI == EPI_GELU) {
                v0 = v0 * 0.5f * (1.0f + erff(v0 * 0.70710678118654752f));
                v1 = v1 * 0.5f * (1.0f + erff(v1 * 0.70710678118654752f));
                v2 = v2 * 0.5f * (1.0f + erff(v2 * 0.70710678118654752f));
                v3 = v3 * 0.5f * (1.0f + erff(v3 * 0.70710678118654752f));
            }
            if (sizeof(OutT) == 4) {
                *(float2*)((float*)C + (size_t)r0 * Ndim + col)       = make_float2(v0, v1);
                *(float2*)((float*)C + (size_t)(r0 + 8) * Ndim + col) = make_float2(v2, v3);
            } else {
                *(__half2*)((__half*)C + (size_t)r0 * Ndim + col)       = __floats2half2_rn(v0, v1);
                *(__half2*)((__half*)C + (size_t)(r0 + 8) * Ndim + col) = __floats2half2_rn(v2, v3);
            }
        }
    }
}

template <int EPI, typename OutT>
__global__ __launch_bounds__(256, 2)
void tc_gemm_kernel(const __half* __restrict__ A, const __half* __restrict__ Wt,
                    const float* __restrict__ bias, const float* __restrict__ resid,
                    OutT* __restrict__ C, int Ndim, int Kdim) {
    extern __shared__ char dsm[];
    gemm_body<EPI, OutT>(A, Wt, bias, resid, C, Ndim, Kdim, blockIdx.y * 128, blockIdx.x * 128, dsm);
}

__global__ __launch_bounds__(256, 2)
void qkv_gemm_kernel(const __half* __restrict__ A,
                     const __half* __restrict__ W0, const __half* __restrict__ W1, const __half* __restrict__ W2,
                     const float* __restrict__ b0, const float* __restrict__ b1, const float* __restrict__ b2,
                     __half* __restrict__ C0, __half* __restrict__ C1, __half* __restrict__ C2) {
    extern __shared__ char dsm[];
    const __half* W = (blockIdx.z == 0) ? W0 : (blockIdx.z == 1) ? W1 : W2;
    const float* bi = (blockIdx.z == 0) ? b0 : (blockIdx.z == 1) ? b1 : b2;
    __half* C = (blockIdx.z == 0) ? C0 : (blockIdx.z == 1) ? C1 : C2;
    gemm_body<EPI_BIAS, __half>(A, W, bi, nullptr, C, CC, CC, blockIdx.y * 128, blockIdx.x * 128, dsm);
}

// ---------------- fp16 tensor-core flash attention (ldsm everywhere, register P/m/l) ----------------
#define QSTR_H 72
#define KSTR_H 72
#define VSTR_H 72
#define ATT_Q_OFFH 0
#define ATT_K_OFFH (128 * QSTR_H)
#define ATT_V_OFFH (ATT_K_OFFH + 64 * KSTR_H)
#define ATT_HALVES (ATT_V_OFFH + 64 * VSTR_H)
#define ATTN_SMEM (ATT_HALVES * 2)          // 36,864 B

__global__ __launch_bounds__(256, 2)
void attn_tc_kernel(const __half* __restrict__ Q, const __half* __restrict__ K,
                    const __half* __restrict__ V, __half* __restrict__ Y) {
    extern __shared__ __half smh[];
    __half* Qs = smh + ATT_Q_OFFH;
    __half* Ks = smh + ATT_K_OFFH;
    __half* Vs = smh + ATT_V_OFFH;

    int tid = threadIdx.x;
    int lane = tid & 31;
    int wid = tid >> 5;
    int lr = lane >> 2;
    int lc = lane & 3;
    int wr = wid * 16;

    // heavy-tile-first scheduling
    int bx = blockIdx.x;
    int qb = (bx < 4) ? ((bx * 2 + 1) * 128) : ((bx - 4) * 2 * 128);
    int bh = blockIdx.y;
    int b = bh / NH, h = bh % NH;
    size_t base = (size_t)b * TT * CC + (size_t)h * HD;

    uint32_t qFrag = smem_u32(Qs) + (uint32_t)((wr + (lane & 15)) * QSTR_H) * 2 + ((lane & 16) ? 16u : 0u);
    uint32_t kFrag = smem_u32(Ks) + (uint32_t)((lane & 7) * KSTR_H) * 2 + (uint32_t)(lane >> 3) * 16u;
    uint32_t vFrag = smem_u32(Vs) + (uint32_t)(((lane & 7) + ((lane >> 3) & 1) * 8) * VSTR_H) * 2
                   + ((lane & 16) ? 16u : 0u);

    {
        const __half2 sc = __float2half2_rn(0.125f);
        for (int i = tid; i < 128 * 8; i += 256) {
            int row = i >> 3, cg = (i & 7) * 8;
            uint4 u = *(const uint4*)(Q + base + (size_t)(qb + row) * CC + cg);
            __half2* hp = (__half2*)&u;
            hp[0] = __hmul2(hp[0], sc); hp[1] = __hmul2(hp[1], sc);
            hp[2] = __hmul2(hp[2], sc); hp[3] = __hmul2(hp[3], sc);
            *(uint4*)(Qs + row * QSTR_H + cg) = u;
        }
    }

    float o[8][4];
#pragma unroll
    for (int j = 0; j < 8; j++)
#pragma unroll
        for (int r = 0; r < 4; r++) o[j][r] = 0.f;

    float m0r = -1e30f, m1r = -1e30f;
    float l0r = 0.f, l1r = 0.f;

    int qmod = qb & 255;
    int rm0 = qmod + wr + lr;
    int rm1 = rm0 + 8;

    for (int kb = 0; kb < TT; kb += 64) {
        int kbm = kb & 255;
        if (kbm > qmod + 127) continue;
        __syncthreads();
        for (int i = tid; i < 64 * 8; i += 256) {
            int row = i >> 3, cg = (i & 7) * 8;
            *(uint4*)(Ks + row * KSTR_H + cg) = *(const uint4*)(K + base + (size_t)(kb + row) * CC + cg);
            *(uint4*)(Vs + row * VSTR_H + cg) = *(const uint4*)(V + base + (size_t)(kb + row) * CC + cg);
        }
        __syncthreads();

        // ---- S = Q K^T ----
        float sacc[8][4];
#pragma unroll
        for (int j = 0; j < 8; j++)
#pragma unroll
            for (int r = 0; r < 4; r++) sacc[j][r] = 0.f;
#pragma unroll
        for (int kc = 0; kc < 2; kc++) {
            uint32_t bf[8][4];
#pragma unroll
            for (int j = 0; j < 8; j++)
                ldsm_x4(kFrag + (uint32_t)(j * 8 * KSTR_H) * 2 + kc * 64, bf[j]);
#pragma unroll
            for (int ksl = 0; ksl < 2; ksl++) {
                int ks = kc * 2 + ksl;
                uint32_t a[4];
                ldsm_x4(qFrag + ks * 32, a);
#pragma unroll
                for (int j = 0; j < 8; j++)
                    mma_f16(sacc[j], a[0], a[1], a[2], a[3], bf[j][2 * ksl], bf[j][2 * ksl + 1]);
            }
        }

        // ---- mask + online softmax ----
        float m0 = -1e30f, m1 = -1e30f;
#pragma unroll
        for (int j = 0; j < 8; j++) {
            int c0 = kbm + j * 8 + 2 * lc;
            if (c0 > rm0)     sacc[j][0] = -1e30f;
            if (c0 + 1 > rm0) sacc[j][1] = -1e30f;
            if (c0 > rm1)     sacc[j][2] = -1e30f;
            if (c0 + 1 > rm1) sacc[j][3] = -1e30f;
            m0 = fmaxf(m0, fmaxf(sacc[j][0], sacc[j][1]));
            m1 = fmaxf(m1, fmaxf(sacc[j][2], sacc[j][3]));
        }
        m0 = fmaxf(m0, __shfl_xor_sync(0xffffffffu, m0, 1));
        m0 = fmaxf(m0, __shfl_xor_sync(0xffffffffu, m0, 2));
        m1 = fmaxf(m1, __shfl_xor_sync(0xffffffffu, m1, 1));
        m1 = fmaxf(m1, __shfl_xor_sync(0xffffffffu, m1, 2));

        float mn0 = fmaxf(m0r, m0), mn1 = fmaxf(m1r, m1);
        float al0 = __expf(m0r - mn0), al1 = __expf(m1r - mn1);
        m0r = mn0; m1r = mn1;

        uint32_t pa[4][4];
        float sum0 = 0.f, sum1 = 0.f;
#pragma unroll
        for (int ks = 0; ks < 4; ks++) {
#pragma unroll
            for (int jj = 0; jj < 2; jj++) {
                int j = 2 * ks + jj;
                float p00 = __expf(sacc[j][0] - mn0);
                float p01 = __expf(sacc[j][1] - mn0);
                float p10 = __expf(sacc[j][2] - mn1);
                float p11 = __expf(sacc[j][3] - mn1);
                sum0 += p00 + p01;
                sum1 += p10 + p11;
                pa[ks][2 * jj]     = h2pack(p00, p01);
                pa[ks][2 * jj + 1] = h2pack(p10, p11);
            }
        }
        sum0 += __shfl_xor_sync(0xffffffffu, sum0, 1);
        sum0 += __shfl_xor_sync(0xffffffffu, sum0, 2);
        sum1 += __shfl_xor_sync(0xffffffffu, sum1, 1);
        sum1 += __shfl_xor_sync(0xffffffffu, sum1, 2);
        l0r = l0r * al0 + sum0;
        l1r = l1r * al1 + sum1;

#pragma unroll
        for (int j = 0; j < 8; j++) {
            o[j][0] *= al0; o[j][1] *= al0; o[j][2] *= al1; o[j][3] *= al1;
        }

        // ---- O += P V ----
#pragma unroll
        for (int ks = 0; ks < 4; ks++) {
#pragma unroll
            for (int j2 = 0; j2 < 4; j2++) {
                uint32_t bv[4];
                ldsm_x4_trans(vFrag + (uint32_t)(ks * 16 * VSTR_H) * 2 + j2 * 32, bv);
                mma_f16(o[2 * j2],     pa[ks][0], pa[ks][1], pa[ks][2], pa[ks][3], bv[0], bv[1]);
                mma_f16(o[2 * j2 + 1], pa[ks][0], pa[ks][1], pa[ks][2], pa[ks][3], bv[2], bv[3]);
            }
        }
    }

    int r0 = wr + lr, r1 = r0 + 8;
    float inv0 = 1.0f / l0r;
    float inv1 = 1.0f / l1r;
#pragma unroll
    for (int j = 0; j < 8; j++) {
        int d = j * 8 + 2 * lc;
        *(__half2*)(Y + base + (size_t)(qb + r0) * CC + d) =
            __floats2half2_rn(o[j][0] * inv0, o[j][1] * inv0);
        *(__half2*)(Y + base + (size_t)(qb + r1) * CC + d) =
            __floats2half2_rn(o[j][2] * inv1, o[j][3] * inv1);
    }
}

// ---------------- host orchestration ----------------
extern "C" void kernel_launch(void* const* d_in, const int* in_sizes, int n_in,
                              void* d_out, int out_size) {
    const float* x     = (const float*)d_in[0];
    const float* ln1_g = (const float*)d_in[1];
    const float* ln1_b = (const float*)d_in[2];
    const float* Wq    = (const float*)d_in[3];
    const float* bq    = (const float*)d_in[4];
    const float* Wk    = (const float*)d_in[5];
    const float* bk    = (const float*)d_in[6];
    const float* Wv    = (const float*)d_in[7];
    const float* bv    = (const float*)d_in[8];
    const float* Wp    = (const float*)d_in[9];
    const float* bp    = (const float*)d_in[10];
    const float* ln2_g = (const float*)d_in[11];
    const float* ln2_b = (const float*)d_in[12];
    const float* W1    = (const float*)d_in[13];
    const float* b1    = (const float*)d_in[14];
    const float* W2    = (const float*)d_in[15];
    const float* b2    = (const float*)d_in[16];

    float* res;
    __half *ln, *q, *k, *v, *y, *h1, *wt;
    cudaGetSymbolAddress((void**)&res, g_res);
    cudaGetSymbolAddress((void**)&ln,  g_ln);
    cudaGetSymbolAddress((void**)&q,   g_q);
    cudaGetSymbolAddress((void**)&k,   g_k);
    cudaGetSymbolAddress((void**)&v,   g_v);
    cudaGetSymbolAddress((void**)&y,   g_y);
    cudaGetSymbolAddress((void**)&h1,  g_h1);
    cudaGetSymbolAddress((void**)&wt,  g_wt);

    cudaFuncSetAttribute(attn_tc_kernel, cudaFuncAttributeMaxDynamicSharedMemorySize, ATTN_SMEM);
    cudaFuncSetAttribute(tc_gemm_kernel<EPI_RESID, float>,  cudaFuncAttributeMaxDynamicSharedMemorySize, GEMM_SMEM_BYTES);
    cudaFuncSetAttribute(tc_gemm_kernel<EPI_GELU, __half>,  cudaFuncAttributeMaxDynamicSharedMemorySize, GEMM_SMEM_BYTES);
    cudaFuncSetAttribute(qkv_gemm_kernel,                   cudaFuncAttributeMaxDynamicSharedMemorySize, GEMM_SMEM_BYTES);

    // ---- convert + transpose weights to half [N][K] ----
    {
        dim3 tb(32, 8);
        convT_kernel<<<dim3(CC/32,  CC/32,  LNUM), tb>>>(Wq, wt + WQ_OFF, CC, CC);
        convT_kernel<<<dim3(CC/32,  CC/32,  LNUM), tb>>>(Wk, wt + WK_OFF, CC, CC);
        convT_kernel<<<dim3(CC/32,  CC/32,  LNUM), tb>>>(Wv, wt + WV_OFF, CC, CC);
        convT_kernel<<<dim3(CC/32,  CC/32,  LNUM), tb>>>(Wp, wt + WP_OFF, CC, CC);
        convT_kernel<<<dim3(HID/32, CC/32,  LNUM), tb>>>(W1, wt + W1_OFF, CC, HID);
        convT_kernel<<<dim3(CC/32,  HID/32, LNUM), tb>>>(W2, wt + W2_OFF, HID, CC);
    }

    dim3 gemm_qkv3(CC / 128, MM / 128, 3);   // 576
    dim3 gemm_c  (CC / 128, MM / 128);       // 192
    dim3 gemm_h  (HID / 128, MM / 128);      // 768
    dim3 attn_grid(TT / 128, BB * NH);       // 384

    for (int l = 0; l < LNUM; l++) {
        const __half* wq = wt + WQ_OFF + (size_t)l * CC * CC;
        const __half* wk = wt + WK_OFF + (size_t)l * CC * CC;
        const __half* wv = wt + WV_OFF + (size_t)l * CC * CC;
        const __half* wp = wt + WP_OFF + (size_t)l * CC * CC;
        const __half* w1 = wt + W1_OFF + (size_t)l * CC * HID;
        const __half* w2 = wt + W2_OFF + (size_t)l * HID * CC;

        const float* resIn = (l == 0) ? x : res;

        ln_kernel<<<MM / 8, 256>>>(resIn, ln1_g + (size_t)l*CC, ln1_b + (size_t)l*CC, ln);
        qkv_gemm_kernel<<<gemm_qkv3, 256, GEMM_SMEM_BYTES>>>(
            ln, wq, wk, wv, bq + (size_t)l*CC, bk + (size_t)l*CC, bv + (size_t)l*CC, q, k, v);
        attn_tc_kernel<<<attn_grid, 256, ATTN_SMEM>>>(q, k, v, y);
        tc_gemm_kernel<EPI_RESID, float><<<gemm_c, 256, GEMM_SMEM_BYTES>>>(
            y, wp, bp + (size_t)l*CC, resIn, res, CC, CC);
        ln_kernel<<<MM / 8, 256>>>(res, ln2_g + (size_t)l*CC, ln2_b + (size_t)l*CC, ln);
        tc_gemm_kernel<EPI_GELU, __half><<<gemm_h, 256, GEMM_SMEM_BYTES>>>(
            ln, w1, b1 + (size_t)l*HID, nullptr, h1, HID, CC);
        float* outC = (l == LNUM - 1) ? (float*)d_out : res;
        tc_gemm_kernel<EPI_RESID, float><<<gemm_c, 256, GEMM_SMEM_BYTES>>>(
            h1, w2, b2 + (size_t)l*CC, res, outC, CC, HID);
    }
}

// round 14
// speedup vs baseline: 2.0696x; 1.0929x over previous
#include <cuda_runtime.h>
#include <cuda_fp16.h>
#include <math.h>
#include <cstdint>

// ---------------- problem constants ----------------
#define LNUM 4
#define BB   4
#define TT   1024
#define CC   768
#define NH   12
#define HD   64
#define HID  3072
#define MM   (BB*TT)          // 4096 rows
#define EPS_LN 1e-5f

// ---------------- scratch (device globals; no allocation allowed) ----------------
__device__ float  g_res [(size_t)MM*CC];
__device__ __half g_ln  [(size_t)MM*CC];
__device__ __half g_q   [(size_t)MM*CC];
__device__ __half g_k   [(size_t)MM*CC];
__device__ __half g_v   [(size_t)MM*CC];
__device__ __half g_y   [(size_t)MM*CC];
__device__ __half g_h1  [(size_t)MM*HID];
__device__ float  g_part[3 * (size_t)MM*CC];   // split-K partials for W2
// half, transposed [N][K] weights
#define WQ_OFF 0
#define WK_OFF (WQ_OFF + (size_t)LNUM*CC*CC)
#define WV_OFF (WK_OFF + (size_t)LNUM*CC*CC)
#define WP_OFF (WV_OFF + (size_t)LNUM*CC*CC)
#define W1_OFF (WP_OFF + (size_t)LNUM*CC*CC)
#define W2_OFF (W1_OFF + (size_t)LNUM*CC*HID)
#define WT_TOTAL (W2_OFF + (size_t)LNUM*CC*HID)
__device__ __half g_wt [WT_TOTAL];

// ---------------- helpers ----------------
__device__ __forceinline__ uint32_t smem_u32(const void* p) {
    uint32_t a;
    asm("{ .reg .u64 t; cvta.to.shared.u64 t, %1; cvt.u32.u64 %0, t; }" : "=r"(a) : "l"(p));
    return a;
}
__device__ __forceinline__ void cp_async16(uint32_t dst, const void* src) {
    asm volatile("cp.async.cg.shared.global [%0], [%1], 16;" :: "r"(dst), "l"(src));
}
#define CP_COMMIT() asm volatile("cp.async.commit_group;" ::: "memory")
template <int N>
__device__ __forceinline__ void cp_wait() {
    asm volatile("cp.async.wait_group %0;" :: "n"(N) : "memory");
}
__device__ __forceinline__ void mma_f16(float* d, uint32_t a0, uint32_t a1, uint32_t a2,
                                        uint32_t a3, uint32_t b0, uint32_t b1) {
    asm volatile(
        "mma.sync.aligned.m16n8k16.row.col.f32.f16.f16.f32 "
        "{%0,%1,%2,%3}, {%4,%5,%6,%7}, {%8,%9}, {%0,%1,%2,%3};"
        : "+f"(d[0]), "+f"(d[1]), "+f"(d[2]), "+f"(d[3])
        : "r"(a0), "r"(a1), "r"(a2), "r"(a3), "r"(b0), "r"(b1));
}
__device__ __forceinline__ void ldsm_x4(uint32_t addr, uint32_t* r) {
    asm volatile("ldmatrix.sync.aligned.m8n8.x4.shared.b16 {%0,%1,%2,%3}, [%4];"
        : "=r"(r[0]), "=r"(r[1]), "=r"(r[2]), "=r"(r[3]) : "r"(addr));
}
__device__ __forceinline__ void ldsm_x4_trans(uint32_t addr, uint32_t* r) {
    asm volatile("ldmatrix.sync.aligned.m8n8.x4.trans.shared.b16 {%0,%1,%2,%3}, [%4];"
        : "=r"(r[0]), "=r"(r[1]), "=r"(r[2]), "=r"(r[3]) : "r"(addr));
}
__device__ __forceinline__ uint32_t h2pack(float a, float b) {
    __half2 h = __floats2half2_rn(a, b);
    return *(uint32_t*)&h;
}

// ---------------- small kernels ----------------
// convert fp32 [K][N] weight -> half transposed [N][K]; grid.z = layer
__global__ void convT_kernel(const float* __restrict__ src, __half* __restrict__ dst,
                             int K, int N) {
    __shared__ float tile[32][33];
    const float* s = src + (size_t)blockIdx.z * K * N;
    __half* d = dst + (size_t)blockIdx.z * K * N;
    int tx = threadIdx.x, ty = threadIdx.y;
    int n0 = blockIdx.x * 32, k0 = blockIdx.y * 32;
#pragma unroll
    for (int i = 0; i < 32; i += 8)
        tile[ty + i][tx] = s[(size_t)(k0 + ty + i) * N + n0 + tx];
    __syncthreads();
#pragma unroll
    for (int i = 0; i < 32; i += 8)
        d[(size_t)(n0 + ty + i) * K + k0 + tx] = __float2half_rn(tile[tx][ty + i]);
}

// layernorm: one warp per row, float4 loads, shuffle-only reduction.
__global__ __launch_bounds__(256)
void ln_kernel(const float* __restrict__ x, const float* __restrict__ g,
               const float* __restrict__ b, __half* __restrict__ out) {
    int lane = threadIdx.x & 31;
    int wrow = threadIdx.x >> 5;
    int row = blockIdx.x * 8 + wrow;
    const float* xr = x + (size_t)row * CC;

    float4 v[6];
    float s = 0.f, s2 = 0.f;
#pragma unroll
    for (int i = 0; i < 6; i++) {
        v[i] = *(const float4*)(xr + i * 128 + lane * 4);
        s  += v[i].x + v[i].y + v[i].z + v[i].w;
        s2 += v[i].x * v[i].x + v[i].y * v[i].y + v[i].z * v[i].z + v[i].w * v[i].w;
    }
#pragma unroll
    for (int o = 16; o; o >>= 1) {
        s  += __shfl_xor_sync(0xffffffffu, s,  o);
        s2 += __shfl_xor_sync(0xffffffffu, s2, o);
    }
    float mu  = s * (1.f / CC);
    float var = s2 * (1.f / CC) - mu * mu;
    float rs  = rsqrtf(var + EPS_LN);

    __half* outr = out + (size_t)row * CC;
#pragma unroll
    for (int i = 0; i < 6; i++) {
        int c = i * 128 + lane * 4;
        float4 gv = *(const float4*)(g + c);
        float4 bv = *(const float4*)(b + c);
        uint2 o2;
        o2.x = h2pack((v[i].x - mu) * rs * gv.x + bv.x, (v[i].y - mu) * rs * gv.y + bv.y);
        o2.y = h2pack((v[i].z - mu) * rs * gv.z + bv.z, (v[i].w - mu) * rs * gv.w + bv.w);
        *(uint2*)(outr + c) = o2;
    }
}

// fused: res = p0+p1+p2 + bias + res (in place), then LN(res) -> out (half)
__global__ __launch_bounds__(256)
void ln_reduce_kernel(const float* __restrict__ p, const float* __restrict__ bias,
                      float* __restrict__ res,
                      const float* __restrict__ g, const float* __restrict__ b,
                      __half* __restrict__ out) {
    int lane = threadIdx.x & 31;
    int wrow = threadIdx.x >> 5;
    int row = blockIdx.x * 8 + wrow;
    size_t roff = (size_t)row * CC;
    const float* p0 = p + roff;
    const float* p1 = p + (size_t)MM * CC + roff;
    const float* p2 = p + 2 * (size_t)MM * CC + roff;
    float* rr = res + roff;

    float4 v[6];
    float s = 0.f, s2 = 0.f;
#pragma unroll
    for (int i = 0; i < 6; i++) {
        int c = i * 128 + lane * 4;
        float4 a0 = *(const float4*)(p0 + c);
        float4 a1 = *(const float4*)(p1 + c);
        float4 a2 = *(const float4*)(p2 + c);
        float4 rv = *(const float4*)(rr + c);
        float4 bb = *(const float4*)(bias + c);
        v[i].x = a0.x + a1.x + a2.x + bb.x + rv.x;
        v[i].y = a0.y + a1.y + a2.y + bb.y + rv.y;
        v[i].z = a0.z + a1.z + a2.z + bb.z + rv.z;
        v[i].w = a0.w + a1.w + a2.w + bb.w + rv.w;
        *(float4*)(rr + c) = v[i];
        s  += v[i].x + v[i].y + v[i].z + v[i].w;
        s2 += v[i].x * v[i].x + v[i].y * v[i].y + v[i].z * v[i].z + v[i].w * v[i].w;
    }
#pragma unroll
    for (int o = 16; o; o >>= 1) {
        s  += __shfl_xor_sync(0xffffffffu, s,  o);
        s2 += __shfl_xor_sync(0xffffffffu, s2, o);
    }
    float mu  = s * (1.f / CC);
    float var = s2 * (1.f / CC) - mu * mu;
    float rs  = rsqrtf(var + EPS_LN);

    __half* outr = out + roff;
#pragma unroll
    for (int i = 0; i < 6; i++) {
        int c = i * 128 + lane * 4;
        float4 gv = *(const float4*)(g + c);
        float4 bv = *(const float4*)(b + c);
        uint2 o2;
        o2.x = h2pack((v[i].x - mu) * rs * gv.x + bv.x, (v[i].y - mu) * rs * gv.y + bv.y);
        o2.y = h2pack((v[i].z - mu) * rs * gv.z + bv.z, (v[i].w - mu) * rs * gv.w + bv.w);
        *(uint2*)(outr + c) = o2;
    }
}

// final-layer reduce: out = p0+p1+p2 + bias + res
__global__ void reduce_out_kernel(const float* __restrict__ p, const float* __restrict__ bias,
                                  const float* __restrict__ res, float* __restrict__ out) {
    int i = blockIdx.x * blockDim.x + threadIdx.x;
    int n4 = MM * CC / 4;
    if (i >= n4) return;
    int c4 = i % (CC / 4);
    float4 a0 = ((const float4*)p)[i];
    float4 a1 = ((const float4*)(p + (size_t)MM * CC))[i];
    float4 a2 = ((const float4*)(p + 2 * (size_t)MM * CC))[i];
    float4 rv = ((const float4*)res)[i];
    float4 bb = ((const float4*)bias)[c4];
    float4 o;
    o.x = a0.x + a1.x + a2.x + rv.x + bb.x;
    o.y = a0.y + a1.y + a2.y + rv.y + bb.y;
    o.z = a0.z + a1.z + a2.z + rv.z + bb.z;
    o.w = a0.w + a1.w + a2.w + rv.w + bb.w;
    ((float4*)out)[i] = o;
}

// ---------------- fp16 mma.sync GEMM, cp.async 4-stage, BK=32, ldsm A+B ----------------
#define EPI_BIAS  0
#define EPI_RESID 1
#define EPI_GELU  2
#define EPI_NONE  3

#define STAGES 4
#define BK 32
#define ASTR_H 40
#define BSTR_H 40
#define A_STG_H (128 * ASTR_H)
#define B_STG_H (128 * BSTR_H)
#define GEMM_SMEM_BYTES (STAGES * (A_STG_H + B_STG_H) * 2 + 512)   // 82,432 B

template <int EPI, typename OutT>
__device__ __forceinline__ void gemm_body(const __half* __restrict__ A, const __half* __restrict__ Wt,
                                          const float* __restrict__ bias, const float* __restrict__ resid,
                                          OutT* __restrict__ C, int Ndim, int Kstride, int Klen,
                                          int bm, int bn, char* dsm) {
    __half* sA = (__half*)dsm;
    __half* sB = (__half*)dsm + STAGES * A_STG_H;
    float* sBias = (float*)(dsm + STAGES * (A_STG_H + B_STG_H) * 2);

    int tid = threadIdx.x;
    int lane = tid & 31;
    int wid = tid >> 5;

    if (EPI != EPI_NONE && tid < 128) sBias[tid] = bias[bn + tid];

    int lr = lane >> 2;
    int lc = lane & 3;
    int wm = (wid & 1) * 64;
    int wn = (wid >> 1) * 32;

    int idx0 = tid * 2, idx1 = tid * 2 + 1;
    int r0i = idx0 >> 2, s0i = (idx0 & 3) * 8;
    int r1i = idx1 >> 2, s1i = (idx1 & 3) * 8;

    uint32_t sA_base = smem_u32(sA);
    uint32_t sB_base = smem_u32(sB);
    uint32_t aFrag = sA_base + (uint32_t)((wm + (lane & 15)) * ASTR_H) * 2 + ((lane & 16) ? 16u : 0u);
    uint32_t bFrag = sB_base + (uint32_t)((wn + (lane & 7)) * BSTR_H) * 2 + (uint32_t)(lane >> 3) * 16u;

    const __half* aSrc0 = A + (size_t)(bm + r0i) * Kstride + s0i;
    const __half* aSrc1 = A + (size_t)(bm + r1i) * Kstride + s1i;
    const __half* bSrc0 = Wt + (size_t)(bn + r0i) * Kstride + s0i;
    const __half* bSrc1 = Wt + (size_t)(bn + r1i) * Kstride + s1i;

    float acc[4][4][4];
#pragma unroll
    for (int i = 0; i < 4; i++)
#pragma unroll
        for (int j = 0; j < 4; j++)
#pragma unroll
            for (int r = 0; r < 4; r++) acc[i][j][r] = 0.f;

    int nch = Klen / BK;

    auto load_stage = [&](int stg, int chunk) {
        int k0 = chunk * BK;
        uint32_t ab = sA_base + (uint32_t)(stg * A_STG_H) * 2;
        uint32_t bb = sB_base + (uint32_t)(stg * B_STG_H) * 2;
        cp_async16(ab + (uint32_t)(r0i * ASTR_H + s0i) * 2, aSrc0 + k0);
        cp_async16(ab + (uint32_t)(r1i * ASTR_H + s1i) * 2, aSrc1 + k0);
        cp_async16(bb + (uint32_t)(r0i * BSTR_H + s0i) * 2, bSrc0 + k0);
        cp_async16(bb + (uint32_t)(r1i * BSTR_H + s1i) * 2, bSrc1 + k0);
    };

#pragma unroll
    for (int s = 0; s < STAGES - 1; s++) {
        if (s < nch) load_stage(s, s);
        CP_COMMIT();
    }
    cp_wait<STAGES - 2>();
    __syncthreads();

    for (int c = 0; c < nch; c++) {
        int buf = c % STAGES;
        int nc = c + STAGES - 1;
        if (nc < nch) load_stage(nc % STAGES, nc);
        CP_COMMIT();

        uint32_t aStage = aFrag + (uint32_t)(buf * A_STG_H) * 2;
        uint32_t bStage = bFrag + (uint32_t)(buf * B_STG_H) * 2;

        uint32_t bfr[4][4];
#pragma unroll
        for (int j = 0; j < 4; j++)
            ldsm_x4(bStage + (uint32_t)(j * 8 * BSTR_H) * 2, bfr[j]);

#pragma unroll
        for (int ks = 0; ks < 2; ks++) {
#pragma unroll
            for (int i = 0; i < 4; i++) {
                uint32_t a[4];
                ldsm_x4(aStage + (uint32_t)(i * 16 * ASTR_H) * 2 + ks * 32, a);
#pragma unroll
                for (int j = 0; j < 4; j++)
                    mma_f16(acc[i][j], a[0], a[1], a[2], a[3], bfr[j][2 * ks], bfr[j][2 * ks + 1]);
            }
        }
        cp_wait<STAGES - 2>();
        __syncthreads();
    }

#pragma unroll
    for (int i = 0; i < 4; i++) {
        int r0 = bm + wm + i * 16 + lr;
#pragma unroll
        for (int j = 0; j < 4; j++) {
            int colL = wn + j * 8 + lc * 2;
            int col = bn + colL;
            float v0 = acc[i][j][0];
            float v1 = acc[i][j][1];
            float v2 = acc[i][j][2];
            float v3 = acc[i][j][3];
            if (EPI != EPI_NONE) {
                v0 += sBias[colL]; v1 += sBias[colL + 1];
                v2 += sBias[colL]; v3 += sBias[colL + 1];
            }
            if (EPI == EPI_RESID) {
                float2 ra = *(const float2*)(resid + (size_t)r0 * Ndim + col);
                float2 rb = *(const float2*)(resid + (size_t)(r0 + 8) * Ndim + col);
                v0 += ra.x; v1 += ra.y; v2 += rb.x; v3 += rb.y;
            }
            if (EPI == EPI_GELU) {
                v0 = v0 * 0.5f * (1.0f + erff(v0 * 0.70710678118654752f));
                v1 = v1 * 0.5f * (1.0f + erff(v1 * 0.70710678118654752f));
                v2 = v2 * 0.5f * (1.0f + erff(v2 * 0.70710678118654752f));
                v3 = v3 * 0.5f * (1.0f + erff(v3 * 0.70710678118654752f));
            }
            if (sizeof(OutT) == 4) {
                *(float2*)((float*)C + (size_t)r0 * Ndim + col)       = make_float2(v0, v1);
                *(float2*)((float*)C + (size_t)(r0 + 8) * Ndim + col) = make_float2(v2, v3);
            } else {
                *(__half2*)((__half*)C + (size_t)r0 * Ndim + col)       = __floats2half2_rn(v0, v1);
                *(__half2*)((__half*)C + (size_t)(r0 + 8) * Ndim + col) = __floats2half2_rn(v2, v3);
            }
        }
    }
}

template <int EPI, typename OutT>
__global__ __launch_bounds__(256, 2)
void tc_gemm_kernel(const __half* __restrict__ A, const __half* __restrict__ Wt,
                    const float* __restrict__ bias, const float* __restrict__ resid,
                    OutT* __restrict__ C, int Ndim, int Kdim) {
    extern __shared__ char dsm[];
    gemm_body<EPI, OutT>(A, Wt, bias, resid, C, Ndim, Kdim, Kdim,
                         blockIdx.y * 128, blockIdx.x * 128, dsm);
}

__global__ __launch_bounds__(256, 2)
void qkv_gemm_kernel(const __half* __restrict__ A,
                     const __half* __restrict__ W0, const __half* __restrict__ W1, const __half* __restrict__ W2,
                     const float* __restrict__ b0, const float* __restrict__ b1, const float* __restrict__ b2,
                     __half* __restrict__ C0, __half* __restrict__ C1, __half* __restrict__ C2) {
    extern __shared__ char dsm[];
    const __half* W = (blockIdx.z == 0) ? W0 : (blockIdx.z == 1) ? W1 : W2;
    const float* bi = (blockIdx.z == 0) ? b0 : (blockIdx.z == 1) ? b1 : b2;
    __half* C = (blockIdx.z == 0) ? C0 : (blockIdx.z == 1) ? C1 : C2;
    gemm_body<EPI_BIAS, __half>(A, W, bi, nullptr, C, CC, CC, CC,
                                blockIdx.y * 128, blockIdx.x * 128, dsm);
}

// W2 split-K: grid (6, 32, 3); slice z covers K in [z*1024, (z+1)*1024)
__global__ __launch_bounds__(256, 2)
void w2_splitk_kernel(const __half* __restrict__ A, const __half* __restrict__ Wt,
                      float* __restrict__ part) {
    extern __shared__ char dsm[];
    int z = blockIdx.z;
    gemm_body<EPI_NONE, float>(A + z * (HID / 3), Wt + z * (HID / 3), nullptr, nullptr,
                               part + (size_t)z * MM * CC, CC, HID, HID / 3,
                               blockIdx.y * 128, blockIdx.x * 128, dsm);
}

// ---------------- fp16 tensor-core flash attention ----------------
#define QSTR_H 72
#define KSTR_H 72
#define VSTR_H 72
#define ATT_Q_OFFH 0
#define ATT_K_OFFH (128 * QSTR_H)
#define ATT_V_OFFH (ATT_K_OFFH + 64 * KSTR_H)
#define ATT_HALVES (ATT_V_OFFH + 64 * VSTR_H)
#define ATTN_SMEM (ATT_HALVES * 2)          // 36,864 B

__global__ __launch_bounds__(256, 2)
void attn_tc_kernel(const __half* __restrict__ Q, const __half* __restrict__ K,
                    const __half* __restrict__ V, __half* __restrict__ Y) {
    extern __shared__ __half smh[];
    __half* Qs = smh + ATT_Q_OFFH;
    __half* Ks = smh + ATT_K_OFFH;
    __half* Vs = smh + ATT_V_OFFH;

    int tid = threadIdx.x;
    int lane = tid & 31;
    int wid = tid >> 5;
    int lr = lane >> 2;
    int lc = lane & 3;
    int wr = wid * 16;

    int bx = blockIdx.x;
    int qb = (bx < 4) ? ((bx * 2 + 1) * 128) : ((bx - 4) * 2 * 128);
    int bh = blockIdx.y;
    int b = bh / NH, h = bh % NH;
    size_t base = (size_t)b * TT * CC + (size_t)h * HD;

    uint32_t qFrag = smem_u32(Qs) + (uint32_t)((wr + (lane & 15)) * QSTR_H) * 2 + ((lane & 16) ? 16u : 0u);
    uint32_t kFrag = smem_u32(Ks) + (uint32_t)((lane & 7) * KSTR_H) * 2 + (uint32_t)(lane >> 3) * 16u;
    uint32_t vFrag = smem_u32(Vs) + (uint32_t)(((lane & 7) + ((lane >> 3) & 1) * 8) * VSTR_H) * 2
                   + ((lane & 16) ? 16u : 0u);

    {
        const __half2 sc = __float2half2_rn(0.125f);
        for (int i = tid; i < 128 * 8; i += 256) {
            int row = i >> 3, cg = (i & 7) * 8;
            uint4 u = *(const uint4*)(Q + base + (size_t)(qb + row) * CC + cg);
            __half2* hp = (__half2*)&u;
            hp[0] = __hmul2(hp[0], sc); hp[1] = __hmul2(hp[1], sc);
            hp[2] = __hmul2(hp[2], sc); hp[3] = __hmul2(hp[3], sc);
            *(uint4*)(Qs + row * QSTR_H + cg) = u;
        }
    }

    float o[8][4];
#pragma unroll
    for (int j = 0; j < 8; j++)
#pragma unroll
        for (int r = 0; r < 4; r++) o[j][r] = 0.f;

    float m0r = -1e30f, m1r = -1e30f;
    float l0r = 0.f, l1r = 0.f;

    int qmod = qb & 255;
    int rm0 = qmod + wr + lr;
    int rm1 = rm0 + 8;

    for (int kb = 0; kb < TT; kb += 64) {
        int kbm = kb & 255;
        if (kbm > qmod + 127) continue;
        __syncthreads();
        for (int i = tid; i < 64 * 8; i += 256) {
            int row = i >> 3, cg = (i & 7) * 8;
            *(uint4*)(Ks + row * KSTR_H + cg) = *(const uint4*)(K + base + (size_t)(kb + row) * CC + cg);
            *(uint4*)(Vs + row * VSTR_H + cg) = *(const uint4*)(V + base + (size_t)(kb + row) * CC + cg);
        }
        __syncthreads();

        float sacc[8][4];
#pragma unroll
        for (int j = 0; j < 8; j++)
#pragma unroll
            for (int r = 0; r < 4; r++) sacc[j][r] = 0.f;
#pragma unroll
        for (int kc = 0; kc < 2; kc++) {
            uint32_t bf[8][4];
#pragma unroll
            for (int j = 0; j < 8; j++)
                ldsm_x4(kFrag + (uint32_t)(j * 8 * KSTR_H) * 2 + kc * 64, bf[j]);
#pragma unroll
            for (int ksl = 0; ksl < 2; ksl++) {
                int ks = kc * 2 + ksl;
                uint32_t a[4];
                ldsm_x4(qFrag + ks * 32, a);
#pragma unroll
                for (int j = 0; j < 8; j++)
                    mma_f16(sacc[j], a[0], a[1], a[2], a[3], bf[j][2 * ksl], bf[j][2 * ksl + 1]);
            }
        }

        float m0 = -1e30f, m1 = -1e30f;
#pragma unroll
        for (int j = 0; j < 8; j++) {
            int c0 = kbm + j * 8 + 2 * lc;
            if (c0 > rm0)     sacc[j][0] = -1e30f;
            if (c0 + 1 > rm0) sacc[j][1] = -1e30f;
            if (c0 > rm1)     sacc[j][2] = -1e30f;
            if (c0 + 1 > rm1) sacc[j][3] = -1e30f;
            m0 = fmaxf(m0, fmaxf(sacc[j][0], sacc[j][1]));
            m1 = fmaxf(m1, fmaxf(sacc[j][2], sacc[j][3]));
        }
        m0 = fmaxf(m0, __shfl_xor_sync(0xffffffffu, m0, 1));
        m0 = fmaxf(m0, __shfl_xor_sync(0xffffffffu, m0, 2));
        m1 = fmaxf(m1, __shfl_xor_sync(0xffffffffu, m1, 1));
        m1 = fmaxf(m1, __shfl_xor_sync(0xffffffffu, m1, 2));

        float mn0 = fmaxf(m0r, m0), mn1 = fmaxf(m1r, m1);
        float al0 = __expf(m0r - mn0), al1 = __expf(m1r - mn1);
        m0r = mn0; m1r = mn1;

        uint32_t pa[4][4];
        float sum0 = 0.f, sum1 = 0.f;
#pragma unroll
        for (int ks = 0; ks < 4; ks++) {
#pragma unroll
            for (int jj = 0; jj < 2; jj++) {
                int j = 2 * ks + jj;
                float p00 = __expf(sacc[j][0] - mn0);
                float p01 = __expf(sacc[j][1] - mn0);
                float p10 = __expf(sacc[j][2] - mn1);
                float p11 = __expf(sacc[j][3] - mn1);
                sum0 += p00 + p01;
                sum1 += p10 + p11;
                pa[ks][2 * jj]     = h2pack(p00, p01);
                pa[ks][2 * jj + 1] = h2pack(p10, p11);
            }
        }
        sum0 += __shfl_xor_sync(0xffffffffu, sum0, 1);
        sum0 += __shfl_xor_sync(0xffffffffu, sum0, 2);
        sum1 += __shfl_xor_sync(0xffffffffu, sum1, 1);
        sum1 += __shfl_xor_sync(0xffffffffu, sum1, 2);
        l0r = l0r * al0 + sum0;
        l1r = l1r * al1 + sum1;

#pragma unroll
        for (int j = 0; j < 8; j++) {
            o[j][0] *= al0; o[j][1] *= al0; o[j][2] *= al1; o[j][3] *= al1;
        }

#pragma unroll
        for (int ks = 0; ks < 4; ks++) {
#pragma unroll
            for (int j2 = 0; j2 < 4; j2++) {
                uint32_t bv[4];
                ldsm_x4_trans(vFrag + (uint32_t)(ks * 16 * VSTR_H) * 2 + j2 * 32, bv);
                mma_f16(o[2 * j2],     pa[ks][0], pa[ks][1], pa[ks][2], pa[ks][3], bv[0], bv[1]);
                mma_f16(o[2 * j2 + 1], pa[ks][0], pa[ks][1], pa[ks][2], pa[ks][3], bv[2], bv[3]);
            }
        }
    }

    int r0 = wr + lr, r1 = r0 + 8;
    float inv0 = 1.0f / l0r;
    float inv1 = 1.0f / l1r;
#pragma unroll
    for (int j = 0; j < 8; j++) {
        int d = j * 8 + 2 * lc;
        *(__half2*)(Y + base + (size_t)(qb + r0) * CC + d) =
            __floats2half2_rn(o[j][0] * inv0, o[j][1] * inv0);
        *(__half2*)(Y + base + (size_t)(qb + r1) * CC + d) =
            __floats2half2_rn(o[j][2] * inv1, o[j][3] * inv1);
    }
}

// ---------------- host orchestration ----------------
extern "C" void kernel_launch(void* const* d_in, const int* in_sizes, int n_in,
                              void* d_out, int out_size) {
    const float* x     = (const float*)d_in[0];
    const float* ln1_g = (const float*)d_in[1];
    const float* ln1_b = (const float*)d_in[2];
    const float* Wq    = (const float*)d_in[3];
    const float* bq    = (const float*)d_in[4];
    const float* Wk    = (const float*)d_in[5];
    const float* bk    = (const float*)d_in[6];
    const float* Wv    = (const float*)d_in[7];
    const float* bv    = (const float*)d_in[8];
    const float* Wp    = (const float*)d_in[9];
    const float* bp    = (const float*)d_in[10];
    const float* ln2_g = (const float*)d_in[11];
    const float* ln2_b = (const float*)d_in[12];
    const float* W1    = (const float*)d_in[13];
    const float* b1    = (const float*)d_in[14];
    const float* W2    = (const float*)d_in[15];
    const float* b2    = (const float*)d_in[16];

    float *res, *part;
    __half *ln, *q, *k, *v, *y, *h1, *wt;
    cudaGetSymbolAddress((void**)&res,  g_res);
    cudaGetSymbolAddress((void**)&part, g_part);
    cudaGetSymbolAddress((void**)&ln,  g_ln);
    cudaGetSymbolAddress((void**)&q,   g_q);
    cudaGetSymbolAddress((void**)&k,   g_k);
    cudaGetSymbolAddress((void**)&v,   g_v);
    cudaGetSymbolAddress((void**)&y,   g_y);
    cudaGetSymbolAddress((void**)&h1,  g_h1);
    cudaGetSymbolAddress((void**)&wt,  g_wt);

    cudaFuncSetAttribute(attn_tc_kernel, cudaFuncAttributeMaxDynamicSharedMemorySize, ATTN_SMEM);
    cudaFuncSetAttribute(tc_gemm_kernel<EPI_RESID, float>,  cudaFuncAttributeMaxDynamicSharedMemorySize, GEMM_SMEM_BYTES);
    cudaFuncSetAttribute(tc_gemm_kernel<EPI_GELU, __half>,  cudaFuncAttributeMaxDynamicSharedMemorySize, GEMM_SMEM_BYTES);
    cudaFuncSetAttribute(qkv_gemm_kernel,                   cudaFuncAttributeMaxDynamicSharedMemorySize, GEMM_SMEM_BYTES);
    cudaFuncSetAttribute(w2_splitk_kernel,                  cudaFuncAttributeMaxDynamicSharedMemorySize, GEMM_SMEM_BYTES);

    // ---- convert + transpose weights to half [N][K] ----
    {
        dim3 tb(32, 8);
        convT_kernel<<<dim3(CC/32,  CC/32,  LNUM), tb>>>(Wq, wt + WQ_OFF, CC, CC);
        convT_kernel<<<dim3(CC/32,  CC/32,  LNUM), tb>>>(Wk, wt + WK_OFF, CC, CC);
        convT_kernel<<<dim3(CC/32,  CC/32,  LNUM), tb>>>(Wv, wt + WV_OFF, CC, CC);
        convT_kernel<<<dim3(CC/32,  CC/32,  LNUM), tb>>>(Wp, wt + WP_OFF, CC, CC);
        convT_kernel<<<dim3(HID/32, CC/32,  LNUM), tb>>>(W1, wt + W1_OFF, CC, HID);
        convT_kernel<<<dim3(CC/32,  HID/32, LNUM), tb>>>(W2, wt + W2_OFF, HID, CC);
    }

    dim3 gemm_qkv3(CC / 128, MM / 128, 3);   // 576
    dim3 gemm_c  (CC / 128, MM / 128);       // 192
    dim3 gemm_h  (HID / 128, MM / 128);      // 768
    dim3 gemm_w2 (CC / 128, MM / 128, 3);    // 576 (split-K)
    dim3 attn_grid(TT / 128, BB * NH);       // 384

    for (int l = 0; l < LNUM; l++) {
        const __half* wq = wt + WQ_OFF + (size_t)l * CC * CC;
        const __half* wk = wt + WK_OFF + (size_t)l * CC * CC;
        const __half* wv = wt + WV_OFF + (size_t)l * CC * CC;
        const __half* wp = wt + WP_OFF + (size_t)l * CC * CC;
        const __half* w1 = wt + W1_OFF + (size_t)l * CC * HID;
        const __half* w2 = wt + W2_OFF + (size_t)l * HID * CC;

        const float* resIn = (l == 0) ? x : res;

        if (l == 0) {
            ln_kernel<<<MM / 8, 256>>>(x, ln1_g, ln1_b, ln);
        } else {
            // fold previous layer's W2 partials + bias + residual into res, then LN1
            ln_reduce_kernel<<<MM / 8, 256>>>(part, b2 + (size_t)(l - 1) * CC, res,
                                              ln1_g + (size_t)l * CC, ln1_b + (size_t)l * CC, ln);
        }
        qkv_gemm_kernel<<<gemm_qkv3, 256, GEMM_SMEM_BYTES>>>(
            ln, wq, wk, wv, bq + (size_t)l*CC, bk + (size_t)l*CC, bv + (size_t)l*CC, q, k, v);
        attn_tc_kernel<<<attn_grid, 256, ATTN_SMEM>>>(q, k, v, y);
        tc_gemm_kernel<EPI_RESID, float><<<gemm_c, 256, GEMM_SMEM_BYTES>>>(
            y, wp, bp + (size_t)l*CC, resIn, res, CC, CC);
        ln_kernel<<<MM / 8, 256>>>(res, ln2_g + (size_t)l*CC, ln2_b + (size_t)l*CC, ln);
        tc_gemm_kernel<EPI_GELU, __half><<<gemm_h, 256, GEMM_SMEM_BYTES>>>(
            ln, w1, b1 + (size_t)l*HID, nullptr, h1, HID, CC);
        w2_splitk_kernel<<<gemm_w2, 256, GEMM_SMEM_BYTES>>>(h1, w2, part);
    }

    // final: out = sum(partials) + b2[3] + res
    {
        int n4 = MM * CC / 4;
        reduce_out_kernel<<<(n4 + 255) / 256, 256>>>(part, b2 + (size_t)3 * CC, res, (float*)d_out);
    }
}

// round 15
// speedup vs baseline: 2.0831x; 1.0065x over previous
#include <cuda_runtime.h>
#include <cuda_fp16.h>
#include <math.h>
#include <cstdint>

// ---------------- problem constants ----------------
#define LNUM 4
#define BB   4
#define TT   1024
#define CC   768
#define NH   12
#define HD   64
#define HID  3072
#define MM   (BB*TT)          // 4096 rows
#define EPS_LN 1e-5f

// ---------------- scratch (device globals; no allocation allowed) ----------------
__device__ float  g_res [(size_t)MM*CC];
__device__ __half g_ln  [(size_t)MM*CC];
__device__ __half g_q   [(size_t)MM*CC];
__device__ __half g_k   [(size_t)MM*CC];
__device__ __half g_v   [(size_t)MM*CC];
__device__ __half g_y   [(size_t)MM*CC];
__device__ __half g_h1  [(size_t)MM*HID];
__device__ float  g_part[3 * (size_t)MM*CC];   // split-K partials (proj and W2, disjoint lifetimes)
// half, transposed [N][K] weights
#define WQ_OFF 0
#define WK_OFF (WQ_OFF + (size_t)LNUM*CC*CC)
#define WV_OFF (WK_OFF + (size_t)LNUM*CC*CC)
#define WP_OFF (WV_OFF + (size_t)LNUM*CC*CC)
#define W1_OFF (WP_OFF + (size_t)LNUM*CC*CC)
#define W2_OFF (W1_OFF + (size_t)LNUM*CC*HID)
#define WT_TOTAL (W2_OFF + (size_t)LNUM*CC*HID)
__device__ __half g_wt [WT_TOTAL];

// ---------------- helpers ----------------
__device__ __forceinline__ uint32_t smem_u32(const void* p) {
    uint32_t a;
    asm("{ .reg .u64 t; cvta.to.shared.u64 t, %1; cvt.u32.u64 %0, t; }" : "=r"(a) : "l"(p));
    return a;
}
__device__ __forceinline__ void cp_async16(uint32_t dst, const void* src) {
    asm volatile("cp.async.cg.shared.global [%0], [%1], 16;" :: "r"(dst), "l"(src));
}
#define CP_COMMIT() asm volatile("cp.async.commit_group;" ::: "memory")
template <int N>
__device__ __forceinline__ void cp_wait() {
    asm volatile("cp.async.wait_group %0;" :: "n"(N) : "memory");
}
__device__ __forceinline__ void mma_f16(float* d, uint32_t a0, uint32_t a1, uint32_t a2,
                                        uint32_t a3, uint32_t b0, uint32_t b1) {
    asm volatile(
        "mma.sync.aligned.m16n8k16.row.col.f32.f16.f16.f32 "
        "{%0,%1,%2,%3}, {%4,%5,%6,%7}, {%8,%9}, {%0,%1,%2,%3};"
        : "+f"(d[0]), "+f"(d[1]), "+f"(d[2]), "+f"(d[3])
        : "r"(a0), "r"(a1), "r"(a2), "r"(a3), "r"(b0), "r"(b1));
}
__device__ __forceinline__ void ldsm_x4(uint32_t addr, uint32_t* r) {
    asm volatile("ldmatrix.sync.aligned.m8n8.x4.shared.b16 {%0,%1,%2,%3}, [%4];"
        : "=r"(r[0]), "=r"(r[1]), "=r"(r[2]), "=r"(r[3]) : "r"(addr));
}
__device__ __forceinline__ void ldsm_x4_trans(uint32_t addr, uint32_t* r) {
    asm volatile("ldmatrix.sync.aligned.m8n8.x4.trans.shared.b16 {%0,%1,%2,%3}, [%4];"
        : "=r"(r[0]), "=r"(r[1]), "=r"(r[2]), "=r"(r[3]) : "r"(addr));
}
__device__ __forceinline__ uint32_t h2pack(float a, float b) {
    __half2 h = __floats2half2_rn(a, b);
    return *(uint32_t*)&h;
}

// ---------------- small kernels ----------------
// convert fp32 [K][N] weight -> half transposed [N][K]; grid.z = layer
__global__ void convT_kernel(const float* __restrict__ src, __half* __restrict__ dst,
                             int K, int N) {
    __shared__ float tile[32][33];
    const float* s = src + (size_t)blockIdx.z * K * N;
    __half* d = dst + (size_t)blockIdx.z * K * N;
    int tx = threadIdx.x, ty = threadIdx.y;
    int n0 = blockIdx.x * 32, k0 = blockIdx.y * 32;
#pragma unroll
    for (int i = 0; i < 32; i += 8)
        tile[ty + i][tx] = s[(size_t)(k0 + ty + i) * N + n0 + tx];
    __syncthreads();
#pragma unroll
    for (int i = 0; i < 32; i += 8)
        d[(size_t)(n0 + ty + i) * K + k0 + tx] = __float2half_rn(tile[tx][ty + i]);
}

// layernorm: one warp per row, float4 loads, shuffle-only reduction.
__global__ __launch_bounds__(256)
void ln_kernel(const float* __restrict__ x, const float* __restrict__ g,
               const float* __restrict__ b, __half* __restrict__ out) {
    int lane = threadIdx.x & 31;
    int wrow = threadIdx.x >> 5;
    int row = blockIdx.x * 8 + wrow;
    const float* xr = x + (size_t)row * CC;

    float4 v[6];
    float s = 0.f, s2 = 0.f;
#pragma unroll
    for (int i = 0; i < 6; i++) {
        v[i] = *(const float4*)(xr + i * 128 + lane * 4);
        s  += v[i].x + v[i].y + v[i].z + v[i].w;
        s2 += v[i].x * v[i].x + v[i].y * v[i].y + v[i].z * v[i].z + v[i].w * v[i].w;
    }
#pragma unroll
    for (int o = 16; o; o >>= 1) {
        s  += __shfl_xor_sync(0xffffffffu, s,  o);
        s2 += __shfl_xor_sync(0xffffffffu, s2, o);
    }
    float mu  = s * (1.f / CC);
    float var = s2 * (1.f / CC) - mu * mu;
    float rs  = rsqrtf(var + EPS_LN);

    __half* outr = out + (size_t)row * CC;
#pragma unroll
    for (int i = 0; i < 6; i++) {
        int c = i * 128 + lane * 4;
        float4 gv = *(const float4*)(g + c);
        float4 bv = *(const float4*)(b + c);
        uint2 o2;
        o2.x = h2pack((v[i].x - mu) * rs * gv.x + bv.x, (v[i].y - mu) * rs * gv.y + bv.y);
        o2.y = h2pack((v[i].z - mu) * rs * gv.z + bv.z, (v[i].w - mu) * rs * gv.w + bv.w);
        *(uint2*)(outr + c) = o2;
    }
}

// fused: resDst = p0+p1+p2 + bias + resSrc, then LN(resDst) -> out (half)
__global__ __launch_bounds__(256)
void ln_reduce_kernel(const float* __restrict__ p, const float* __restrict__ bias,
                      const float* __restrict__ resSrc, float* __restrict__ resDst,
                      const float* __restrict__ g, const float* __restrict__ b,
                      __half* __restrict__ out) {
    int lane = threadIdx.x & 31;
    int wrow = threadIdx.x >> 5;
    int row = blockIdx.x * 8 + wrow;
    size_t roff = (size_t)row * CC;
    const float* p0 = p + roff;
    const float* p1 = p + (size_t)MM * CC + roff;
    const float* p2 = p + 2 * (size_t)MM * CC + roff;
    const float* rs_ = resSrc + roff;
    float* rd = resDst + roff;

    float4 v[6];
    float s = 0.f, s2 = 0.f;
#pragma unroll
    for (int i = 0; i < 6; i++) {
        int c = i * 128 + lane * 4;
        float4 a0 = *(const float4*)(p0 + c);
        float4 a1 = *(const float4*)(p1 + c);
        float4 a2 = *(const float4*)(p2 + c);
        float4 rv = *(const float4*)(rs_ + c);
        float4 bb = *(const float4*)(bias + c);
        v[i].x = a0.x + a1.x + a2.x + bb.x + rv.x;
        v[i].y = a0.y + a1.y + a2.y + bb.y + rv.y;
        v[i].z = a0.z + a1.z + a2.z + bb.z + rv.z;
        v[i].w = a0.w + a1.w + a2.w + bb.w + rv.w;
        *(float4*)(rd + c) = v[i];
        s  += v[i].x + v[i].y + v[i].z + v[i].w;
        s2 += v[i].x * v[i].x + v[i].y * v[i].y + v[i].z * v[i].z + v[i].w * v[i].w;
    }
#pragma unroll
    for (int o = 16; o; o >>= 1) {
        s  += __shfl_xor_sync(0xffffffffu, s,  o);
        s2 += __shfl_xor_sync(0xffffffffu, s2, o);
    }
    float mu  = s * (1.f / CC);
    float var = s2 * (1.f / CC) - mu * mu;
    float rs  = rsqrtf(var + EPS_LN);

    __half* outr = out + roff;
#pragma unroll
    for (int i = 0; i < 6; i++) {
        int c = i * 128 + lane * 4;
        float4 gv = *(const float4*)(g + c);
        float4 bv = *(const float4*)(b + c);
        uint2 o2;
        o2.x = h2pack((v[i].x - mu) * rs * gv.x + bv.x, (v[i].y - mu) * rs * gv.y + bv.y);
        o2.y = h2pack((v[i].z - mu) * rs * gv.z + bv.z, (v[i].w - mu) * rs * gv.w + bv.w);
        *(uint2*)(outr + c) = o2;
    }
}

// final-layer reduce: out = p0+p1+p2 + bias + res
__global__ void reduce_out_kernel(const float* __restrict__ p, const float* __restrict__ bias,
                                  const float* __restrict__ res, float* __restrict__ out) {
    int i = blockIdx.x * blockDim.x + threadIdx.x;
    int n4 = MM * CC / 4;
    if (i >= n4) return;
    int c4 = i % (CC / 4);
    float4 a0 = ((const float4*)p)[i];
    float4 a1 = ((const float4*)(p + (size_t)MM * CC))[i];
    float4 a2 = ((const float4*)(p + 2 * (size_t)MM * CC))[i];
    float4 rv = ((const float4*)res)[i];
    float4 bb = ((const float4*)bias)[c4];
    float4 o;
    o.x = a0.x + a1.x + a2.x + rv.x + bb.x;
    o.y = a0.y + a1.y + a2.y + rv.y + bb.y;
    o.z = a0.z + a1.z + a2.z + rv.z + bb.z;
    o.w = a0.w + a1.w + a2.w + rv.w + bb.w;
    ((float4*)out)[i] = o;
}

// ---------------- fp16 mma.sync GEMM, cp.async 4-stage, BK=32, ldsm A+B ----------------
#define EPI_BIAS  0
#define EPI_RESID 1
#define EPI_GELU  2
#define EPI_NONE  3

#define STAGES 4
#define BK 32
#define ASTR_H 40
#define BSTR_H 40
#define A_STG_H (128 * ASTR_H)
#define B_STG_H (128 * BSTR_H)
#define GEMM_SMEM_BYTES (STAGES * (A_STG_H + B_STG_H) * 2 + 512)   // 82,432 B

template <int EPI, typename OutT>
__device__ __forceinline__ void gemm_body(const __half* __restrict__ A, const __half* __restrict__ Wt,
                                          const float* __restrict__ bias, const float* __restrict__ resid,
                                          OutT* __restrict__ C, int Ndim, int Kstride, int Klen,
                                          int bm, int bn, char* dsm) {
    __half* sA = (__half*)dsm;
    __half* sB = (__half*)dsm + STAGES * A_STG_H;
    float* sBias = (float*)(dsm + STAGES * (A_STG_H + B_STG_H) * 2);

    int tid = threadIdx.x;
    int lane = tid & 31;
    int wid = tid >> 5;

    if (EPI != EPI_NONE && tid < 128) sBias[tid] = bias[bn + tid];

    int lr = lane >> 2;
    int lc = lane & 3;
    int wm = (wid & 1) * 64;
    int wn = (wid >> 1) * 32;

    int idx0 = tid * 2, idx1 = tid * 2 + 1;
    int r0i = idx0 >> 2, s0i = (idx0 & 3) * 8;
    int r1i = idx1 >> 2, s1i = (idx1 & 3) * 8;

    uint32_t sA_base = smem_u32(sA);
    uint32_t sB_base = smem_u32(sB);
    uint32_t aFrag = sA_base + (uint32_t)((wm + (lane & 15)) * ASTR_H) * 2 + ((lane & 16) ? 16u : 0u);
    uint32_t bFrag = sB_base + (uint32_t)((wn + (lane & 7)) * BSTR_H) * 2 + (uint32_t)(lane >> 3) * 16u;

    const __half* aSrc0 = A + (size_t)(bm + r0i) * Kstride + s0i;
    const __half* aSrc1 = A + (size_t)(bm + r1i) * Kstride + s1i;
    const __half* bSrc0 = Wt + (size_t)(bn + r0i) * Kstride + s0i;
    const __half* bSrc1 = Wt + (size_t)(bn + r1i) * Kstride + s1i;

    float acc[4][4][4];
#pragma unroll
    for (int i = 0; i < 4; i++)
#pragma unroll
        for (int j = 0; j < 4; j++)
#pragma unroll
            for (int r = 0; r < 4; r++) acc[i][j][r] = 0.f;

    int nch = Klen / BK;

    auto load_stage = [&](int stg, int chunk) {
        int k0 = chunk * BK;
        uint32_t ab = sA_base + (uint32_t)(stg * A_STG_H) * 2;
        uint32_t bb = sB_base + (uint32_t)(stg * B_STG_H) * 2;
        cp_async16(ab + (uint32_t)(r0i * ASTR_H + s0i) * 2, aSrc0 + k0);
        cp_async16(ab + (uint32_t)(r1i * ASTR_H + s1i) * 2, aSrc1 + k0);
        cp_async16(bb + (uint32_t)(r0i * BSTR_H + s0i) * 2, bSrc0 + k0);
        cp_async16(bb + (uint32_t)(r1i * BSTR_H + s1i) * 2, bSrc1 + k0);
    };

#pragma unroll
    for (int s = 0; s < STAGES - 1; s++) {
        if (s < nch) load_stage(s, s);
        CP_COMMIT();
    }
    cp_wait<STAGES - 2>();
    __syncthreads();

    for (int c = 0; c < nch; c++) {
        int buf = c % STAGES;
        int nc = c + STAGES - 1;
        if (nc < nch) load_stage(nc % STAGES, nc);
        CP_COMMIT();

        uint32_t aStage = aFrag + (uint32_t)(buf * A_STG_H) * 2;
        uint32_t bStage = bFrag + (uint32_t)(buf * B_STG_H) * 2;

        uint32_t bfr[4][4];
#pragma unroll
        for (int j = 0; j < 4; j++)
            ldsm_x4(bStage + (uint32_t)(j * 8 * BSTR_H) * 2, bfr[j]);

#pragma unroll
        for (int ks = 0; ks < 2; ks++) {
#pragma unroll
            for (int i = 0; i < 4; i++) {
                uint32_t a[4];
                ldsm_x4(aStage + (uint32_t)(i * 16 * ASTR_H) * 2 + ks * 32, a);
#pragma unroll
                for (int j = 0; j < 4; j++)
                    mma_f16(acc[i][j], a[0], a[1], a[2], a[3], bfr[j][2 * ks], bfr[j][2 * ks + 1]);
            }
        }
        cp_wait<STAGES - 2>();
        __syncthreads();
    }

#pragma unroll
    for (int i = 0; i < 4; i++) {
        int r0 = bm + wm + i * 16 + lr;
#pragma unroll
        for (int j = 0; j < 4; j++) {
            int colL = wn + j * 8 + lc * 2;
            int col = bn + colL;
            float v0 = acc[i][j][0];
            float v1 = acc[i][j][1];
            float v2 = acc[i][j][2];
            float v3 = acc[i][j][3];
            if (EPI != EPI_NONE) {
                v0 += sBias[colL]; v1 += sBias[colL + 1];
                v2 += sBias[colL]; v3 += sBias[colL + 1];
            }
            if (EPI == EPI_RESID) {
                float2 ra = *(const float2*)(resid + (size_t)r0 * Ndim + col);
                float2 rb = *(const float2*)(resid + (size_t)(r0 + 8) * Ndim + col);
                v0 += ra.x; v1 += ra.y; v2 += rb.x; v3 += rb.y;
            }
            if (EPI == EPI_GELU) {
                v0 = v0 * 0.5f * (1.0f + erff(v0 * 0.70710678118654752f));
                v1 = v1 * 0.5f * (1.0f + erff(v1 * 0.70710678118654752f));
                v2 = v2 * 0.5f * (1.0f + erff(v2 * 0.70710678118654752f));
                v3 = v3 * 0.5f * (1.0f + erff(v3 * 0.70710678118654752f));
            }
            if (sizeof(OutT) == 4) {
                *(float2*)((float*)C + (size_t)r0 * Ndim + col)       = make_float2(v0, v1);
                *(float2*)((float*)C + (size_t)(r0 + 8) * Ndim + col) = make_float2(v2, v3);
            } else {
                *(__half2*)((__half*)C + (size_t)r0 * Ndim + col)       = __floats2half2_rn(v0, v1);
                *(__half2*)((__half*)C + (size_t)(r0 + 8) * Ndim + col) = __floats2half2_rn(v2, v3);
            }
        }
    }
}

template <int EPI, typename OutT>
__global__ __launch_bounds__(256, 2)
void tc_gemm_kernel(const __half* __restrict__ A, const __half* __restrict__ Wt,
                    const float* __restrict__ bias, const float* __restrict__ resid,
                    OutT* __restrict__ C, int Ndim, int Kdim) {
    extern __shared__ char dsm[];
    gemm_body<EPI, OutT>(A, Wt, bias, resid, C, Ndim, Kdim, Kdim,
                         blockIdx.y * 128, blockIdx.x * 128, dsm);
}

__global__ __launch_bounds__(256, 2)
void qkv_gemm_kernel(const __half* __restrict__ A,
                     const __half* __restrict__ W0, const __half* __restrict__ W1, const __half* __restrict__ W2,
                     const float* __restrict__ b0, const float* __restrict__ b1, const float* __restrict__ b2,
                     __half* __restrict__ C0, __half* __restrict__ C1, __half* __restrict__ C2) {
    extern __shared__ char dsm[];
    const __half* W = (blockIdx.z == 0) ? W0 : (blockIdx.z == 1) ? W1 : W2;
    const float* bi = (blockIdx.z == 0) ? b0 : (blockIdx.z == 1) ? b1 : b2;
    __half* C = (blockIdx.z == 0) ? C0 : (blockIdx.z == 1) ? C1 : C2;
    gemm_body<EPI_BIAS, __half>(A, W, bi, nullptr, C, CC, CC, CC,
                                blockIdx.y * 128, blockIdx.x * 128, dsm);
}

// split-K GEMM: grid (6, 32, 3); slice z covers Klen = Kdim/3
__global__ __launch_bounds__(256, 2)
void splitk_gemm_kernel(const __half* __restrict__ A, const __half* __restrict__ Wt,
                        float* __restrict__ part, int Kdim) {
    extern __shared__ char dsm[];
    int z = blockIdx.z;
    int kslice = Kdim / 3;
    gemm_body<EPI_NONE, float>(A + z * kslice, Wt + z * kslice, nullptr, nullptr,
                               part + (size_t)z * MM * CC, CC, Kdim, kslice,
                               blockIdx.y * 128, blockIdx.x * 128, dsm);
}

// ---------------- fp16 tensor-core flash attention ----------------
#define QSTR_H 72
#define KSTR_H 72
#define VSTR_H 72
#define ATT_Q_OFFH 0
#define ATT_K_OFFH (128 * QSTR_H)
#define ATT_V_OFFH (ATT_K_OFFH + 64 * KSTR_H)
#define ATT_HALVES (ATT_V_OFFH + 64 * VSTR_H)
#define ATTN_SMEM (ATT_HALVES * 2)          // 36,864 B

__global__ __launch_bounds__(256, 2)
void attn_tc_kernel(const __half* __restrict__ Q, const __half* __restrict__ K,
                    const __half* __restrict__ V, __half* __restrict__ Y) {
    extern __shared__ __half smh[];
    __half* Qs = smh + ATT_Q_OFFH;
    __half* Ks = smh + ATT_K_OFFH;
    __half* Vs = smh + ATT_V_OFFH;

    int tid = threadIdx.x;
    int lane = tid & 31;
    int wid = tid >> 5;
    int lr = lane >> 2;
    int lc = lane & 3;
    int wr = wid * 16;

    int bx = blockIdx.x;
    int qb = (bx < 4) ? ((bx * 2 + 1) * 128) : ((bx - 4) * 2 * 128);
    int bh = blockIdx.y;
    int b = bh / NH, h = bh % NH;
    size_t base = (size_t)b * TT * CC + (size_t)h * HD;

    uint32_t qFrag = smem_u32(Qs) + (uint32_t)((wr + (lane & 15)) * QSTR_H) * 2 + ((lane & 16) ? 16u : 0u);
    uint32_t kFrag = smem_u32(Ks) + (uint32_t)((lane & 7) * KSTR_H) * 2 + (uint32_t)(lane >> 3) * 16u;
    uint32_t vFrag = smem_u32(Vs) + (uint32_t)(((lane & 7) + ((lane >> 3) & 1) * 8) * VSTR_H) * 2
                   + ((lane & 16) ? 16u : 0u);

    {
        const __half2 sc = __float2half2_rn(0.125f);
        for (int i = tid; i < 128 * 8; i += 256) {
            int row = i >> 3, cg = (i & 7) * 8;
            uint4 u = *(const uint4*)(Q + base + (size_t)(qb + row) * CC + cg);
            __half2* hp = (__half2*)&u;
            hp[0] = __hmul2(hp[0], sc); hp[1] = __hmul2(hp[1], sc);
            hp[2] = __hmul2(hp[2], sc); hp[3] = __hmul2(hp[3], sc);
            *(uint4*)(Qs + row * QSTR_H + cg) = u;
        }
    }

    float o[8][4];
#pragma unroll
    for (int j = 0; j < 8; j++)
#pragma unroll
        for (int r = 0; r < 4; r++) o[j][r] = 0.f;

    float m0r = -1e30f, m1r = -1e30f;
    float l0r = 0.f, l1r = 0.f;

    int qmod = qb & 255;
    int rm0 = qmod + wr + lr;
    int rm1 = rm0 + 8;

    for (int kb = 0; kb < TT; kb += 64) {
        int kbm = kb & 255;
        if (kbm > qmod + 127) continue;
        __syncthreads();
        for (int i = tid; i < 64 * 8; i += 256) {
            int row = i >> 3, cg = (i & 7) * 8;
            *(uint4*)(Ks + row * KSTR_H + cg) = *(const uint4*)(K + base + (size_t)(kb + row) * CC + cg);
            *(uint4*)(Vs + row * VSTR_H + cg) = *(const uint4*)(V + base + (size_t)(kb + row) * CC + cg);
        }
        __syncthreads();

        float sacc[8][4];
#pragma unroll
        for (int j = 0; j < 8; j++)
#pragma unroll
            for (int r = 0; r < 4; r++) sacc[j][r] = 0.f;
#pragma unroll
        for (int kc = 0; kc < 2; kc++) {
            uint32_t bf[8][4];
#pragma unroll
            for (int j = 0; j < 8; j++)
                ldsm_x4(kFrag + (uint32_t)(j * 8 * KSTR_H) * 2 + kc * 64, bf[j]);
#pragma unroll
            for (int ksl = 0; ksl < 2; ksl++) {
                int ks = kc * 2 + ksl;
                uint32_t a[4];
                ldsm_x4(qFrag + ks * 32, a);
#pragma unroll
                for (int j = 0; j < 8; j++)
                    mma_f16(sacc[j], a[0], a[1], a[2], a[3], bf[j][2 * ksl], bf[j][2 * ksl + 1]);
            }
        }

        float m0 = -1e30f, m1 = -1e30f;
#pragma unroll
        for (int j = 0; j < 8; j++) {
            int c0 = kbm + j * 8 + 2 * lc;
            if (c0 > rm0)     sacc[j][0] = -1e30f;
            if (c0 + 1 > rm0) sacc[j][1] = -1e30f;
            if (c0 > rm1)     sacc[j][2] = -1e30f;
            if (c0 + 1 > rm1) sacc[j][3] = -1e30f;
            m0 = fmaxf(m0, fmaxf(sacc[j][0], sacc[j][1]));
            m1 = fmaxf(m1, fmaxf(sacc[j][2], sacc[j][3]));
        }
        m0 = fmaxf(m0, __shfl_xor_sync(0xffffffffu, m0, 1));
        m0 = fmaxf(m0, __shfl_xor_sync(0xffffffffu, m0, 2));
        m1 = fmaxf(m1, __shfl_xor_sync(0xffffffffu, m1, 1));
        m1 = fmaxf(m1, __shfl_xor_sync(0xffffffffu, m1, 2));

        float mn0 = fmaxf(m0r, m0), mn1 = fmaxf(m1r, m1);
        float al0 = __expf(m0r - mn0), al1 = __expf(m1r - mn1);
        m0r = mn0; m1r = mn1;

        uint32_t pa[4][4];
        float sum0 = 0.f, sum1 = 0.f;
#pragma unroll
        for (int ks = 0; ks < 4; ks++) {
#pragma unroll
            for (int jj = 0; jj < 2; jj++) {
                int j = 2 * ks + jj;
                float p00 = __expf(sacc[j][0] - mn0);
                float p01 = __expf(sacc[j][1] - mn0);
                float p10 = __expf(sacc[j][2] - mn1);
                float p11 = __expf(sacc[j][3] - mn1);
                sum0 += p00 + p01;
                sum1 += p10 + p11;
                pa[ks][2 * jj]     = h2pack(p00, p01);
                pa[ks][2 * jj + 1] = h2pack(p10, p11);
            }
        }
        sum0 += __shfl_xor_sync(0xffffffffu, sum0, 1);
        sum0 += __shfl_xor_sync(0xffffffffu, sum0, 2);
        sum1 += __shfl_xor_sync(0xffffffffu, sum1, 1);
        sum1 += __shfl_xor_sync(0xffffffffu, sum1, 2);
        l0r = l0r * al0 + sum0;
        l1r = l1r * al1 + sum1;

#pragma unroll
        for (int j = 0; j < 8; j++) {
            o[j][0] *= al0; o[j][1] *= al0; o[j][2] *= al1; o[j][3] *= al1;
        }

#pragma unroll
        for (int ks = 0; ks < 4; ks++) {
#pragma unroll
            for (int j2 = 0; j2 < 4; j2++) {
                uint32_t bv[4];
                ldsm_x4_trans(vFrag + (uint32_t)(ks * 16 * VSTR_H) * 2 + j2 * 32, bv);
                mma_f16(o[2 * j2],     pa[ks][0], pa[ks][1], pa[ks][2], pa[ks][3], bv[0], bv[1]);
                mma_f16(o[2 * j2 + 1], pa[ks][0], pa[ks][1], pa[ks][2], pa[ks][3], bv[2], bv[3]);
            }
        }
    }

    int r0 = wr + lr, r1 = r0 + 8;
    float inv0 = 1.0f / l0r;
    float inv1 = 1.0f / l1r;
#pragma unroll
    for (int j = 0; j < 8; j++) {
        int d = j * 8 + 2 * lc;
        *(__half2*)(Y + base + (size_t)(qb + r0) * CC + d) =
            __floats2half2_rn(o[j][0] * inv0, o[j][1] * inv0);
        *(__half2*)(Y + base + (size_t)(qb + r1) * CC + d) =
            __floats2half2_rn(o[j][2] * inv1, o[j][3] * inv1);
    }
}

// ---------------- host orchestration ----------------
extern "C" void kernel_launch(void* const* d_in, const int* in_sizes, int n_in,
                              void* d_out, int out_size) {
    const float* x     = (const float*)d_in[0];
    const float* ln1_g = (const float*)d_in[1];
    const float* ln1_b = (const float*)d_in[2];
    const float* Wq    = (const float*)d_in[3];
    const float* bq    = (const float*)d_in[4];
    const float* Wk    = (const float*)d_in[5];
    const float* bk    = (const float*)d_in[6];
    const float* Wv    = (const float*)d_in[7];
    const float* bv    = (const float*)d_in[8];
    const float* Wp    = (const float*)d_in[9];
    const float* bp    = (const float*)d_in[10];
    const float* ln2_g = (const float*)d_in[11];
    const float* ln2_b = (const float*)d_in[12];
    const float* W1    = (const float*)d_in[13];
    const float* b1    = (const float*)d_in[14];
    const float* W2    = (const float*)d_in[15];
    const float* b2    = (const float*)d_in[16];

    float *res, *part;
    __half *ln, *q, *k, *v, *y, *h1, *wt;
    cudaGetSymbolAddress((void**)&res,  g_res);
    cudaGetSymbolAddress((void**)&part, g_part);
    cudaGetSymbolAddress((void**)&ln,  g_ln);
    cudaGetSymbolAddress((void**)&q,   g_q);
    cudaGetSymbolAddress((void**)&k,   g_k);
    cudaGetSymbolAddress((void**)&v,   g_v);
    cudaGetSymbolAddress((void**)&y,   g_y);
    cudaGetSymbolAddress((void**)&h1,  g_h1);
    cudaGetSymbolAddress((void**)&wt,  g_wt);

    cudaFuncSetAttribute(attn_tc_kernel, cudaFuncAttributeMaxDynamicSharedMemorySize, ATTN_SMEM);
    cudaFuncSetAttribute(tc_gemm_kernel<EPI_GELU, __half>,  cudaFuncAttributeMaxDynamicSharedMemorySize, GEMM_SMEM_BYTES);
    cudaFuncSetAttribute(qkv_gemm_kernel,                   cudaFuncAttributeMaxDynamicSharedMemorySize, GEMM_SMEM_BYTES);
    cudaFuncSetAttribute(splitk_gemm_kernel,                cudaFuncAttributeMaxDynamicSharedMemorySize, GEMM_SMEM_BYTES);

    // ---- convert + transpose weights to half [N][K] ----
    {
        dim3 tb(32, 8);
        convT_kernel<<<dim3(CC/32,  CC/32,  LNUM), tb>>>(Wq, wt + WQ_OFF, CC, CC);
        convT_kernel<<<dim3(CC/32,  CC/32,  LNUM), tb>>>(Wk, wt + WK_OFF, CC, CC);
        convT_kernel<<<dim3(CC/32,  CC/32,  LNUM), tb>>>(Wv, wt + WV_OFF, CC, CC);
        convT_kernel<<<dim3(CC/32,  CC/32,  LNUM), tb>>>(Wp, wt + WP_OFF, CC, CC);
        convT_kernel<<<dim3(HID/32, CC/32,  LNUM), tb>>>(W1, wt + W1_OFF, CC, HID);
        convT_kernel<<<dim3(CC/32,  HID/32, LNUM), tb>>>(W2, wt + W2_OFF, HID, CC);
    }

    dim3 gemm_qkv3(CC / 128, MM / 128, 3);   // 576
    dim3 gemm_h   (HID / 128, MM / 128);     // 768
    dim3 gemm_sk  (CC / 128, MM / 128, 3);   // 576 (split-K)
    dim3 attn_grid(TT / 128, BB * NH);       // 384

    for (int l = 0; l < LNUM; l++) {
        const __half* wq = wt + WQ_OFF + (size_t)l * CC * CC;
        const __half* wk = wt + WK_OFF + (size_t)l * CC * CC;
        const __half* wv = wt + WV_OFF + (size_t)l * CC * CC;
        const __half* wp = wt + WP_OFF + (size_t)l * CC * CC;
        const __half* w1 = wt + W1_OFF + (size_t)l * CC * HID;
        const __half* w2 = wt + W2_OFF + (size_t)l * HID * CC;

        const float* resIn = (l == 0) ? x : res;

        if (l == 0) {
            ln_kernel<<<MM / 8, 256>>>(x, ln1_g, ln1_b, ln);
        } else {
            // fold previous layer's W2 partials + b2 + residual into res, then LN1
            ln_reduce_kernel<<<MM / 8, 256>>>(part, b2 + (size_t)(l - 1) * CC, res, res,
                                              ln1_g + (size_t)l * CC, ln1_b + (size_t)l * CC, ln);
        }
        qkv_gemm_kernel<<<gemm_qkv3, 256, GEMM_SMEM_BYTES>>>(
            ln, wq, wk, wv, bq + (size_t)l*CC, bk + (size_t)l*CC, bv + (size_t)l*CC, q, k, v);
        attn_tc_kernel<<<attn_grid, 256, ATTN_SMEM>>>(q, k, v, y);
        // proj split-K -> partials; fold + bp + resid into res, then LN2
        splitk_gemm_kernel<<<gemm_sk, 256, GEMM_SMEM_BYTES>>>(y, wp, part, CC);
        ln_reduce_kernel<<<MM / 8, 256>>>(part, bp + (size_t)l * CC, resIn, res,
                                          ln2_g + (size_t)l * CC, ln2_b + (size_t)l * CC, ln);
        tc_gemm_kernel<EPI_GELU, __half><<<gemm_h, 256, GEMM_SMEM_BYTES>>>(
            ln, w1, b1 + (size_t)l*HID, nullptr, h1, HID, CC);
        splitk_gemm_kernel<<<gemm_sk, 256, GEMM_SMEM_BYTES>>>(h1, w2, part, HID);
    }

    // final: out = sum(partials) + b2[3] + res
    {
        int n4 = MM * CC / 4;
        reduce_out_kernel<<<(n4 + 255) / 256, 256>>>(part, b2 + (size_t)3 * CC, res, (float*)d_out);
    }
}

// round 16
// speedup vs baseline: 2.1686x; 1.0411x over previous
#include <cuda_runtime.h>
#include <cuda_fp16.h>
#include <math.h>
#include <cstdint>

// ---------------- problem constants ----------------
#define LNUM 4
#define BB   4
#define TT   1024
#define CC   768
#define NH   12
#define HD   64
#define HID  3072
#define MM   (BB*TT)          // 4096 rows
#define EPS_LN 1e-5f

// ---------------- scratch (device globals; no allocation allowed) ----------------
__device__ float  g_res [(size_t)MM*CC];
__device__ __half g_ln  [(size_t)MM*CC];
__device__ __half g_q   [(size_t)MM*CC];
__device__ __half g_k   [(size_t)MM*CC];
__device__ __half g_v   [(size_t)MM*CC];
__device__ __half g_y   [(size_t)MM*CC];
__device__ __half g_h1  [(size_t)MM*HID];
__device__ float  g_part[3 * (size_t)MM*CC];   // split-K partials
// half weights in NATURAL [K][N] layout (no transpose)
#define WQ_OFF 0
#define WK_OFF (WQ_OFF + (size_t)LNUM*CC*CC)
#define WV_OFF (WK_OFF + (size_t)LNUM*CC*CC)
#define WP_OFF (WV_OFF + (size_t)LNUM*CC*CC)
#define W1_OFF (WP_OFF + (size_t)LNUM*CC*CC)
#define W2_OFF (W1_OFF + (size_t)LNUM*CC*HID)
#define WT_TOTAL (W2_OFF + (size_t)LNUM*CC*HID)
__device__ __half g_wt [WT_TOTAL];

// ---------------- helpers ----------------
__device__ __forceinline__ uint32_t smem_u32(const void* p) {
    uint32_t a;
    asm("{ .reg .u64 t; cvta.to.shared.u64 t, %1; cvt.u32.u64 %0, t; }" : "=r"(a) : "l"(p));
    return a;
}
__device__ __forceinline__ void cp_async16(uint32_t dst, const void* src) {
    asm volatile("cp.async.cg.shared.global [%0], [%1], 16;" :: "r"(dst), "l"(src));
}
#define CP_COMMIT() asm volatile("cp.async.commit_group;" ::: "memory")
template <int N>
__device__ __forceinline__ void cp_wait() {
    asm volatile("cp.async.wait_group %0;" :: "n"(N) : "memory");
}
__device__ __forceinline__ void mma_f16(float* d, uint32_t a0, uint32_t a1, uint32_t a2,
                                        uint32_t a3, uint32_t b0, uint32_t b1) {
    asm volatile(
        "mma.sync.aligned.m16n8k16.row.col.f32.f16.f16.f32 "
        "{%0,%1,%2,%3}, {%4,%5,%6,%7}, {%8,%9}, {%0,%1,%2,%3};"
        : "+f"(d[0]), "+f"(d[1]), "+f"(d[2]), "+f"(d[3])
        : "r"(a0), "r"(a1), "r"(a2), "r"(a3), "r"(b0), "r"(b1));
}
__device__ __forceinline__ void ldsm_x4(uint32_t addr, uint32_t* r) {
    asm volatile("ldmatrix.sync.aligned.m8n8.x4.shared.b16 {%0,%1,%2,%3}, [%4];"
        : "=r"(r[0]), "=r"(r[1]), "=r"(r[2]), "=r"(r[3]) : "r"(addr));
}
__device__ __forceinline__ void ldsm_x4_trans(uint32_t addr, uint32_t* r) {
    asm volatile("ldmatrix.sync.aligned.m8n8.x4.trans.shared.b16 {%0,%1,%2,%3}, [%4];"
        : "=r"(r[0]), "=r"(r[1]), "=r"(r[2]), "=r"(r[3]) : "r"(addr));
}
__device__ __forceinline__ uint32_t h2pack(float a, float b) {
    __half2 h = __floats2half2_rn(a, b);
    return *(uint32_t*)&h;
}

// ---------------- small kernels ----------------
// one-shot convert of ALL weights fp32 -> half, natural layout, single launch.
#define R_SM  (LNUM * CC * CC / 4)          // n4 per small region (589824)
#define R_BG  (LNUM * CC * HID / 4)         // n4 per big region  (2359296)
#define N4_ALL (4 * R_SM + 2 * R_BG)
__global__ void conv_all_kernel(const float* __restrict__ wq, const float* __restrict__ wk,
                                const float* __restrict__ wv, const float* __restrict__ wp,
                                const float* __restrict__ w1, const float* __restrict__ w2,
                                __half* __restrict__ dst) {
    int i = blockIdx.x * blockDim.x + threadIdx.x;
    if (i >= N4_ALL) return;
    const float* src;
    int off;
    if (i < 2 * R_SM) {
        if (i < R_SM)       { src = wq; off = i; }
        else                { src = wk; off = i - R_SM; }
    } else if (i < 4 * R_SM) {
        if (i < 3 * R_SM)   { src = wv; off = i - 2 * R_SM; }
        else                { src = wp; off = i - 3 * R_SM; }
    } else if (i < 4 * R_SM + R_BG) { src = w1; off = i - 4 * R_SM; }
    else                            { src = w2; off = i - 4 * R_SM - R_BG; }
    float4 v = ((const float4*)src)[off];
    uint2 o;
    o.x = h2pack(v.x, v.y);
    o.y = h2pack(v.z, v.w);
    ((uint2*)dst)[i] = o;
}

// layernorm: one warp per row, float4 loads, shuffle-only reduction.
__global__ __launch_bounds__(256)
void ln_kernel(const float* __restrict__ x, const float* __restrict__ g,
               const float* __restrict__ b, __half* __restrict__ out) {
    int lane = threadIdx.x & 31;
    int wrow = threadIdx.x >> 5;
    int row = blockIdx.x * 8 + wrow;
    const float* xr = x + (size_t)row * CC;

    float4 v[6];
    float s = 0.f, s2 = 0.f;
#pragma unroll
    for (int i = 0; i < 6; i++) {
        v[i] = *(const float4*)(xr + i * 128 + lane * 4);
        s  += v[i].x + v[i].y + v[i].z + v[i].w;
        s2 += v[i].x * v[i].x + v[i].y * v[i].y + v[i].z * v[i].z + v[i].w * v[i].w;
    }
#pragma unroll
    for (int o = 16; o; o >>= 1) {
        s  += __shfl_xor_sync(0xffffffffu, s,  o);
        s2 += __shfl_xor_sync(0xffffffffu, s2, o);
    }
    float mu  = s * (1.f / CC);
    float var = s2 * (1.f / CC) - mu * mu;
    float rs  = rsqrtf(var + EPS_LN);

    __half* outr = out + (size_t)row * CC;
#pragma unroll
    for (int i = 0; i < 6; i++) {
        int c = i * 128 + lane * 4;
        float4 gv = *(const float4*)(g + c);
        float4 bv = *(const float4*)(b + c);
        uint2 o2;
        o2.x = h2pack((v[i].x - mu) * rs * gv.x + bv.x, (v[i].y - mu) * rs * gv.y + bv.y);
        o2.y = h2pack((v[i].z - mu) * rs * gv.z + bv.z, (v[i].w - mu) * rs * gv.w + bv.w);
        *(uint2*)(outr + c) = o2;
    }
}

// fused: resDst = p0+p1+p2 + bias + resSrc, then LN(resDst) -> out (half)
__global__ __launch_bounds__(256)
void ln_reduce_kernel(const float* __restrict__ p, const float* __restrict__ bias,
                      const float* __restrict__ resSrc, float* __restrict__ resDst,
                      const float* __restrict__ g, const float* __restrict__ b,
                      __half* __restrict__ out) {
    int lane = threadIdx.x & 31;
    int wrow = threadIdx.x >> 5;
    int row = blockIdx.x * 8 + wrow;
    size_t roff = (size_t)row * CC;
    const float* p0 = p + roff;
    const float* p1 = p + (size_t)MM * CC + roff;
    const float* p2 = p + 2 * (size_t)MM * CC + roff;
    const float* rs_ = resSrc + roff;
    float* rd = resDst + roff;

    float4 v[6];
    float s = 0.f, s2 = 0.f;
#pragma unroll
    for (int i = 0; i < 6; i++) {
        int c = i * 128 + lane * 4;
        float4 a0 = *(const float4*)(p0 + c);
        float4 a1 = *(const float4*)(p1 + c);
        float4 a2 = *(const float4*)(p2 + c);
        float4 rv = *(const float4*)(rs_ + c);
        float4 bb = *(const float4*)(bias + c);
        v[i].x = a0.x + a1.x + a2.x + bb.x + rv.x;
        v[i].y = a0.y + a1.y + a2.y + bb.y + rv.y;
        v[i].z = a0.z + a1.z + a2.z + bb.z + rv.z;
        v[i].w = a0.w + a1.w + a2.w + bb.w + rv.w;
        *(float4*)(rd + c) = v[i];
        s  += v[i].x + v[i].y + v[i].z + v[i].w;
        s2 += v[i].x * v[i].x + v[i].y * v[i].y + v[i].z * v[i].z + v[i].w * v[i].w;
    }
#pragma unroll
    for (int o = 16; o; o >>= 1) {
        s  += __shfl_xor_sync(0xffffffffu, s,  o);
        s2 += __shfl_xor_sync(0xffffffffu, s2, o);
    }
    float mu  = s * (1.f / CC);
    float var = s2 * (1.f / CC) - mu * mu;
    float rs  = rsqrtf(var + EPS_LN);

    __half* outr = out + roff;
#pragma unroll
    for (int i = 0; i < 6; i++) {
        int c = i * 128 + lane * 4;
        float4 gv = *(const float4*)(g + c);
        float4 bv = *(const float4*)(b + c);
        uint2 o2;
        o2.x = h2pack((v[i].x - mu) * rs * gv.x + bv.x, (v[i].y - mu) * rs * gv.y + bv.y);
        o2.y = h2pack((v[i].z - mu) * rs * gv.z + bv.z, (v[i].w - mu) * rs * gv.w + bv.w);
        *(uint2*)(outr + c) = o2;
    }
}

// final-layer reduce: out = p0+p1+p2 + bias + res
__global__ void reduce_out_kernel(const float* __restrict__ p, const float* __restrict__ bias,
                                  const float* __restrict__ res, float* __restrict__ out) {
    int i = blockIdx.x * blockDim.x + threadIdx.x;
    int n4 = MM * CC / 4;
    if (i >= n4) return;
    int c4 = i % (CC / 4);
    float4 a0 = ((const float4*)p)[i];
    float4 a1 = ((const float4*)(p + (size_t)MM * CC))[i];
    float4 a2 = ((const float4*)(p + 2 * (size_t)MM * CC))[i];
    float4 rv = ((const float4*)res)[i];
    float4 bb = ((const float4*)bias)[c4];
    float4 o;
    o.x = a0.x + a1.x + a2.x + rv.x + bb.x;
    o.y = a0.y + a1.y + a2.y + rv.y + bb.y;
    o.z = a0.z + a1.z + a2.z + rv.z + bb.z;
    o.w = a0.w + a1.w + a2.w + rv.w + bb.w;
    ((float4*)out)[i] = o;
}

// ---------------- fp16 mma.sync GEMM, cp.async 4-stage, BK=32 ----------------
// A [M][K] row-major (ldsm), B = W [K][N] row-major (trans-ldsm fragments).
#define EPI_BIAS  0
#define EPI_GELU  2
#define EPI_NONE  3

#define STAGES 4
#define BK 32
#define ASTR_H 40
#define BSTR_H 136                       // halfs per B k-row (128 data + 8 pad)
#define A_STG_H (128 * ASTR_H)           // 5120 halfs
#define B_STG_H (32 * BSTR_H)            // 4352 halfs
#define GEMM_SMEM_BYTES (STAGES * (A_STG_H + B_STG_H) * 2 + 512)   // 76,288 B

template <int EPI, typename OutT>
__device__ __forceinline__ void gemm_body(const __half* __restrict__ A, const __half* __restrict__ W,
                                          const float* __restrict__ bias,
                                          OutT* __restrict__ C, int Ndim, int Kstride, int Klen,
                                          int bm, int bn, char* dsm) {
    __half* sA = (__half*)dsm;
    __half* sB = (__half*)dsm + STAGES * A_STG_H;
    float* sBias = (float*)(dsm + STAGES * (A_STG_H + B_STG_H) * 2);

    int tid = threadIdx.x;
    int lane = tid & 31;
    int wid = tid >> 5;

    if (EPI != EPI_NONE && tid < 128) sBias[tid] = bias[bn + tid];

    int lr = lane >> 2;
    int lc = lane & 3;
    int wm = (wid & 1) * 64;
    int wn = (wid >> 1) * 32;

    // A cp.async mapping (rows of A): 2 chunks/thread
    int idx0 = tid * 2, idx1 = tid * 2 + 1;
    int aR0 = idx0 >> 2, aS0 = (idx0 & 3) * 8;
    int aR1 = idx1 >> 2, aS1 = (idx1 & 3) * 8;
    // B cp.async mapping (k-rows of W): 2 chunks/thread; idx 0..511: kr=idx>>4, ng=(idx&15)*8
    int bK0 = idx0 >> 4, bN0 = (idx0 & 15) * 8;
    int bK1 = idx1 >> 4, bN1 = (idx1 & 15) * 8;

    uint32_t sA_base = smem_u32(sA);
    uint32_t sB_base = smem_u32(sB);
    uint32_t aFrag = sA_base + (uint32_t)((wm + (lane & 15)) * ASTR_H) * 2 + ((lane & 16) ? 16u : 0u);
    // trans B frag: row = (lane&7) + ((lane>>3)&1)*8, col = wn + ((lane&16)?8:0)
    uint32_t bFrag = sB_base + (uint32_t)(((lane & 7) + ((lane >> 3) & 1) * 8) * BSTR_H) * 2
                   + (uint32_t)(wn + ((lane & 16) ? 8 : 0)) * 2;

    const __half* aSrc0 = A + (size_t)(bm + aR0) * Kstride + aS0;
    const __half* aSrc1 = A + (size_t)(bm + aR1) * Kstride + aS1;
    const __half* bSrc0 = W + (size_t)bK0 * Ndim + bn + bN0;
    const __half* bSrc1 = W + (size_t)bK1 * Ndim + bn + bN1;

    float acc[4][4][4];
#pragma unroll
    for (int i = 0; i < 4; i++)
#pragma unroll
        for (int j = 0; j < 4; j++)
#pragma unroll
            for (int r = 0; r < 4; r++) acc[i][j][r] = 0.f;

    int nch = Klen / BK;

    auto load_stage = [&](int stg, int chunk) {
        int k0 = chunk * BK;
        uint32_t ab = sA_base + (uint32_t)(stg * A_STG_H) * 2;
        uint32_t bb = sB_base + (uint32_t)(stg * B_STG_H) * 2;
        cp_async16(ab + (uint32_t)(aR0 * ASTR_H + aS0) * 2, aSrc0 + k0);
        cp_async16(ab + (uint32_t)(aR1 * ASTR_H + aS1) * 2, aSrc1 + k0);
        cp_async16(bb + (uint32_t)(bK0 * BSTR_H + bN0) * 2, bSrc0 + (size_t)k0 * Ndim);
        cp_async16(bb + (uint32_t)(bK1 * BSTR_H + bN1) * 2, bSrc1 + (size_t)k0 * Ndim);
    };

#pragma unroll
    for (int s = 0; s < STAGES - 1; s++) {
        if (s < nch) load_stage(s, s);
        CP_COMMIT();
    }
    cp_wait<STAGES - 2>();
    __syncthreads();

    for (int c = 0; c < nch; c++) {
        int buf = c % STAGES;
        int nc = c + STAGES - 1;
        if (nc < nch) load_stage(nc % STAGES, nc);
        CP_COMMIT();

        uint32_t aStage = aFrag + (uint32_t)(buf * A_STG_H) * 2;
        uint32_t bStage = bFrag + (uint32_t)(buf * B_STG_H) * 2;

        // B frags via trans ldsm: [ks][j2] covers k rows ks*16.., n cols j2*16..
        uint32_t bfr[2][2][4];
#pragma unroll
        for (int ks = 0; ks < 2; ks++)
#pragma unroll
            for (int j2 = 0; j2 < 2; j2++)
                ldsm_x4_trans(bStage + (uint32_t)(ks * 16 * BSTR_H) * 2 + j2 * 32, bfr[ks][j2]);

#pragma unroll
        for (int ks = 0; ks < 2; ks++) {
#pragma unroll
            for (int i = 0; i < 4; i++) {
                uint32_t a[4];
                ldsm_x4(aStage + (uint32_t)(i * 16 * ASTR_H) * 2 + ks * 32, a);
#pragma unroll
                for (int j2 = 0; j2 < 2; j2++) {
                    mma_f16(acc[i][2 * j2],     a[0], a[1], a[2], a[3], bfr[ks][j2][0], bfr[ks][j2][1]);
                    mma_f16(acc[i][2 * j2 + 1], a[0], a[1], a[2], a[3], bfr[ks][j2][2], bfr[ks][j2][3]);
                }
            }
        }
        cp_wait<STAGES - 2>();
        __syncthreads();
    }

#pragma unroll
    for (int i = 0; i < 4; i++) {
        int r0 = bm + wm + i * 16 + lr;
#pragma unroll
        for (int j = 0; j < 4; j++) {
            int colL = wn + j * 8 + lc * 2;
            int col = bn + colL;
            float v0 = acc[i][j][0];
            float v1 = acc[i][j][1];
            float v2 = acc[i][j][2];
            float v3 = acc[i][j][3];
            if (EPI != EPI_NONE) {
                v0 += sBias[colL]; v1 += sBias[colL + 1];
                v2 += sBias[colL]; v3 += sBias[colL + 1];
            }
            if (EPI == EPI_GELU) {
                v0 = v0 * 0.5f * (1.0f + erff(v0 * 0.70710678118654752f));
                v1 = v1 * 0.5f * (1.0f + erff(v1 * 0.70710678118654752f));
                v2 = v2 * 0.5f * (1.0f + erff(v2 * 0.70710678118654752f));
                v3 = v3 * 0.5f * (1.0f + erff(v3 * 0.70710678118654752f));
            }
            if (sizeof(OutT) == 4) {
                *(float2*)((float*)C + (size_t)r0 * Ndim + col)       = make_float2(v0, v1);
                *(float2*)((float*)C + (size_t)(r0 + 8) * Ndim + col) = make_float2(v2, v3);
            } else {
                *(__half2*)((__half*)C + (size_t)r0 * Ndim + col)       = __floats2half2_rn(v0, v1);
                *(__half2*)((__half*)C + (size_t)(r0 + 8) * Ndim + col) = __floats2half2_rn(v2, v3);
            }
        }
    }
}

template <int EPI, typename OutT>
__global__ __launch_bounds__(256, 2)
void tc_gemm_kernel(const __half* __restrict__ A, const __half* __restrict__ W,
                    const float* __restrict__ bias,
                    OutT* __restrict__ C, int Ndim, int Kdim) {
    extern __shared__ char dsm[];
    gemm_body<EPI, OutT>(A, W, bias, C, Ndim, Kdim, Kdim,
                         blockIdx.y * 128, blockIdx.x * 128, dsm);
}

__global__ __launch_bounds__(256, 2)
void qkv_gemm_kernel(const __half* __restrict__ A,
                     const __half* __restrict__ W0, const __half* __restrict__ W1, const __half* __restrict__ W2,
                     const float* __restrict__ b0, const float* __restrict__ b1, const float* __restrict__ b2,
                     __half* __restrict__ C0, __half* __restrict__ C1, __half* __restrict__ C2) {
    extern __shared__ char dsm[];
    const __half* W = (blockIdx.z == 0) ? W0 : (blockIdx.z == 1) ? W1 : W2;
    const float* bi = (blockIdx.z == 0) ? b0 : (blockIdx.z == 1) ? b1 : b2;
    __half* C = (blockIdx.z == 0) ? C0 : (blockIdx.z == 1) ? C1 : C2;
    gemm_body<EPI_BIAS, __half>(A, W, bi, C, CC, CC, CC,
                                blockIdx.y * 128, blockIdx.x * 128, dsm);
}

// split-K GEMM: grid (6, 32, 3); slice z: A cols / W rows offset z*kslice
__global__ __launch_bounds__(256, 2)
void splitk_gemm_kernel(const __half* __restrict__ A, const __half* __restrict__ W,
                        float* __restrict__ part, int Kdim, int Ndim) {
    extern __shared__ char dsm[];
    int z = blockIdx.z;
    int kslice = Kdim / 3;
    gemm_body<EPI_NONE, float>(A + z * kslice, W + (size_t)z * kslice * Ndim, nullptr,
                               part + (size_t)z * MM * CC, Ndim, Kdim, kslice,
                               blockIdx.y * 128, blockIdx.x * 128, dsm);
}

// ---------------- fp16 tensor-core flash attention ----------------
#define QSTR_H 72
#define KSTR_H 72
#define VSTR_H 72
#define ATT_Q_OFFH 0
#define ATT_K_OFFH (128 * QSTR_H)
#define ATT_V_OFFH (ATT_K_OFFH + 64 * KSTR_H)
#define ATT_HALVES (ATT_V_OFFH + 64 * VSTR_H)
#define ATTN_SMEM (ATT_HALVES * 2)          // 36,864 B

__global__ __launch_bounds__(256, 2)
void attn_tc_kernel(const __half* __restrict__ Q, const __half* __restrict__ K,
                    const __half* __restrict__ V, __half* __restrict__ Y) {
    extern __shared__ __half smh[];
    __half* Qs = smh + ATT_Q_OFFH;
    __half* Ks = smh + ATT_K_OFFH;
    __half* Vs = smh + ATT_V_OFFH;

    int tid = threadIdx.x;
    int lane = tid & 31;
    int wid = tid >> 5;
    int lr = lane >> 2;
    int lc = lane & 3;
    int wr = wid * 16;

    int bx = blockIdx.x;
    int qb = (bx < 4) ? ((bx * 2 + 1) * 128) : ((bx - 4) * 2 * 128);
    int bh = blockIdx.y;
    int b = bh / NH, h = bh % NH;
    size_t base = (size_t)b * TT * CC + (size_t)h * HD;

    uint32_t qFrag = smem_u32(Qs) + (uint32_t)((wr + (lane & 15)) * QSTR_H) * 2 + ((lane & 16) ? 16u : 0u);
    uint32_t kFrag = smem_u32(Ks) + (uint32_t)((lane & 7) * KSTR_H) * 2 + (uint32_t)(lane >> 3) * 16u;
    uint32_t vFrag = smem_u32(Vs) + (uint32_t)(((lane & 7) + ((lane >> 3) & 1) * 8) * VSTR_H) * 2
                   + ((lane & 16) ? 16u : 0u);

    {
        const __half2 sc = __float2half2_rn(0.125f);
        for (int i = tid; i < 128 * 8; i += 256) {
            int row = i >> 3, cg = (i & 7) * 8;
            uint4 u = *(const uint4*)(Q + base + (size_t)(qb + row) * CC + cg);
            __half2* hp = (__half2*)&u;
            hp[0] = __hmul2(hp[0], sc); hp[1] = __hmul2(hp[1], sc);
            hp[2] = __hmul2(hp[2], sc); hp[3] = __hmul2(hp[3], sc);
            *(uint4*)(Qs + row * QSTR_H + cg) = u;
        }
    }

    float o[8][4];
#pragma unroll
    for (int j = 0; j < 8; j++)
#pragma unroll
        for (int r = 0; r < 4; r++) o[j][r] = 0.f;

    float m0r = -1e30f, m1r = -1e30f;
    float l0r = 0.f, l1r = 0.f;

    int qmod = qb & 255;
    int rm0 = qmod + wr + lr;
    int rm1 = rm0 + 8;

    for (int kb = 0; kb < TT; kb += 64) {
        int kbm = kb & 255;
        if (kbm > qmod + 127) continue;
        __syncthreads();
        for (int i = tid; i < 64 * 8; i += 256) {
            int row = i >> 3, cg = (i & 7) * 8;
            *(uint4*)(Ks + row * KSTR_H + cg) = *(const uint4*)(K + base + (size_t)(kb + row) * CC + cg);
            *(uint4*)(Vs + row * VSTR_H + cg) = *(const uint4*)(V + base + (size_t)(kb + row) * CC + cg);
        }
        __syncthreads();

        float sacc[8][4];
#pragma unroll
        for (int j = 0; j < 8; j++)
#pragma unroll
            for (int r = 0; r < 4; r++) sacc[j][r] = 0.f;
#pragma unroll
        for (int kc = 0; kc < 2; kc++) {
            uint32_t bf[8][4];
#pragma unroll
            for (int j = 0; j < 8; j++)
                ldsm_x4(kFrag + (uint32_t)(j * 8 * KSTR_H) * 2 + kc * 64, bf[j]);
#pragma unroll
            for (int ksl = 0; ksl < 2; ksl++) {
                int ks = kc * 2 + ksl;
                uint32_t a[4];
                ldsm_x4(qFrag + ks * 32, a);
#pragma unroll
                for (int j = 0; j < 8; j++)
                    mma_f16(sacc[j], a[0], a[1], a[2], a[3], bf[j][2 * ksl], bf[j][2 * ksl + 1]);
            }
        }

        float m0 = -1e30f, m1 = -1e30f;
#pragma unroll
        for (int j = 0; j < 8; j++) {
            int c0 = kbm + j * 8 + 2 * lc;
            if (c0 > rm0)     sacc[j][0] = -1e30f;
            if (c0 + 1 > rm0) sacc[j][1] = -1e30f;
            if (c0 > rm1)     sacc[j][2] = -1e30f;
            if (c0 + 1 > rm1) sacc[j][3] = -1e30f;
            m0 = fmaxf(m0, fmaxf(sacc[j][0], sacc[j][1]));
            m1 = fmaxf(m1, fmaxf(sacc[j][2], sacc[j][3]));
        }
        m0 = fmaxf(m0, __shfl_xor_sync(0xffffffffu, m0, 1));
        m0 = fmaxf(m0, __shfl_xor_sync(0xffffffffu, m0, 2));
        m1 = fmaxf(m1, __shfl_xor_sync(0xffffffffu, m1, 1));
        m1 = fmaxf(m1, __shfl_xor_sync(0xffffffffu, m1, 2));

        float mn0 = fmaxf(m0r, m0), mn1 = fmaxf(m1r, m1);
        float al0 = __expf(m0r - mn0), al1 = __expf(m1r - mn1);
        m0r = mn0; m1r = mn1;

        uint32_t pa[4][4];
        float sum0 = 0.f, sum1 = 0.f;
#pragma unroll
        for (int ks = 0; ks < 4; ks++) {
#pragma unroll
            for (int jj = 0; jj < 2; jj++) {
                int j = 2 * ks + jj;
                float p00 = __expf(sacc[j][0] - mn0);
                float p01 = __expf(sacc[j][1] - mn0);
                float p10 = __expf(sacc[j][2] - mn1);
                float p11 = __expf(sacc[j][3] - mn1);
                sum0 += p00 + p01;
                sum1 += p10 + p11;
                pa[ks][2 * jj]     = h2pack(p00, p01);
                pa[ks][2 * jj + 1] = h2pack(p10, p11);
            }
        }
        sum0 += __shfl_xor_sync(0xffffffffu, sum0, 1);
        sum0 += __shfl_xor_sync(0xffffffffu, sum0, 2);
        sum1 += __shfl_xor_sync(0xffffffffu, sum1, 1);
        sum1 += __shfl_xor_sync(0xffffffffu, sum1, 2);
        l0r = l0r * al0 + sum0;
        l1r = l1r * al1 + sum1;

#pragma unroll
        for (int j = 0; j < 8; j++) {
            o[j][0] *= al0; o[j][1] *= al0; o[j][2] *= al1; o[j][3] *= al1;
        }

#pragma unroll
        for (int ks = 0; ks < 4; ks++) {
#pragma unroll
            for (int j2 = 0; j2 < 4; j2++) {
                uint32_t bv[4];
                ldsm_x4_trans(vFrag + (uint32_t)(ks * 16 * VSTR_H) * 2 + j2 * 32, bv);
                mma_f16(o[2 * j2],     pa[ks][0], pa[ks][1], pa[ks][2], pa[ks][3], bv[0], bv[1]);
                mma_f16(o[2 * j2 + 1], pa[ks][0], pa[ks][1], pa[ks][2], pa[ks][3], bv[2], bv[3]);
            }
        }
    }

    int r0 = wr + lr, r1 = r0 + 8;
    float inv0 = 1.0f / l0r;
    float inv1 = 1.0f / l1r;
#pragma unroll
    for (int j = 0; j < 8; j++) {
        int d = j * 8 + 2 * lc;
        *(__half2*)(Y + base + (size_t)(qb + r0) * CC + d) =
            __floats2half2_rn(o[j][0] * inv0, o[j][1] * inv0);
        *(__half2*)(Y + base + (size_t)(qb + r1) * CC + d) =
            __floats2half2_rn(o[j][2] * inv1, o[j][3] * inv1);
    }
}

// ---------------- host orchestration ----------------
extern "C" void kernel_launch(void* const* d_in, const int* in_sizes, int n_in,
                              void* d_out, int out_size) {
    const float* x     = (const float*)d_in[0];
    const float* ln1_g = (const float*)d_in[1];
    const float* ln1_b = (const float*)d_in[2];
    const float* Wq    = (const float*)d_in[3];
    const float* bq    = (const float*)d_in[4];
    const float* Wk    = (const float*)d_in[5];
    const float* bk    = (const float*)d_in[6];
    const float* Wv    = (const float*)d_in[7];
    const float* bv    = (const float*)d_in[8];
    const float* Wp    = (const float*)d_in[9];
    const float* bp    = (const float*)d_in[10];
    const float* ln2_g = (const float*)d_in[11];
    const float* ln2_b = (const float*)d_in[12];
    const float* W1    = (const float*)d_in[13];
    const float* b1    = (const float*)d_in[14];
    const float* W2    = (const float*)d_in[15];
    const float* b2    = (const float*)d_in[16];

    float *res, *part;
    __half *ln, *q, *k, *v, *y, *h1, *wt;
    cudaGetSymbolAddress((void**)&res,  g_res);
    cudaGetSymbolAddress((void**)&part, g_part);
    cudaGetSymbolAddress((void**)&ln,  g_ln);
    cudaGetSymbolAddress((void**)&q,   g_q);
    cudaGetSymbolAddress((void**)&k,   g_k);
    cudaGetSymbolAddress((void**)&v,   g_v);
    cudaGetSymbolAddress((void**)&y,   g_y);
    cudaGetSymbolAddress((void**)&h1,  g_h1);
    cudaGetSymbolAddress((void**)&wt,  g_wt);

    cudaFuncSetAttribute(attn_tc_kernel, cudaFuncAttributeMaxDynamicSharedMemorySize, ATTN_SMEM);
    cudaFuncSetAttribute(tc_gemm_kernel<EPI_GELU, __half>,  cudaFuncAttributeMaxDynamicSharedMemorySize, GEMM_SMEM_BYTES);
    cudaFuncSetAttribute(qkv_gemm_kernel,                   cudaFuncAttributeMaxDynamicSharedMemorySize, GEMM_SMEM_BYTES);
    cudaFuncSetAttribute(splitk_gemm_kernel,                cudaFuncAttributeMaxDynamicSharedMemorySize, GEMM_SMEM_BYTES);

    // ---- one-shot convert of all weights to half (natural layout) ----
    conv_all_kernel<<<(N4_ALL + 255) / 256, 256>>>(Wq, Wk, Wv, Wp, W1, W2, wt);

    dim3 gemm_qkv3(CC / 128, MM / 128, 3);   // 576
    dim3 gemm_h   (HID / 128, MM / 128);     // 768
    dim3 gemm_sk  (CC / 128, MM / 128, 3);   // 576 (split-K)
    dim3 attn_grid(TT / 128, BB * NH);       // 384

    for (int l = 0; l < LNUM; l++) {
        const __half* wq = wt + WQ_OFF + (size_t)l * CC * CC;
        const __half* wk = wt + WK_OFF + (size_t)l * CC * CC;
        const __half* wv = wt + WV_OFF + (size_t)l * CC * CC;
        const __half* wp = wt + WP_OFF + (size_t)l * CC * CC;
        const __half* w1 = wt + W1_OFF + (size_t)l * CC * HID;
        const __half* w2 = wt + W2_OFF + (size_t)l * HID * CC;

        const float* resIn = (l == 0) ? x : res;

        if (l == 0) {
            ln_kernel<<<MM / 8, 256>>>(x, ln1_g, ln1_b, ln);
        } else {
            ln_reduce_kernel<<<MM / 8, 256>>>(part, b2 + (size_t)(l - 1) * CC, res, res,
                                              ln1_g + (size_t)l * CC, ln1_b + (size_t)l * CC, ln);
        }
        qkv_gemm_kernel<<<gemm_qkv3, 256, GEMM_SMEM_BYTES>>>(
            ln, wq, wk, wv, bq + (size_t)l*CC, bk + (size_t)l*CC, bv + (size_t)l*CC, q, k, v);
        attn_tc_kernel<<<attn_grid, 256, ATTN_SMEM>>>(q, k, v, y);
        splitk_gemm_kernel<<<gemm_sk, 256, GEMM_SMEM_BYTES>>>(y, wp, part, CC, CC);
        ln_reduce_kernel<<<MM / 8, 256>>>(part, bp + (size_t)l * CC, resIn, res,
                                          ln2_g + (size_t)l * CC, ln2_b + (size_t)l * CC, ln);
        tc_gemm_kernel<EPI_GELU, __half><<<gemm_h, 256, GEMM_SMEM_BYTES>>>(
            ln, w1, b1 + (size_t)l*HID, h1, HID, CC);
        splitk_gemm_kernel<<<gemm_sk, 256, GEMM_SMEM_BYTES>>>(h1, w2, part, HID, CC);
    }

    // final: out = sum(partials) + b2[3] + res
    {
        int n4 = MM * CC / 4;
        reduce_out_kernel<<<(n4 + 255) / 256, 256>>>(part, b2 + (size_t)3 * CC, res, (float*)d_out);
    }
}

// round 17
// speedup vs baseline: 2.2887x; 1.0553x over previous
#include <cuda_runtime.h>
#include <cuda_fp16.h>
#include <math.h>
#include <cstdint>

// ---------------- problem constants ----------------
#define LNUM 4
#define BB   4
#define TT   1024
#define CC   768
#define NH   12
#define HD   64
#define HID  3072
#define MM   (BB*TT)          // 4096 rows
#define EPS_LN 1e-5f

// ---------------- scratch (device globals; no allocation allowed) ----------------
__device__ float  g_res [(size_t)MM*CC];
__device__ __half g_ln  [(size_t)MM*CC];
__device__ __half g_q   [(size_t)MM*CC];
__device__ __half g_k   [(size_t)MM*CC];
__device__ __half g_v   [(size_t)MM*CC];
__device__ __half g_y   [(size_t)MM*CC];
__device__ __half g_h1  [(size_t)MM*HID];
__device__ float  g_part[3 * (size_t)MM*CC];   // split-K partials
// half weights in NATURAL [K][N] layout (no transpose)
#define WQ_OFF 0
#define WK_OFF (WQ_OFF + (size_t)LNUM*CC*CC)
#define WV_OFF (WK_OFF + (size_t)LNUM*CC*CC)
#define WP_OFF (WV_OFF + (size_t)LNUM*CC*CC)
#define W1_OFF (WP_OFF + (size_t)LNUM*CC*CC)
#define W2_OFF (W1_OFF + (size_t)LNUM*CC*HID)
#define WT_TOTAL (W2_OFF + (size_t)LNUM*CC*HID)
__device__ __half g_wt [WT_TOTAL];

// ---------------- helpers ----------------
__device__ __forceinline__ uint32_t smem_u32(const void* p) {
    uint32_t a;
    asm("{ .reg .u64 t; cvta.to.shared.u64 t, %1; cvt.u32.u64 %0, t; }" : "=r"(a) : "l"(p));
    return a;
}
__device__ __forceinline__ void cp_async16(uint32_t dst, const void* src) {
    asm volatile("cp.async.cg.shared.global [%0], [%1], 16;" :: "r"(dst), "l"(src));
}
#define CP_COMMIT() asm volatile("cp.async.commit_group;" ::: "memory")
template <int N>
__device__ __forceinline__ void cp_wait() {
    asm volatile("cp.async.wait_group %0;" :: "n"(N) : "memory");
}
__device__ __forceinline__ void mma_f16(float* d, uint32_t a0, uint32_t a1, uint32_t a2,
                                        uint32_t a3, uint32_t b0, uint32_t b1) {
    asm volatile(
        "mma.sync.aligned.m16n8k16.row.col.f32.f16.f16.f32 "
        "{%0,%1,%2,%3}, {%4,%5,%6,%7}, {%8,%9}, {%0,%1,%2,%3};"
        : "+f"(d[0]), "+f"(d[1]), "+f"(d[2]), "+f"(d[3])
        : "r"(a0), "r"(a1), "r"(a2), "r"(a3), "r"(b0), "r"(b1));
}
__device__ __forceinline__ void ldsm_x4(uint32_t addr, uint32_t* r) {
    asm volatile("ldmatrix.sync.aligned.m8n8.x4.shared.b16 {%0,%1,%2,%3}, [%4];"
        : "=r"(r[0]), "=r"(r[1]), "=r"(r[2]), "=r"(r[3]) : "r"(addr));
}
__device__ __forceinline__ void ldsm_x4_trans(uint32_t addr, uint32_t* r) {
    asm volatile("ldmatrix.sync.aligned.m8n8.x4.trans.shared.b16 {%0,%1,%2,%3}, [%4];"
        : "=r"(r[0]), "=r"(r[1]), "=r"(r[2]), "=r"(r[3]) : "r"(addr));
}
__device__ __forceinline__ uint32_t h2pack(float a, float b) {
    __half2 h = __floats2half2_rn(a, b);
    return *(uint32_t*)&h;
}

// ---------------- small kernels ----------------
#define R_SM  (LNUM * CC * CC / 4)
#define R_BG  (LNUM * CC * HID / 4)
#define N4_ALL (4 * R_SM + 2 * R_BG)
__global__ void conv_all_kernel(const float* __restrict__ wq, const float* __restrict__ wk,
                                const float* __restrict__ wv, const float* __restrict__ wp,
                                const float* __restrict__ w1, const float* __restrict__ w2,
                                __half* __restrict__ dst) {
    int i = blockIdx.x * blockDim.x + threadIdx.x;
    if (i >= N4_ALL) return;
    const float* src;
    int off;
    if (i < 2 * R_SM) {
        if (i < R_SM)       { src = wq; off = i; }
        else                { src = wk; off = i - R_SM; }
    } else if (i < 4 * R_SM) {
        if (i < 3 * R_SM)   { src = wv; off = i - 2 * R_SM; }
        else                { src = wp; off = i - 3 * R_SM; }
    } else if (i < 4 * R_SM + R_BG) { src = w1; off = i - 4 * R_SM; }
    else                            { src = w2; off = i - 4 * R_SM - R_BG; }
    float4 v = ((const float4*)src)[off];
    uint2 o;
    o.x = h2pack(v.x, v.y);
    o.y = h2pack(v.z, v.w);
    ((uint2*)dst)[i] = o;
}

// layernorm: one warp per row
__global__ __launch_bounds__(256)
void ln_kernel(const float* __restrict__ x, const float* __restrict__ g,
               const float* __restrict__ b, __half* __restrict__ out) {
    int lane = threadIdx.x & 31;
    int wrow = threadIdx.x >> 5;
    int row = blockIdx.x * 8 + wrow;
    const float* xr = x + (size_t)row * CC;

    float4 v[6];
    float s = 0.f, s2 = 0.f;
#pragma unroll
    for (int i = 0; i < 6; i++) {
        v[i] = *(const float4*)(xr + i * 128 + lane * 4);
        s  += v[i].x + v[i].y + v[i].z + v[i].w;
        s2 += v[i].x * v[i].x + v[i].y * v[i].y + v[i].z * v[i].z + v[i].w * v[i].w;
    }
#pragma unroll
    for (int o = 16; o; o >>= 1) {
        s  += __shfl_xor_sync(0xffffffffu, s,  o);
        s2 += __shfl_xor_sync(0xffffffffu, s2, o);
    }
    float mu  = s * (1.f / CC);
    float var = s2 * (1.f / CC) - mu * mu;
    float rs  = rsqrtf(var + EPS_LN);

    __half* outr = out + (size_t)row * CC;
#pragma unroll
    for (int i = 0; i < 6; i++) {
        int c = i * 128 + lane * 4;
        float4 gv = *(const float4*)(g + c);
        float4 bv = *(const float4*)(b + c);
        uint2 o2;
        o2.x = h2pack((v[i].x - mu) * rs * gv.x + bv.x, (v[i].y - mu) * rs * gv.y + bv.y);
        o2.y = h2pack((v[i].z - mu) * rs * gv.z + bv.z, (v[i].w - mu) * rs * gv.w + bv.w);
        *(uint2*)(outr + c) = o2;
    }
}

// fused: resDst = p0+p1+p2 + bias + resSrc, then LN(resDst) -> out (half)
__global__ __launch_bounds__(256)
void ln_reduce_kernel(const float* __restrict__ p, const float* __restrict__ bias,
                      const float* __restrict__ resSrc, float* __restrict__ resDst,
                      const float* __restrict__ g, const float* __restrict__ b,
                      __half* __restrict__ out) {
    int lane = threadIdx.x & 31;
    int wrow = threadIdx.x >> 5;
    int row = blockIdx.x * 8 + wrow;
    size_t roff = (size_t)row * CC;
    const float* p0 = p + roff;
    const float* p1 = p + (size_t)MM * CC + roff;
    const float* p2 = p + 2 * (size_t)MM * CC + roff;
    const float* rs_ = resSrc + roff;
    float* rd = resDst + roff;

    float4 v[6];
    float s = 0.f, s2 = 0.f;
#pragma unroll
    for (int i = 0; i < 6; i++) {
        int c = i * 128 + lane * 4;
        float4 a0 = *(const float4*)(p0 + c);
        float4 a1 = *(const float4*)(p1 + c);
        float4 a2 = *(const float4*)(p2 + c);
        float4 rv = *(const float4*)(rs_ + c);
        float4 bb = *(const float4*)(bias + c);
        v[i].x = a0.x + a1.x + a2.x + bb.x + rv.x;
        v[i].y = a0.y + a1.y + a2.y + bb.y + rv.y;
        v[i].z = a0.z + a1.z + a2.z + bb.z + rv.z;
        v[i].w = a0.w + a1.w + a2.w + bb.w + rv.w;
        *(float4*)(rd + c) = v[i];
        s  += v[i].x + v[i].y + v[i].z + v[i].w;
        s2 += v[i].x * v[i].x + v[i].y * v[i].y + v[i].z * v[i].z + v[i].w * v[i].w;
    }
#pragma unroll
    for (int o = 16; o; o >>= 1) {
        s  += __shfl_xor_sync(0xffffffffu, s,  o);
        s2 += __shfl_xor_sync(0xffffffffu, s2, o);
    }
    float mu  = s * (1.f / CC);
    float var = s2 * (1.f / CC) - mu * mu;
    float rs  = rsqrtf(var + EPS_LN);

    __half* outr = out + roff;
#pragma unroll
    for (int i = 0; i < 6; i++) {
        int c = i * 128 + lane * 4;
        float4 gv = *(const float4*)(g + c);
        float4 bv = *(const float4*)(b + c);
        uint2 o2;
        o2.x = h2pack((v[i].x - mu) * rs * gv.x + bv.x, (v[i].y - mu) * rs * gv.y + bv.y);
        o2.y = h2pack((v[i].z - mu) * rs * gv.z + bv.z, (v[i].w - mu) * rs * gv.w + bv.w);
        *(uint2*)(outr + c) = o2;
    }
}

// final-layer reduce: out = p0+p1+p2 + bias + res
__global__ void reduce_out_kernel(const float* __restrict__ p, const float* __restrict__ bias,
                                  const float* __restrict__ res, float* __restrict__ out) {
    int i = blockIdx.x * blockDim.x + threadIdx.x;
    int n4 = MM * CC / 4;
    if (i >= n4) return;
    int c4 = i % (CC / 4);
    float4 a0 = ((const float4*)p)[i];
    float4 a1 = ((const float4*)(p + (size_t)MM * CC))[i];
    float4 a2 = ((const float4*)(p + 2 * (size_t)MM * CC))[i];
    float4 rv = ((const float4*)res)[i];
    float4 bb = ((const float4*)bias)[c4];
    float4 o;
    o.x = a0.x + a1.x + a2.x + rv.x + bb.x;
    o.y = a0.y + a1.y + a2.y + rv.y + bb.y;
    o.z = a0.z + a1.z + a2.z + rv.z + bb.z;
    o.w = a0.w + a1.w + a2.w + rv.w + bb.w;
    ((float4*)out)[i] = o;
}

// ---------------- fp16 mma.sync GEMM (unchanged from R16) ----------------
#define EPI_BIAS  0
#define EPI_GELU  2
#define EPI_NONE  3

#define STAGES 4
#define BK 32
#define ASTR_H 40
#define BSTR_H 136
#define A_STG_H (128 * ASTR_H)
#define B_STG_H (32 * BSTR_H)
#define GEMM_SMEM_BYTES (STAGES * (A_STG_H + B_STG_H) * 2 + 512)   // 76,288 B

template <int EPI, typename OutT>
__device__ __forceinline__ void gemm_body(const __half* __restrict__ A, const __half* __restrict__ W,
                                          const float* __restrict__ bias,
                                          OutT* __restrict__ C, int Ndim, int Kstride, int Klen,
                                          int bm, int bn, char* dsm) {
    __half* sA = (__half*)dsm;
    __half* sB = (__half*)dsm + STAGES * A_STG_H;
    float* sBias = (float*)(dsm + STAGES * (A_STG_H + B_STG_H) * 2);

    int tid = threadIdx.x;
    int lane = tid & 31;
    int wid = tid >> 5;

    if (EPI != EPI_NONE && tid < 128) sBias[tid] = bias[bn + tid];

    int lr = lane >> 2;
    int lc = lane & 3;
    int wm = (wid & 1) * 64;
    int wn = (wid >> 1) * 32;

    int idx0 = tid * 2, idx1 = tid * 2 + 1;
    int aR0 = idx0 >> 2, aS0 = (idx0 & 3) * 8;
    int aR1 = idx1 >> 2, aS1 = (idx1 & 3) * 8;
    int bK0 = idx0 >> 4, bN0 = (idx0 & 15) * 8;
    int bK1 = idx1 >> 4, bN1 = (idx1 & 15) * 8;

    uint32_t sA_base = smem_u32(sA);
    uint32_t sB_base = smem_u32(sB);
    uint32_t aFrag = sA_base + (uint32_t)((wm + (lane & 15)) * ASTR_H) * 2 + ((lane & 16) ? 16u : 0u);
    uint32_t bFrag = sB_base + (uint32_t)(((lane & 7) + ((lane >> 3) & 1) * 8) * BSTR_H) * 2
                   + (uint32_t)(wn + ((lane & 16) ? 8 : 0)) * 2;

    const __half* aSrc0 = A + (size_t)(bm + aR0) * Kstride + aS0;
    const __half* aSrc1 = A + (size_t)(bm + aR1) * Kstride + aS1;
    const __half* bSrc0 = W + (size_t)bK0 * Ndim + bn + bN0;
    const __half* bSrc1 = W + (size_t)bK1 * Ndim + bn + bN1;

    float acc[4][4][4];
#pragma unroll
    for (int i = 0; i < 4; i++)
#pragma unroll
        for (int j = 0; j < 4; j++)
#pragma unroll
            for (int r = 0; r < 4; r++) acc[i][j][r] = 0.f;

    int nch = Klen / BK;

    auto load_stage = [&](int stg, int chunk) {
        int k0 = chunk * BK;
        uint32_t ab = sA_base + (uint32_t)(stg * A_STG_H) * 2;
        uint32_t bb = sB_base + (uint32_t)(stg * B_STG_H) * 2;
        cp_async16(ab + (uint32_t)(aR0 * ASTR_H + aS0) * 2, aSrc0 + k0);
        cp_async16(ab + (uint32_t)(aR1 * ASTR_H + aS1) * 2, aSrc1 + k0);
        cp_async16(bb + (uint32_t)(bK0 * BSTR_H + bN0) * 2, bSrc0 + (size_t)k0 * Ndim);
        cp_async16(bb + (uint32_t)(bK1 * BSTR_H + bN1) * 2, bSrc1 + (size_t)k0 * Ndim);
    };

#pragma unroll
    for (int s = 0; s < STAGES - 1; s++) {
        if (s < nch) load_stage(s, s);
        CP_COMMIT();
    }
    cp_wait<STAGES - 2>();
    __syncthreads();

    for (int c = 0; c < nch; c++) {
        int buf = c % STAGES;
        int nc = c + STAGES - 1;
        if (nc < nch) load_stage(nc % STAGES, nc);
        CP_COMMIT();

        uint32_t aStage = aFrag + (uint32_t)(buf * A_STG_H) * 2;
        uint32_t bStage = bFrag + (uint32_t)(buf * B_STG_H) * 2;

        uint32_t bfr[2][2][4];
#pragma unroll
        for (int ks = 0; ks < 2; ks++)
#pragma unroll
            for (int j2 = 0; j2 < 2; j2++)
                ldsm_x4_trans(bStage + (uint32_t)(ks * 16 * BSTR_H) * 2 + j2 * 32, bfr[ks][j2]);

#pragma unroll
        for (int ks = 0; ks < 2; ks++) {
#pragma unroll
            for (int i = 0; i < 4; i++) {
                uint32_t a[4];
                ldsm_x4(aStage + (uint32_t)(i * 16 * ASTR_H) * 2 + ks * 32, a);
#pragma unroll
                for (int j2 = 0; j2 < 2; j2++) {
                    mma_f16(acc[i][2 * j2],     a[0], a[1], a[2], a[3], bfr[ks][j2][0], bfr[ks][j2][1]);
                    mma_f16(acc[i][2 * j2 + 1], a[0], a[1], a[2], a[3], bfr[ks][j2][2], bfr[ks][j2][3]);
                }
            }
        }
        cp_wait<STAGES - 2>();
        __syncthreads();
    }

#pragma unroll
    for (int i = 0; i < 4; i++) {
        int r0 = bm + wm + i * 16 + lr;
#pragma unroll
        for (int j = 0; j < 4; j++) {
            int colL = wn + j * 8 + lc * 2;
            int col = bn + colL;
            float v0 = acc[i][j][0];
            float v1 = acc[i][j][1];
            float v2 = acc[i][j][2];
            float v3 = acc[i][j][3];
            if (EPI != EPI_NONE) {
                v0 += sBias[colL]; v1 += sBias[colL + 1];
                v2 += sBias[colL]; v3 += sBias[colL + 1];
            }
            if (EPI == EPI_GELU) {
                v0 = v0 * 0.5f * (1.0f + erff(v0 * 0.70710678118654752f));
                v1 = v1 * 0.5f * (1.0f + erff(v1 * 0.70710678118654752f));
                v2 = v2 * 0.5f * (1.0f + erff(v2 * 0.70710678118654752f));
                v3 = v3 * 0.5f * (1.0f + erff(v3 * 0.70710678118654752f));
            }
            if (sizeof(OutT) == 4) {
                *(float2*)((float*)C + (size_t)r0 * Ndim + col)       = make_float2(v0, v1);
                *(float2*)((float*)C + (size_t)(r0 + 8) * Ndim + col) = make_float2(v2, v3);
            } else {
                *(__half2*)((__half*)C + (size_t)r0 * Ndim + col)       = __floats2half2_rn(v0, v1);
                *(__half2*)((__half*)C + (size_t)(r0 + 8) * Ndim + col) = __floats2half2_rn(v2, v3);
            }
        }
    }
}

template <int EPI, typename OutT>
__global__ __launch_bounds__(256, 2)
void tc_gemm_kernel(const __half* __restrict__ A, const __half* __restrict__ W,
                    const float* __restrict__ bias,
                    OutT* __restrict__ C, int Ndim, int Kdim) {
    extern __shared__ char dsm[];
    gemm_body<EPI, OutT>(A, W, bias, C, Ndim, Kdim, Kdim,
                         blockIdx.y * 128, blockIdx.x * 128, dsm);
}

__global__ __launch_bounds__(256, 2)
void qkv_gemm_kernel(const __half* __restrict__ A,
                     const __half* __restrict__ W0, const __half* __restrict__ W1, const __half* __restrict__ W2,
                     const float* __restrict__ b0, const float* __restrict__ b1, const float* __restrict__ b2,
                     __half* __restrict__ C0, __half* __restrict__ C1, __half* __restrict__ C2) {
    extern __shared__ char dsm[];
    const __half* W = (blockIdx.z == 0) ? W0 : (blockIdx.z == 1) ? W1 : W2;
    const float* bi = (blockIdx.z == 0) ? b0 : (blockIdx.z == 1) ? b1 : b2;
    __half* C = (blockIdx.z == 0) ? C0 : (blockIdx.z == 1) ? C1 : C2;
    gemm_body<EPI_BIAS, __half>(A, W, bi, C, CC, CC, CC,
                                blockIdx.y * 128, blockIdx.x * 128, dsm);
}

__global__ __launch_bounds__(256, 2)
void splitk_gemm_kernel(const __half* __restrict__ A, const __half* __restrict__ W,
                        float* __restrict__ part, int Kdim, int Ndim) {
    extern __shared__ char dsm[];
    int z = blockIdx.z;
    int kslice = Kdim / 3;
    gemm_body<EPI_NONE, float>(A + z * kslice, W + (size_t)z * kslice * Ndim, nullptr,
                               part + (size_t)z * MM * CC, Ndim, Kdim, kslice,
                               blockIdx.y * 128, blockIdx.x * 128, dsm);
}

// ---------------- fp16 flash attention, cp.async double-buffered K/V ----------------
#define QSTR_H 72
#define KSTR_H 72
#define VSTR_H 72
#define KV_TILE_H (64 * KSTR_H)          // 4608 halfs per K (or V) tile
#define ATT_Q_OFFH 0
#define ATT_K_OFFH (128 * QSTR_H)                        // 9216
#define ATT_V_OFFH (ATT_K_OFFH + 2 * KV_TILE_H)          // 18432
#define ATT_HALVES (ATT_V_OFFH + 2 * KV_TILE_H)          // 27648
#define ATTN_SMEM (ATT_HALVES * 2)                       // 55,296 B

__global__ __launch_bounds__(256, 2)
void attn_tc_kernel(const __half* __restrict__ Q, const __half* __restrict__ K,
                    const __half* __restrict__ V, __half* __restrict__ Y) {
    extern __shared__ __half smh[];
    __half* Qs = smh + ATT_Q_OFFH;

    int tid = threadIdx.x;
    int lane = tid & 31;
    int wid = tid >> 5;
    int lr = lane >> 2;
    int lc = lane & 3;
    int wr = wid * 16;

    // heavy-tile-first scheduling
    int bx = blockIdx.x;
    int qb = (bx < 4) ? ((bx * 2 + 1) * 128) : ((bx - 4) * 2 * 128);
    int bh = blockIdx.y;
    int b = bh / NH, h = bh % NH;
    size_t base = (size_t)b * TT * CC + (size_t)h * HD;

    uint32_t kBase = smem_u32(smh + ATT_K_OFFH);
    uint32_t vBase = smem_u32(smh + ATT_V_OFFH);
    uint32_t qFrag = smem_u32(Qs) + (uint32_t)((wr + (lane & 15)) * QSTR_H) * 2 + ((lane & 16) ? 16u : 0u);
    uint32_t kFragOff = (uint32_t)((lane & 7) * KSTR_H) * 2 + (uint32_t)(lane >> 3) * 16u;
    uint32_t vFragOff = (uint32_t)(((lane & 7) + ((lane >> 3) & 1) * 8) * VSTR_H) * 2
                      + ((lane & 16) ? 16u : 0u);

    // cp.async K/V tile loader: 2 chunks each of K and V per thread
    int ldRow0 = tid >> 3,            ldCg0 = (tid & 7) * 8;
    int ldRow1 = (tid + 256) >> 3,    ldCg1 = (tid & 7) * 8;
    auto load_kv = [&](int kb, int buf) {
        uint32_t kB = kBase + (uint32_t)(buf * KV_TILE_H) * 2;
        uint32_t vB = vBase + (uint32_t)(buf * KV_TILE_H) * 2;
        const __half* kSrc = K + base + (size_t)kb * CC;
        const __half* vSrc = V + base + (size_t)kb * CC;
        cp_async16(kB + (uint32_t)(ldRow0 * KSTR_H + ldCg0) * 2, kSrc + (size_t)ldRow0 * CC + ldCg0);
        cp_async16(kB + (uint32_t)(ldRow1 * KSTR_H + ldCg1) * 2, kSrc + (size_t)ldRow1 * CC + ldCg1);
        cp_async16(vB + (uint32_t)(ldRow0 * VSTR_H + ldCg0) * 2, vSrc + (size_t)ldRow0 * CC + ldCg0);
        cp_async16(vB + (uint32_t)(ldRow1 * VSTR_H + ldCg1) * 2, vSrc + (size_t)ldRow1 * CC + ldCg1);
    };

    int qmod = qb & 255;
    // valid k-tile list
    int kbs[16], nkb = 0;
    for (int kb = 0; kb < TT; kb += 64)
        if ((kb & 255) <= qmod + 127) kbs[nkb++] = kb;

    // prefetch tile 0 while loading Q
    load_kv(kbs[0], 0);
    CP_COMMIT();
    {
        const __half2 sc = __float2half2_rn(0.125f);
        for (int i = tid; i < 128 * 8; i += 256) {
            int row = i >> 3, cg = (i & 7) * 8;
            uint4 u = *(const uint4*)(Q + base + (size_t)(qb + row) * CC + cg);
            __half2* hp = (__half2*)&u;
            hp[0] = __hmul2(hp[0], sc); hp[1] = __hmul2(hp[1], sc);
            hp[2] = __hmul2(hp[2], sc); hp[3] = __hmul2(hp[3], sc);
            *(uint4*)(Qs + row * QSTR_H + cg) = u;
        }
    }
    cp_wait<0>();
    __syncthreads();

    float o[8][4];
#pragma unroll
    for (int j = 0; j < 8; j++)
#pragma unroll
        for (int r = 0; r < 4; r++) o[j][r] = 0.f;

    float m0r = -1e30f, m1r = -1e30f;
    float l0r = 0.f, l1r = 0.f;

    int rm0 = qmod + wr + lr;
    int rm1 = rm0 + 8;

    for (int it = 0; it < nkb; it++) {
        int buf = it & 1;
        int kbm = kbs[it] & 255;
        // prefetch next tile into the other buffer (safe: drained at prior barrier)
        if (it + 1 < nkb) { load_kv(kbs[it + 1], buf ^ 1); CP_COMMIT(); }

        uint32_t kFrag = kBase + (uint32_t)(buf * KV_TILE_H) * 2 + kFragOff;
        uint32_t vFrag = vBase + (uint32_t)(buf * KV_TILE_H) * 2 + vFragOff;

        // ---- S = Q K^T ----
        float sacc[8][4];
#pragma unroll
        for (int j = 0; j < 8; j++)
#pragma unroll
            for (int r = 0; r < 4; r++) sacc[j][r] = 0.f;
#pragma unroll
        for (int kc = 0; kc < 2; kc++) {
            uint32_t bf[8][4];
#pragma unroll
            for (int j = 0; j < 8; j++)
                ldsm_x4(kFrag + (uint32_t)(j * 8 * KSTR_H) * 2 + kc * 64, bf[j]);
#pragma unroll
            for (int ksl = 0; ksl < 2; ksl++) {
                int ks = kc * 2 + ksl;
                uint32_t a[4];
                ldsm_x4(qFrag + ks * 32, a);
#pragma unroll
                for (int j = 0; j < 8; j++)
                    mma_f16(sacc[j], a[0], a[1], a[2], a[3], bf[j][2 * ksl], bf[j][2 * ksl + 1]);
            }
        }

        // ---- mask + online softmax (registers) ----
        float m0 = -1e30f, m1 = -1e30f;
#pragma unroll
        for (int j = 0; j < 8; j++) {
            int c0 = kbm + j * 8 + 2 * lc;
            if (c0 > rm0)     sacc[j][0] = -1e30f;
            if (c0 + 1 > rm0) sacc[j][1] = -1e30f;
            if (c0 > rm1)     sacc[j][2] = -1e30f;
            if (c0 + 1 > rm1) sacc[j][3] = -1e30f;
            m0 = fmaxf(m0, fmaxf(sacc[j][0], sacc[j][1]));
            m1 = fmaxf(m1, fmaxf(sacc[j][2], sacc[j][3]));
        }
        m0 = fmaxf(m0, __shfl_xor_sync(0xffffffffu, m0, 1));
        m0 = fmaxf(m0, __shfl_xor_sync(0xffffffffu, m0, 2));
        m1 = fmaxf(m1, __shfl_xor_sync(0xffffffffu, m1, 1));
        m1 = fmaxf(m1, __shfl_xor_sync(0xffffffffu, m1, 2));

        float mn0 = fmaxf(m0r, m0), mn1 = fmaxf(m1r, m1);
        float al0 = __expf(m0r - mn0), al1 = __expf(m1r - mn1);
        m0r = mn0; m1r = mn1;

        uint32_t pa[4][4];
        float sum0 = 0.f, sum1 = 0.f;
#pragma unroll
        for (int ks = 0; ks < 4; ks++) {
#pragma unroll
            for (int jj = 0; jj < 2; jj++) {
                int j = 2 * ks + jj;
                float p00 = __expf(sacc[j][0] - mn0);
                float p01 = __expf(sacc[j][1] - mn0);
                float p10 = __expf(sacc[j][2] - mn1);
                float p11 = __expf(sacc[j][3] - mn1);
                sum0 += p00 + p01;
                sum1 += p10 + p11;
                pa[ks][2 * jj]     = h2pack(p00, p01);
                pa[ks][2 * jj + 1] = h2pack(p10, p11);
            }
        }
        sum0 += __shfl_xor_sync(0xffffffffu, sum0, 1);
        sum0 += __shfl_xor_sync(0xffffffffu, sum0, 2);
        sum1 += __shfl_xor_sync(0xffffffffu, sum1, 1);
        sum1 += __shfl_xor_sync(0xffffffffu, sum1, 2);
        l0r = l0r * al0 + sum0;
        l1r = l1r * al1 + sum1;

#pragma unroll
        for (int j = 0; j < 8; j++) {
            o[j][0] *= al0; o[j][1] *= al0; o[j][2] *= al1; o[j][3] *= al1;
        }

        // ---- O += P V ----
#pragma unroll
        for (int ks = 0; ks < 4; ks++) {
#pragma unroll
            for (int j2 = 0; j2 < 4; j2++) {
                uint32_t bv[4];
                ldsm_x4_trans(vFrag + (uint32_t)(ks * 16 * VSTR_H) * 2 + j2 * 32, bv);
                mma_f16(o[2 * j2],     pa[ks][0], pa[ks][1], pa[ks][2], pa[ks][3], bv[0], bv[1]);
                mma_f16(o[2 * j2 + 1], pa[ks][0], pa[ks][1], pa[ks][2], pa[ks][3], bv[2], bv[3]);
            }
        }

        // wait next tile's data + drain this buffer before it gets overwritten
        if (it + 1 < nkb) cp_wait<0>();
        __syncthreads();
    }

    int r0 = wr + lr, r1 = r0 + 8;
    float inv0 = 1.0f / l0r;
    float inv1 = 1.0f / l1r;
#pragma unroll
    for (int j = 0; j < 8; j++) {
        int d = j * 8 + 2 * lc;
        *(__half2*)(Y + base + (size_t)(qb + r0) * CC + d) =
            __floats2half2_rn(o[j][0] * inv0, o[j][1] * inv0);
        *(__half2*)(Y + base + (size_t)(qb + r1) * CC + d) =
            __floats2half2_rn(o[j][2] * inv1, o[j][3] * inv1);
    }
}

// ---------------- host orchestration ----------------
extern "C" void kernel_launch(void* const* d_in, const int* in_sizes, int n_in,
                              void* d_out, int out_size) {
    const float* x     = (const float*)d_in[0];
    const float* ln1_g = (const float*)d_in[1];
    const float* ln1_b = (const float*)d_in[2];
    const float* Wq    = (const float*)d_in[3];
    const float* bq    = (const float*)d_in[4];
    const float* Wk    = (const float*)d_in[5];
    const float* bk    = (const float*)d_in[6];
    const float* Wv    = (const float*)d_in[7];
    const float* bv    = (const float*)d_in[8];
    const float* Wp    = (const float*)d_in[9];
    const float* bp    = (const float*)d_in[10];
    const float* ln2_g = (const float*)d_in[11];
    const float* ln2_b = (const float*)d_in[12];
    const float* W1    = (const float*)d_in[13];
    const float* b1    = (const float*)d_in[14];
    const float* W2    = (const float*)d_in[15];
    const float* b2    = (const float*)d_in[16];

    float *res, *part;
    __half *ln, *q, *k, *v, *y, *h1, *wt;
    cudaGetSymbolAddress((void**)&res,  g_res);
    cudaGetSymbolAddress((void**)&part, g_part);
    cudaGetSymbolAddress((void**)&ln,  g_ln);
    cudaGetSymbolAddress((void**)&q,   g_q);
    cudaGetSymbolAddress((void**)&k,   g_k);
    cudaGetSymbolAddress((void**)&v,   g_v);
    cudaGetSymbolAddress((void**)&y,   g_y);
    cudaGetSymbolAddress((void**)&h1,  g_h1);
    cudaGetSymbolAddress((void**)&wt,  g_wt);

    cudaFuncSetAttribute(attn_tc_kernel, cudaFuncAttributeMaxDynamicSharedMemorySize, ATTN_SMEM);
    cudaFuncSetAttribute(tc_gemm_kernel<EPI_GELU, __half>,  cudaFuncAttributeMaxDynamicSharedMemorySize, GEMM_SMEM_BYTES);
    cudaFuncSetAttribute(qkv_gemm_kernel,                   cudaFuncAttributeMaxDynamicSharedMemorySize, GEMM_SMEM_BYTES);
    cudaFuncSetAttribute(splitk_gemm_kernel,                cudaFuncAttributeMaxDynamicSharedMemorySize, GEMM_SMEM_BYTES);

    // ---- one-shot convert of all weights to half (natural layout) ----
    conv_all_kernel<<<(N4_ALL + 255) / 256, 256>>>(Wq, Wk, Wv, Wp, W1, W2, wt);

    dim3 gemm_qkv3(CC / 128, MM / 128, 3);   // 576
    dim3 gemm_h   (HID / 128, MM / 128);     // 768
    dim3 gemm_sk  (CC / 128, MM / 128, 3);   // 576 (split-K)
    dim3 attn_grid(TT / 128, BB * NH);       // 384

    for (int l = 0; l < LNUM; l++) {
        const __half* wq = wt + WQ_OFF + (size_t)l * CC * CC;
        const __half* wk = wt + WK_OFF + (size_t)l * CC * CC;
        const __half* wv = wt + WV_OFF + (size_t)l * CC * CC;
        const __half* wp = wt + WP_OFF + (size_t)l * CC * CC;
        const __half* w1 = wt + W1_OFF + (size_t)l * CC * HID;
        const __half* w2 = wt + W2_OFF + (size_t)l * HID * CC;

        const float* resIn = (l == 0) ? x : res;

        if (l == 0) {
            ln_kernel<<<MM / 8, 256>>>(x, ln1_g, ln1_b, ln);
        } else {
            ln_reduce_kernel<<<MM / 8, 256>>>(part, b2 + (size_t)(l - 1) * CC, res, res,
                                              ln1_g + (size_t)l * CC, ln1_b + (size_t)l * CC, ln);
        }
        qkv_gemm_kernel<<<gemm_qkv3, 256, GEMM_SMEM_BYTES>>>(
            ln, wq, wk, wv, bq + (size_t)l*CC, bk + (size_t)l*CC, bv + (size_t)l*CC, q, k, v);
        attn_tc_kernel<<<attn_grid, 256, ATTN_SMEM>>>(q, k, v, y);
        splitk_gemm_kernel<<<gemm_sk, 256, GEMM_SMEM_BYTES>>>(y, wp, part, CC, CC);
        ln_reduce_kernel<<<MM / 8, 256>>>(part, bp + (size_t)l * CC, resIn, res,
                                          ln2_g + (size_t)l * CC, ln2_b + (size_t)l * CC, ln);
        tc_gemm_kernel<EPI_GELU, __half><<<gemm_h, 256, GEMM_SMEM_BYTES>>>(
            ln, w1, b1 + (size_t)l*HID, h1, HID, CC);
        splitk_gemm_kernel<<<gemm_sk, 256, GEMM_SMEM_BYTES>>>(h1, w2, part, HID, CC);
    }

    // final: out = sum(partials) + b2[3] + res
    {
        int n4 = MM * CC / 4;
        reduce_out_kernel<<<(n4 + 255) / 256, 256>>>(part, b2 + (size_t)3 * CC, res, (float*)d_out);
    }
}